// round 8
// baseline (speedup 1.0000x reference)
#include <cuda_runtime.h>
#include <cuda_bf16.h>
#include <cuda_fp16.h>
#include <cstdint>

#define S_TOT 2048
#define DMODEL 3072
#define NHEADS 48
#define HDIM 64
#define RANK_ 128
#define TLEN 226
#define VLEN 1822

#define K2 (2 * DMODEL)       // 6144 fp16 2-term width of D
#define LDB_BIG (K2 + 256)    // 6400: [W-split | lu-split]
#define BIG_CHUNKS (LDB_BIG / 64)   // 100
#define H_CHUNKS (K2 / 64)          // 96

// ---------------- fp32 scratch ----------------------------------------------
__device__ __align__(256) float g_q[S_TOT * DMODEL];
__device__ __align__(256) float g_k[S_TOT * DMODEL];
__device__ __align__(256) float g_v[S_TOT * DMODEL];
__device__ __align__(256) float g_t[S_TOT * 3 * RANK_];
__device__ __align__(256) float g_attn[S_TOT * DMODEL];

// ---------------- fp16 split operand buffers ---------------------------------
__device__ __align__(256) __half g_ab[(size_t)S_TOT * K2];
__device__ __align__(256) __half g_tb[(size_t)S_TOT * 768];
__device__ __align__(256) __half g_wb[3][(size_t)DMODEL * LDB_BIG];
__device__ __align__(256) __half g_ldb[(size_t)(3 * RANK_) * K2];

// ---------------- attention split planes (bf16 3-term, head-major) ----------
__device__ __align__(256) __nv_bfloat16 g_qhi[(size_t)NHEADS * S_TOT * HDIM];
__device__ __align__(256) __nv_bfloat16 g_qlo[(size_t)NHEADS * S_TOT * HDIM];
__device__ __align__(256) __nv_bfloat16 g_khi[(size_t)NHEADS * S_TOT * HDIM];
__device__ __align__(256) __nv_bfloat16 g_klo[(size_t)NHEADS * S_TOT * HDIM];
__device__ __align__(256) __nv_bfloat16 g_vthi[(size_t)NHEADS * HDIM * S_TOT];
__device__ __align__(256) __nv_bfloat16 g_vtlo[(size_t)NHEADS * HDIM * S_TOT];

// ============================================================================
// helpers
// ============================================================================
__device__ __forceinline__ uint32_t s2u(const void* p) {
    return (uint32_t)__cvta_generic_to_shared(p);
}
__device__ __forceinline__ void cpa16(uint32_t s, const void* g) {
    asm volatile("cp.async.cg.shared.global [%0], [%1], 16;" :: "r"(s), "l"(g));
}
__device__ __forceinline__ void cpa_commit() {
    asm volatile("cp.async.commit_group;" ::: "memory");
}
__device__ __forceinline__ void ldsm4(uint32_t* r, uint32_t a) {
    asm volatile("ldmatrix.sync.aligned.m8n8.x4.shared.b16 {%0,%1,%2,%3}, [%4];"
                 : "=r"(r[0]), "=r"(r[1]), "=r"(r[2]), "=r"(r[3]) : "r"(a));
}
__device__ __forceinline__ void ldsm2(uint32_t* r, uint32_t a) {
    asm volatile("ldmatrix.sync.aligned.m8n8.x2.shared.b16 {%0,%1}, [%2];"
                 : "=r"(r[0]), "=r"(r[1]) : "r"(a));
}
__device__ __forceinline__ void mma_bf16(float* c, const uint32_t* a, const uint32_t* b) {
    asm volatile(
        "mma.sync.aligned.m16n8k16.row.col.f32.bf16.bf16.f32 "
        "{%0,%1,%2,%3}, {%4,%5,%6,%7}, {%8,%9}, {%0,%1,%2,%3};"
        : "+f"(c[0]), "+f"(c[1]), "+f"(c[2]), "+f"(c[3])
        : "r"(a[0]), "r"(a[1]), "r"(a[2]), "r"(a[3]), "r"(b[0]), "r"(b[1]));
}
__device__ __forceinline__ void mma_f16(float* c, const uint32_t* a, const uint32_t* b) {
    asm volatile(
        "mma.sync.aligned.m16n8k16.row.col.f32.f16.f16.f32 "
        "{%0,%1,%2,%3}, {%4,%5,%6,%7}, {%8,%9}, {%0,%1,%2,%3};"
        : "+f"(c[0]), "+f"(c[1]), "+f"(c[2]), "+f"(c[3])
        : "r"(a[0]), "r"(a[1]), "r"(a[2]), "r"(a[3]), "r"(b[0]), "r"(b[1]));
}
__device__ __forceinline__ void split2bf(float x, float y, uint32_t& hi, uint32_t& lo) {
    __nv_bfloat162 h = __floats2bfloat162_rn(x, y);
    float hx = __bfloat162float(h.x), hy = __bfloat162float(h.y);
    __nv_bfloat162 l = __floats2bfloat162_rn(x - hx, y - hy);
    hi = *reinterpret_cast<uint32_t*>(&h);
    lo = *reinterpret_cast<uint32_t*>(&l);
}

// ============================================================================
// fp16 split kernels
// ============================================================================
__global__ void split_kernel_h(const float* __restrict__ src,
                               __half* __restrict__ dst,
                               int K, int dstStride, int dstOff, int amode, int n)
{
    int i = blockIdx.x * 256 + threadIdx.x;
    if (i >= n) return;
    int r = i / K, k = i % K;
    float x = src[i];
    __half hi = __float2half_rn(x);
    __half sec = amode ? __float2half_rn(x - __half2float(hi)) : hi;
    __half* d = dst + (size_t)r * dstStride + dstOff;
    d[k] = hi;
    d[K + k] = sec;
}

__global__ void split_concat_kernel(const float* __restrict__ hid,
                                    const float* __restrict__ enc)
{
    int i = blockIdx.x * 256 + threadIdx.x;
    if (i >= S_TOT * DMODEL) return;
    int r = i / DMODEL, k = i % DMODEL;
    float x = (r < TLEN) ? enc[i] : hid[i - TLEN * DMODEL];
    __half hi = __float2half_rn(x);
    __half lo = __float2half_rn(x - __half2float(hi));
    __half* d = g_ab + (size_t)r * K2;
    d[k] = hi;
    d[DMODEL + k] = lo;
}

__global__ void split_a_kernel(const float* __restrict__ src)
{
    int i = blockIdx.x * 256 + threadIdx.x;
    if (i >= S_TOT * DMODEL) return;
    int r = i / DMODEL, k = i % DMODEL;
    float x = src[i];
    __half hi = __float2half_rn(x);
    __half lo = __float2half_rn(x - __half2float(hi));
    __half* d = g_ab + (size_t)r * K2;
    d[k] = hi;
    d[DMODEL + k] = lo;
}

__global__ void tsplit_kernel(int nproj)
{
    int n = S_TOT * nproj * RANK_;
    int i = blockIdx.x * 256 + threadIdx.x;
    if (i >= n) return;
    int kw = nproj * RANK_;
    int r = i / kw, k = i % kw;
    int p = k >> 7, kk = k & 127;
    float x = g_t[(size_t)r * kw + k];
    __half hi = __float2half_rn(x);
    __half lo = __float2half_rn(x - __half2float(hi));
    __half* d = g_tb + (size_t)r * 768 + p * 256;
    d[kk] = hi;
    d[128 + kk] = lo;
}

// ============================================================================
// HMMA NT GEMM, BK=64, 128 threads (4 warps 2x2), warp tile 64x64,
// two-source A (main + tail), optional permuted store. 2 CTAs/SM.
// ============================================================================
#define GEMM_SMEM (4 * 128 * 72 * 2)   // 73728 bytes

__global__ void __launch_bounds__(128, 2) gemm_hmma(
    const __half* __restrict__ Ah, int lda_h, int h_chunks,
    const __half* __restrict__ At, int lda_t, int toff,
    const __half* __restrict__ B, int ldb,
    const float* __restrict__ bias, float* __restrict__ C, int ldc,
    int chunks, int use_atomic, int permute)
{
    extern __shared__ __half sm[];
    __half* smA = sm;                     // [2][128*72]
    __half* smB = sm + 2 * 128 * 72;      // [2][128*72]

    const int tid = threadIdx.x;
    const int lane = tid & 31;
    const int wid = tid >> 5;             // 0..3
    const int wm0 = (wid & 1) * 64;
    const int wn0 = (wid >> 1) * 64;
    const int r0 = blockIdx.y << 7;
    const int c0 = blockIdx.x << 7;
    const int kbase = blockIdx.z * chunks * 64;

    float acc[4][8][4];
#pragma unroll
    for (int i = 0; i < 4; i++)
#pragma unroll
        for (int j = 0; j < 8; j++)
#pragma unroll
            for (int e = 0; e < 4; e++) acc[i][j][e] = 0.f;

    const int lrow = tid >> 3;            // 0..15
    const int lch = tid & 7;              // 16B chunk within 128B row

    auto load_tile = [&](int c) {
        int b = c & 1;
        uint32_t sa = s2u(smA) + b * (128 * 144) + lrow * 144 + lch * 16;
        uint32_t sb = s2u(smB) + b * (128 * 144) + lrow * 144 + lch * 16;
        const __half* ga;
        int alda;
        if (c < h_chunks) { ga = Ah + kbase + c * 64 + lch * 8; alda = lda_h; }
        else              { ga = At + toff + (c - h_chunks) * 64 + lch * 8; alda = lda_t; }
        const __half* gb = B + (size_t)c0 * ldb + kbase + c * 64 + lch * 8;
#pragma unroll
        for (int i = 0; i < 8; i++) {
            int row = lrow + i * 16;
            cpa16(sa + i * (16 * 144), ga + (size_t)(r0 + row) * alda);
            cpa16(sb + i * (16 * 144), gb + (size_t)row * ldb);
        }
        cpa_commit();
    };

    load_tile(0);

    for (int c = 0; c < chunks; c++) {
        if (c + 1 < chunks) {
            load_tile(c + 1);
            asm volatile("cp.async.wait_group 1;" ::: "memory");
        } else {
            asm volatile("cp.async.wait_group 0;" ::: "memory");
        }
        __syncthreads();

        int b = c & 1;
        uint32_t saw = s2u(smA) + b * (128 * 144)
                       + (uint32_t)((wm0 + (lane & 15)) * 144) + ((lane >> 4) << 4);
        uint32_t sbw = s2u(smB) + b * (128 * 144)
                       + (uint32_t)((wn0 + (lane & 7)) * 144) + (((lane >> 3) & 1) << 4);
#pragma unroll
        for (int s = 0; s < 4; s++) {
            uint32_t af[4][4], bf[8][2];
#pragma unroll
            for (int i = 0; i < 4; i++) ldsm4(af[i], saw + i * (16 * 144) + s * 32);
#pragma unroll
            for (int j = 0; j < 8; j++) ldsm2(bf[j], sbw + j * (8 * 144) + s * 32);
#pragma unroll
            for (int i = 0; i < 4; i++)
#pragma unroll
                for (int j = 0; j < 8; j++)
                    mma_f16(acc[i][j], af[i], bf[j]);
        }
        __syncthreads();
    }

#pragma unroll
    for (int i = 0; i < 4; i++) {
#pragma unroll
        for (int j = 0; j < 8; j++) {
            int mm = r0 + wm0 + i * 16 + (lane >> 2);
            int nn = c0 + wn0 + j * 8 + (lane & 3) * 2;
            int row0 = mm, row1 = mm + 8;
            if (permute) {
                row0 = (row0 < TLEN) ? row0 + VLEN : row0 - TLEN;
                row1 = (row1 < TLEN) ? row1 + VLEN : row1 - TLEN;
            }
            float* p0 = C + (size_t)row0 * ldc + nn;
            float* p1 = C + (size_t)row1 * ldc + nn;
            if (use_atomic) {
                atomicAdd(p0,     acc[i][j][0]);
                atomicAdd(p0 + 1, acc[i][j][1]);
                atomicAdd(p1,     acc[i][j][2]);
                atomicAdd(p1 + 1, acc[i][j][3]);
            } else {
                float b0v = bias ? bias[nn] : 0.f;
                float b1v = bias ? bias[nn + 1] : 0.f;
                p0[0] = acc[i][j][0] + b0v;
                p0[1] = acc[i][j][1] + b1v;
                p1[0] = acc[i][j][2] + b0v;
                p1[1] = acc[i][j][3] + b1v;
            }
        }
    }
}

// ============================================================================
// LN(64) + RoPE -> bf16 hi/lo planes, head-major
// ============================================================================
__global__ void ln_rope_split(const float* __restrict__ x,
                              const float* __restrict__ gamma,
                              const float* __restrict__ beta,
                              const float* __restrict__ cosb,
                              const float* __restrict__ sinb,
                              __nv_bfloat16* __restrict__ hi_out,
                              __nv_bfloat16* __restrict__ lo_out,
                              float qscale)
{
    int gw = (blockIdx.x * blockDim.x + threadIdx.x) >> 5;
    int lane = threadIdx.x & 31;
    if (gw >= S_TOT * NHEADS) return;
    int pos = gw / NHEADS, head = gw % NHEADS;
    const float* row = x + (size_t)pos * DMODEL + head * HDIM;

    float2 v = ((const float2*)row)[lane];
    float sum = v.x + v.y;
#pragma unroll
    for (int o = 16; o; o >>= 1) sum += __shfl_xor_sync(0xffffffffu, sum, o);
    float mu = sum * (1.f / 64.f);
    float dx = v.x - mu, dy = v.y - mu;
    float vs = dx * dx + dy * dy;
#pragma unroll
    for (int o = 16; o; o >>= 1) vs += __shfl_xor_sync(0xffffffffu, vs, o);
    float inv = rsqrtf(vs * (1.f / 64.f) + 1e-5f);

    float y0 = dx * inv * gamma[lane * 2]     + beta[lane * 2];
    float y1 = dy * inv * gamma[lane * 2 + 1] + beta[lane * 2 + 1];

    if (pos >= TLEN) {
        int r = pos - TLEN;
        float c0 = cosb[r * HDIM + lane * 2], c1 = cosb[r * HDIM + lane * 2 + 1];
        float s0 = sinb[r * HDIM + lane * 2], s1 = sinb[r * HDIM + lane * 2 + 1];
        float t0 = y0 * c0 - y1 * s0;
        float t1 = y1 * c1 + y0 * s1;
        y0 = t0; y1 = t1;
    }
    y0 *= qscale; y1 *= qscale;

    size_t base = ((size_t)head * S_TOT + pos) * HDIM;
    uint32_t hi, lo;
    split2bf(y0, y1, hi, lo);
    *reinterpret_cast<uint32_t*>(hi_out + base + lane * 2) = hi;
    *reinterpret_cast<uint32_t*>(lo_out + base + lane * 2) = lo;
}

// ============================================================================
// V transpose + split (bf16)
// ============================================================================
__global__ void vt_split()
{
    __shared__ float tile[64][65];
    int head = blockIdx.y, p0 = blockIdx.x * 64;
    int tid = threadIdx.x;
#pragma unroll
    for (int i = 0; i < 16; i++) {
        int idx = tid + i * 256;
        int p = idx >> 6, d = idx & 63;
        tile[p][d] = g_v[(size_t)(p0 + p) * DMODEL + head * HDIM + d];
    }
    __syncthreads();
#pragma unroll
    for (int i = 0; i < 16; i++) {
        int idx = tid + i * 256;
        int d = idx >> 6, p = idx & 63;
        float x = tile[p][d];
        __nv_bfloat16 hi = __float2bfloat16(x);
        __nv_bfloat16 lo = __float2bfloat16(x - __bfloat162float(hi));
        size_t o = ((size_t)head * HDIM + d) * S_TOT + p0 + p;
        g_vthi[o] = hi;
        g_vtlo[o] = lo;
    }
}

// ============================================================================
// HMMA flash attention (bf16 3-term)
// ============================================================================
#define ATT_SQH 0
#define ATT_SQL 18432
#define ATT_SK  36864
#define ATT_SV  110592
#define ATT_SMEM 180224

__global__ void __launch_bounds__(256) attn_hmma()
{
    extern __shared__ char smc[];
    const int head = blockIdx.y;
    const int q0 = blockIdx.x * 128;
    const int tid = threadIdx.x;
    const int lane = tid & 31;
    const int wid = tid >> 5;

    const uint32_t smb = s2u(smc);

    {
        const __nv_bfloat16* Qh = g_qhi + ((size_t)head * S_TOT + q0) * HDIM;
        const __nv_bfloat16* Ql = g_qlo + ((size_t)head * S_TOT + q0) * HDIM;
#pragma unroll
        for (int i = 0; i < 4; i++) {
            int idx = tid + i * 256;
            int row = idx >> 3, ch = idx & 7;
            cpa16(smb + ATT_SQH + row * 144 + ch * 16, Qh + row * HDIM + ch * 8);
            cpa16(smb + ATT_SQL + row * 144 + ch * 16, Ql + row * HDIM + ch * 8);
        }
        cpa_commit();
    }

    auto load_kv = [&](int c) {
        int buf = c & 1;
        const __nv_bfloat16* Kh = g_khi + ((size_t)head * S_TOT + c * 128) * HDIM;
        const __nv_bfloat16* Kl = g_klo + ((size_t)head * S_TOT + c * 128) * HDIM;
        uint32_t kb = smb + ATT_SK + buf * 36864;
#pragma unroll
        for (int i = 0; i < 4; i++) {
            int idx = tid + i * 256;
            int row = idx >> 3, ch = idx & 7;
            cpa16(kb + row * 144 + ch * 16, Kh + row * HDIM + ch * 8);
            cpa16(kb + 18432 + row * 144 + ch * 16, Kl + row * HDIM + ch * 8);
        }
        const __nv_bfloat16* Vh = g_vthi + (size_t)head * HDIM * S_TOT + c * 128;
        const __nv_bfloat16* Vl = g_vtlo + (size_t)head * HDIM * S_TOT + c * 128;
        uint32_t vb = smb + ATT_SV + buf * 34816;
#pragma unroll
        for (int i = 0; i < 4; i++) {
            int idx = tid + i * 256;
            int d = idx >> 4, ch = idx & 15;
            cpa16(vb + d * 272 + ch * 16, Vh + (size_t)d * S_TOT + ch * 8);
            cpa16(vb + 17408 + d * 272 + ch * 16, Vl + (size_t)d * S_TOT + ch * 8);
        }
        cpa_commit();
    };

    load_kv(0);

    uint32_t aQh[4][4], aQl[4][4];
    float O[8][4];
#pragma unroll
    for (int j = 0; j < 8; j++)
#pragma unroll
        for (int e = 0; e < 4; e++) O[j][e] = 0.f;
    float m0 = -1e30f, m1 = -1e30f, l0 = 0.f, l1 = 0.f;

    for (int c = 0; c < S_TOT / 128; c++) {
        if (c + 1 < S_TOT / 128) {
            load_kv(c + 1);
            asm volatile("cp.async.wait_group 1;" ::: "memory");
        } else {
            asm volatile("cp.async.wait_group 0;" ::: "memory");
        }
        __syncthreads();

        if (c == 0) {
            uint32_t qa = smb + (uint32_t)((wid * 16 + (lane & 15)) * 144)
                          + ((lane >> 4) << 4);
#pragma unroll
            for (int kc = 0; kc < 4; kc++) {
                ldsm4(aQh[kc], qa + ATT_SQH + kc * 32);
                ldsm4(aQl[kc], qa + ATT_SQL + kc * 32);
            }
        }

        int buf = c & 1;
        float s[16][4];
#pragma unroll
        for (int j = 0; j < 16; j++)
#pragma unroll
            for (int e = 0; e < 4; e++) s[j][e] = 0.f;

        uint32_t kb = smb + ATT_SK + buf * 36864 + (uint32_t)((lane & 7) * 144)
                      + (((lane >> 3) & 1) << 4);
#pragma unroll
        for (int kc = 0; kc < 4; kc++) {
#pragma unroll
            for (int j = 0; j < 16; j++) {
                uint32_t bh[2], bl[2];
                uint32_t a = kb + j * (8 * 144) + kc * 32;
                ldsm2(bh, a);
                mma_bf16(s[j], aQh[kc], bh);
                mma_bf16(s[j], aQl[kc], bh);
                ldsm2(bl, a + 18432);
                mma_bf16(s[j], aQh[kc], bl);
            }
        }

        float mx0 = -1e30f, mx1 = -1e30f;
#pragma unroll
        for (int j = 0; j < 16; j++) {
            mx0 = fmaxf(mx0, fmaxf(s[j][0], s[j][1]));
            mx1 = fmaxf(mx1, fmaxf(s[j][2], s[j][3]));
        }
        mx0 = fmaxf(mx0, __shfl_xor_sync(0xffffffffu, mx0, 1));
        mx0 = fmaxf(mx0, __shfl_xor_sync(0xffffffffu, mx0, 2));
        mx1 = fmaxf(mx1, __shfl_xor_sync(0xffffffffu, mx1, 1));
        mx1 = fmaxf(mx1, __shfl_xor_sync(0xffffffffu, mx1, 2));
        float mn0 = fmaxf(m0, mx0), mn1 = fmaxf(m1, mx1);
        float cr0 = __expf(m0 - mn0), cr1 = __expf(m1 - mn1);
        m0 = mn0; m1 = mn1;

        float rs0 = 0.f, rs1 = 0.f;
#pragma unroll
        for (int j = 0; j < 16; j++) {
            s[j][0] = __expf(s[j][0] - mn0);
            s[j][1] = __expf(s[j][1] - mn0);
            s[j][2] = __expf(s[j][2] - mn1);
            s[j][3] = __expf(s[j][3] - mn1);
            rs0 += s[j][0] + s[j][1];
            rs1 += s[j][2] + s[j][3];
        }
        rs0 += __shfl_xor_sync(0xffffffffu, rs0, 1);
        rs0 += __shfl_xor_sync(0xffffffffu, rs0, 2);
        rs1 += __shfl_xor_sync(0xffffffffu, rs1, 1);
        rs1 += __shfl_xor_sync(0xffffffffu, rs1, 2);
        l0 = l0 * cr0 + rs0;
        l1 = l1 * cr1 + rs1;

#pragma unroll
        for (int j = 0; j < 8; j++) {
            O[j][0] *= cr0; O[j][1] *= cr0;
            O[j][2] *= cr1; O[j][3] *= cr1;
        }

        uint32_t vb = smb + ATT_SV + buf * 34816 + (uint32_t)((lane & 7) * 272)
                      + (((lane >> 3) & 1) << 4);
#pragma unroll
        for (int ck = 0; ck < 8; ck++) {
            uint32_t ah[4], al[4];
            split2bf(s[2 * ck][0],     s[2 * ck][1],     ah[0], al[0]);
            split2bf(s[2 * ck][2],     s[2 * ck][3],     ah[1], al[1]);
            split2bf(s[2 * ck + 1][0], s[2 * ck + 1][1], ah[2], al[2]);
            split2bf(s[2 * ck + 1][2], s[2 * ck + 1][3], ah[3], al[3]);
#pragma unroll
            for (int jd = 0; jd < 8; jd++) {
                uint32_t bh[2], bl[2];
                uint32_t a = vb + jd * (8 * 272) + ck * 32;
                ldsm2(bh, a);
                mma_bf16(O[jd], ah, bh);
                mma_bf16(O[jd], al, bh);
                ldsm2(bl, a + 17408);
                mma_bf16(O[jd], ah, bl);
            }
        }
        __syncthreads();
    }

    float i0 = 1.f / l0, i1 = 1.f / l1;
    int r = q0 + wid * 16 + (lane >> 2);
    int cb = head * HDIM + (lane & 3) * 2;
#pragma unroll
    for (int jd = 0; jd < 8; jd++) {
        float* p0 = g_attn + (size_t)r * DMODEL + cb + jd * 8;
        float* p1 = g_attn + (size_t)(r + 8) * DMODEL + cb + jd * 8;
        p0[0] = O[jd][0] * i0; p0[1] = O[jd][1] * i0;
        p1[0] = O[jd][2] * i1; p1[1] = O[jd][3] * i1;
    }
}

// ============================================================================
extern "C" void kernel_launch(void* const* d_in, const int* in_sizes, int n_in,
                              void* d_out, int out_size)
{
    const float* hid = (const float*)d_in[0];
    const float* enc = (const float*)d_in[1];
    const float* rc  = (const float*)d_in[2];
    const float* rs  = (const float*)d_in[3];
    const float* Wq  = (const float*)d_in[4];  const float* bq = (const float*)d_in[5];
    const float* Wk  = (const float*)d_in[6];  const float* bk = (const float*)d_in[7];
    const float* Wv  = (const float*)d_in[8];  const float* bv = (const float*)d_in[9];
    const float* Wo  = (const float*)d_in[10]; const float* bo = (const float*)d_in[11];
    const float* lqd = (const float*)d_in[12]; const float* lqu = (const float*)d_in[13];
    const float* lkd = (const float*)d_in[14]; const float* lku = (const float*)d_in[15];
    const float* lvd = (const float*)d_in[16]; const float* lvu = (const float*)d_in[17];
    const float* lpd = (const float*)d_in[18]; const float* lpu = (const float*)d_in[19];
    const float* gq  = (const float*)d_in[20]; const float* btq = (const float*)d_in[21];
    const float* gk  = (const float*)d_in[22]; const float* btk = (const float*)d_in[23];

    static int attr_done = 0;
    if (!attr_done) {
        cudaFuncSetAttribute(attn_hmma, cudaFuncAttributeMaxDynamicSharedMemorySize,
                             ATT_SMEM);
        cudaFuncSetAttribute(gemm_hmma, cudaFuncAttributeMaxDynamicSharedMemorySize,
                             GEMM_SMEM);
        attr_done = 1;
    }

    float *pq, *pk, *pv, *pt, *pa;
    __half *pab, *ptb, *pldb;
    __half* pwb[3];
    __nv_bfloat16 *pqh, *pql, *pkh, *pkl;
    cudaGetSymbolAddress((void**)&pq, g_q);
    cudaGetSymbolAddress((void**)&pk, g_k);
    cudaGetSymbolAddress((void**)&pv, g_v);
    cudaGetSymbolAddress((void**)&pt, g_t);
    cudaGetSymbolAddress((void**)&pa, g_attn);
    cudaGetSymbolAddress((void**)&pab, g_ab);
    cudaGetSymbolAddress((void**)&ptb, g_tb);
    cudaGetSymbolAddress((void**)&pldb, g_ldb);
    {
        __half* base;
        cudaGetSymbolAddress((void**)&base, g_wb);
        for (int p = 0; p < 3; p++) pwb[p] = base + (size_t)p * DMODEL * LDB_BIG;
    }
    cudaGetSymbolAddress((void**)&pqh, g_qhi);
    cudaGetSymbolAddress((void**)&pql, g_qlo);
    cudaGetSymbolAddress((void**)&pkh, g_khi);
    cudaGetSymbolAddress((void**)&pkl, g_klo);

    const int nHD = S_TOT * DMODEL;
    const int nW  = DMODEL * DMODEL;
    const int nLD = RANK_ * DMODEL;
    const int nLU = DMODEL * RANK_;

    dim3 big_grid(DMODEL / 128, S_TOT / 128, 1);     // 24 x 16
    dim3 lora3_grid(3, S_TOT / 128, 8);              // N=384, split-K 8
    dim3 lora1_grid(1, S_TOT / 128, 8);              // N=128, split-K 8
    const int LORA_CH = H_CHUNKS / 8;                // 12

    // ---- A operand (h) + all weight splits up front ----
    split_concat_kernel<<<(nHD + 255) / 256, 256>>>(hid, enc);
    const float* Ws[3]  = {Wq, Wk, Wv};
    const float* lus[3] = {lqu, lku, lvu};
    const float* lds[3] = {lqd, lkd, lvd};
    for (int p = 0; p < 3; p++) {
        split_kernel_h<<<(nW + 255) / 256, 256>>>(Ws[p], pwb[p], DMODEL, LDB_BIG, 0, 0, nW);
        split_kernel_h<<<(nLU + 255) / 256, 256>>>(lus[p], pwb[p], RANK_, LDB_BIG, K2, 0, nLU);
        split_kernel_h<<<(nLD + 255) / 256, 256>>>(lds[p], pldb + (size_t)(p * RANK_) * K2,
                                                   DMODEL, K2, 0, 0, nLD);
    }

    // ---- batched lora-down for q,k,v: t[2048x384] ----
    cudaMemsetAsync(pt, 0, S_TOT * 3 * RANK_ * sizeof(float));
    gemm_hmma<<<lora3_grid, 128, GEMM_SMEM>>>(pab, K2, H_CHUNKS, nullptr, 0, 0,
                                              pldb, K2, nullptr, pt, 3 * RANK_,
                                              LORA_CH, 1, 0);
    tsplit_kernel<<<(S_TOT * 3 * RANK_ + 255) / 256, 256>>>(3);

    // ---- three big GEMMs back-to-back ----
    float* outs[3] = {pq, pk, pv};
    const float* bs[3] = {bq, bk, bv};
    for (int p = 0; p < 3; p++) {
        gemm_hmma<<<big_grid, 128, GEMM_SMEM>>>(pab, K2, H_CHUNKS, ptb, 768, p * 256,
                                                pwb[p], LDB_BIG, bs[p], outs[p], DMODEL,
                                                BIG_CHUNKS, 0, 0);
    }

    // ---- LN + RoPE -> bf16 split planes ----
    int ln_blocks = (S_TOT * NHEADS * 32 + 255) / 256;
    ln_rope_split<<<ln_blocks, 256>>>(pq, gq, btq, rc, rs, pqh, pql, 0.125f);
    ln_rope_split<<<ln_blocks, 256>>>(pk, gk, btk, rc, rs, pkh, pkl, 1.0f);
    vt_split<<<dim3(S_TOT / 64, NHEADS), 256>>>();

    attn_hmma<<<dim3(S_TOT / 128, NHEADS), 256, ATT_SMEM>>>();

    // ---- output projection (fused permute into epilogue) ----
    split_a_kernel<<<(nHD + 255) / 256, 256>>>(pa);
    split_kernel_h<<<(nW + 255) / 256, 256>>>(Wo, pwb[0], DMODEL, LDB_BIG, 0, 0, nW);
    split_kernel_h<<<(nLU + 255) / 256, 256>>>(lpu, pwb[0], RANK_, LDB_BIG, K2, 0, nLU);
    split_kernel_h<<<(nLD + 255) / 256, 256>>>(lpd, pldb, DMODEL, K2, 0, 0, nLD);
    cudaMemsetAsync(pt, 0, S_TOT * RANK_ * sizeof(float));
    gemm_hmma<<<lora1_grid, 128, GEMM_SMEM>>>(pab, K2, H_CHUNKS, nullptr, 0, 0,
                                              pldb, K2, nullptr, pt, RANK_,
                                              LORA_CH, 1, 0);
    tsplit_kernel<<<(S_TOT * RANK_ + 255) / 256, 256>>>(1);
    gemm_hmma<<<big_grid, 128, GEMM_SMEM>>>(pab, K2, H_CHUNKS, ptb, 768, 0,
                                            pwb[0], LDB_BIG, bo, (float*)d_out, DMODEL,
                                            BIG_CHUNKS, 0, 1);
}

// round 9
// speedup vs baseline: 1.0649x; 1.0649x over previous
#include <cuda_runtime.h>
#include <cuda_bf16.h>
#include <cuda_fp16.h>
#include <cstdint>

#define S_TOT 2048
#define DMODEL 3072
#define NHEADS 48
#define HDIM 64
#define RANK_ 128
#define TLEN 226
#define VLEN 1822

#define K2 (2 * DMODEL)       // 6144
#define LDB_BIG (K2 + 256)    // 6400
#define BIG_CHUNKS (LDB_BIG / 64)   // 100
#define H_CHUNKS (K2 / 64)          // 96

// ---------------- fp32 scratch ----------------------------------------------
__device__ __align__(256) float g_q[S_TOT * DMODEL];
__device__ __align__(256) float g_k[S_TOT * DMODEL];
__device__ __align__(256) float g_v[S_TOT * DMODEL];
__device__ __align__(256) float g_t[S_TOT * 3 * RANK_];
__device__ __align__(256) float g_attn[S_TOT * DMODEL];

// ---------------- fp16 split operand buffers ---------------------------------
__device__ __align__(256) __half g_ab[(size_t)S_TOT * K2];
__device__ __align__(256) __half g_tb[(size_t)S_TOT * 768];
__device__ __align__(256) __half g_wb[3][(size_t)DMODEL * LDB_BIG];
__device__ __align__(256) __half g_ldb[(size_t)(3 * RANK_) * K2];

// ---------------- attention split planes (bf16 3-term, head-major) ----------
__device__ __align__(256) __nv_bfloat16 g_qhi[(size_t)NHEADS * S_TOT * HDIM];
__device__ __align__(256) __nv_bfloat16 g_qlo[(size_t)NHEADS * S_TOT * HDIM];
__device__ __align__(256) __nv_bfloat16 g_khi[(size_t)NHEADS * S_TOT * HDIM];
__device__ __align__(256) __nv_bfloat16 g_klo[(size_t)NHEADS * S_TOT * HDIM];
__device__ __align__(256) __nv_bfloat16 g_vthi[(size_t)NHEADS * HDIM * S_TOT];
__device__ __align__(256) __nv_bfloat16 g_vtlo[(size_t)NHEADS * HDIM * S_TOT];

// ============================================================================
// helpers
// ============================================================================
__device__ __forceinline__ uint32_t s2u(const void* p) {
    return (uint32_t)__cvta_generic_to_shared(p);
}
__device__ __forceinline__ void cpa16(uint32_t s, const void* g) {
    asm volatile("cp.async.cg.shared.global [%0], [%1], 16;" :: "r"(s), "l"(g));
}
__device__ __forceinline__ void cpa_commit() {
    asm volatile("cp.async.commit_group;" ::: "memory");
}
__device__ __forceinline__ void ldsm4(uint32_t* r, uint32_t a) {
    asm volatile("ldmatrix.sync.aligned.m8n8.x4.shared.b16 {%0,%1,%2,%3}, [%4];"
                 : "=r"(r[0]), "=r"(r[1]), "=r"(r[2]), "=r"(r[3]) : "r"(a));
}
__device__ __forceinline__ void ldsm2(uint32_t* r, uint32_t a) {
    asm volatile("ldmatrix.sync.aligned.m8n8.x2.shared.b16 {%0,%1}, [%2];"
                 : "=r"(r[0]), "=r"(r[1]) : "r"(a));
}
__device__ __forceinline__ void mma_bf16(float* c, const uint32_t* a, const uint32_t* b) {
    asm volatile(
        "mma.sync.aligned.m16n8k16.row.col.f32.bf16.bf16.f32 "
        "{%0,%1,%2,%3}, {%4,%5,%6,%7}, {%8,%9}, {%0,%1,%2,%3};"
        : "+f"(c[0]), "+f"(c[1]), "+f"(c[2]), "+f"(c[3])
        : "r"(a[0]), "r"(a[1]), "r"(a[2]), "r"(a[3]), "r"(b[0]), "r"(b[1]));
}
__device__ __forceinline__ void mma_f16(float* c, const uint32_t* a, const uint32_t* b) {
    asm volatile(
        "mma.sync.aligned.m16n8k16.row.col.f32.f16.f16.f32 "
        "{%0,%1,%2,%3}, {%4,%5,%6,%7}, {%8,%9}, {%0,%1,%2,%3};"
        : "+f"(c[0]), "+f"(c[1]), "+f"(c[2]), "+f"(c[3])
        : "r"(a[0]), "r"(a[1]), "r"(a[2]), "r"(a[3]), "r"(b[0]), "r"(b[1]));
}
__device__ __forceinline__ void split2bf(float x, float y, uint32_t& hi, uint32_t& lo) {
    __nv_bfloat162 h = __floats2bfloat162_rn(x, y);
    float hx = __bfloat162float(h.x), hy = __bfloat162float(h.y);
    __nv_bfloat162 l = __floats2bfloat162_rn(x - hx, y - hy);
    hi = *reinterpret_cast<uint32_t*>(&h);
    lo = *reinterpret_cast<uint32_t*>(&l);
}

// ============================================================================
// fp16 split kernels
// ============================================================================
__global__ void split_kernel_h(const float* __restrict__ src,
                               __half* __restrict__ dst,
                               int K, int dstStride, int dstOff, int amode, int n)
{
    int i = blockIdx.x * 256 + threadIdx.x;
    if (i >= n) return;
    int r = i / K, k = i % K;
    float x = src[i];
    __half hi = __float2half_rn(x);
    __half sec = amode ? __float2half_rn(x - __half2float(hi)) : hi;
    __half* d = dst + (size_t)r * dstStride + dstOff;
    d[k] = hi;
    d[K + k] = sec;
}

// batched 3-source B-split (W or lu or ld)
__global__ void split3_kernel(const float* __restrict__ s0,
                              const float* __restrict__ s1,
                              const float* __restrict__ s2,
                              __half* __restrict__ dst, size_t dstProjStride,
                              int K, int dstStride, int dstOff, int n)
{
    int i = blockIdx.x * 256 + threadIdx.x;
    if (i >= 3 * n) return;
    int p = i / n, j = i % n;
    const float* src = (p == 0) ? s0 : (p == 1) ? s1 : s2;
    int r = j / K, k = j % K;
    float x = src[j];
    __half hi = __float2half_rn(x);
    __half* d = dst + p * dstProjStride + (size_t)r * dstStride + dstOff;
    d[k] = hi;
    d[K + k] = hi;
}

__global__ void split_concat_kernel(const float* __restrict__ hid,
                                    const float* __restrict__ enc)
{
    int i = blockIdx.x * 256 + threadIdx.x;
    if (i >= S_TOT * DMODEL) return;
    int r = i / DMODEL, k = i % DMODEL;
    float x = (r < TLEN) ? enc[i] : hid[i - TLEN * DMODEL];
    __half hi = __float2half_rn(x);
    __half lo = __float2half_rn(x - __half2float(hi));
    __half* d = g_ab + (size_t)r * K2;
    d[k] = hi;
    d[DMODEL + k] = lo;
}

__global__ void split_a_kernel(const float* __restrict__ src)
{
    int i = blockIdx.x * 256 + threadIdx.x;
    if (i >= S_TOT * DMODEL) return;
    int r = i / DMODEL, k = i % DMODEL;
    float x = src[i];
    __half hi = __float2half_rn(x);
    __half lo = __float2half_rn(x - __half2float(hi));
    __half* d = g_ab + (size_t)r * K2;
    d[k] = hi;
    d[DMODEL + k] = lo;
}

__global__ void tsplit_kernel(int nproj)
{
    int n = S_TOT * nproj * RANK_;
    int i = blockIdx.x * 256 + threadIdx.x;
    if (i >= n) return;
    int kw = nproj * RANK_;
    int r = i / kw, k = i % kw;
    int p = k >> 7, kk = k & 127;
    float x = g_t[(size_t)r * kw + k];
    __half hi = __float2half_rn(x);
    __half lo = __float2half_rn(x - __half2float(hi));
    __half* d = g_tb + (size_t)r * 768 + p * 256;
    d[kk] = hi;
    d[128 + kk] = lo;
}

// ============================================================================
// GEMM core (BK=64, 4 warps 2x2, warp tile 64x64), shared by both kernels
// ============================================================================
#define GEMM_SMEM (4 * 128 * 72 * 2)   // 73728 bytes

struct GemmCore {
    float acc[4][8][4];
    __half *smA, *smB;
    int tid, lane, wid, wm0, wn0, lrow, lch;

    __device__ __forceinline__ void init(__half* sm) {
        smA = sm; smB = sm + 2 * 128 * 72;
        tid = threadIdx.x; lane = tid & 31; wid = tid >> 5;
        wm0 = (wid & 1) * 64; wn0 = (wid >> 1) * 64;
        lrow = tid >> 3; lch = tid & 7;
#pragma unroll
        for (int i = 0; i < 4; i++)
#pragma unroll
            for (int j = 0; j < 8; j++)
#pragma unroll
                for (int e = 0; e < 4; e++) acc[i][j][e] = 0.f;
    }

    __device__ __forceinline__ void load_tile(int c, const __half* gaRow, int alda,
                                              const __half* gbRow, int ldb) {
        int b = c & 1;
        uint32_t sa = s2u(smA) + b * (128 * 144) + lrow * 144 + lch * 16;
        uint32_t sb = s2u(smB) + b * (128 * 144) + lrow * 144 + lch * 16;
#pragma unroll
        for (int i = 0; i < 8; i++) {
            int row = lrow + i * 16;
            cpa16(sa + i * (16 * 144), gaRow + (size_t)row * alda);
            cpa16(sb + i * (16 * 144), gbRow + (size_t)row * ldb);
        }
        cpa_commit();
    }

    __device__ __forceinline__ void compute(int c) {
        int b = c & 1;
        uint32_t saw = s2u(smA) + b * (128 * 144)
                       + (uint32_t)((wm0 + (lane & 15)) * 144) + ((lane >> 4) << 4);
        uint32_t sbw = s2u(smB) + b * (128 * 144)
                       + (uint32_t)((wn0 + (lane & 7)) * 144) + (((lane >> 3) & 1) << 4);
#pragma unroll
        for (int s = 0; s < 4; s++) {
            uint32_t af[4][4], bf[8][2];
#pragma unroll
            for (int i = 0; i < 4; i++) ldsm4(af[i], saw + i * (16 * 144) + s * 32);
#pragma unroll
            for (int j = 0; j < 8; j++) ldsm2(bf[j], sbw + j * (8 * 144) + s * 32);
#pragma unroll
            for (int i = 0; i < 4; i++)
#pragma unroll
                for (int j = 0; j < 8; j++)
                    mma_f16(acc[i][j], af[i], bf[j]);
        }
    }

    __device__ __forceinline__ void store(int r0, int c0, const float* bias,
                                          float* C, int ldc, int use_atomic, int permute) {
#pragma unroll
        for (int i = 0; i < 4; i++) {
#pragma unroll
            for (int j = 0; j < 8; j++) {
                int mm = r0 + wm0 + i * 16 + (lane >> 2);
                int nn = c0 + wn0 + j * 8 + (lane & 3) * 2;
                int row0 = mm, row1 = mm + 8;
                if (permute) {
                    row0 = (row0 < TLEN) ? row0 + VLEN : row0 - TLEN;
                    row1 = (row1 < TLEN) ? row1 + VLEN : row1 - TLEN;
                }
                float* p0 = C + (size_t)row0 * ldc + nn;
                float* p1 = C + (size_t)row1 * ldc + nn;
                if (use_atomic) {
                    atomicAdd(p0,     acc[i][j][0]);
                    atomicAdd(p0 + 1, acc[i][j][1]);
                    atomicAdd(p1,     acc[i][j][2]);
                    atomicAdd(p1 + 1, acc[i][j][3]);
                } else {
                    float b0v = bias ? bias[nn] : 0.f;
                    float b1v = bias ? bias[nn + 1] : 0.f;
                    p0[0] = acc[i][j][0] + b0v;
                    p0[1] = acc[i][j][1] + b1v;
                    p1[0] = acc[i][j][2] + b0v;
                    p1[1] = acc[i][j][3] + b1v;
                }
            }
        }
    }
};

// generic GEMM (lora-down split-K, out-proj)
__global__ void __launch_bounds__(128, 2) gemm_hmma(
    const __half* __restrict__ Ah, int lda_h, int h_chunks,
    const __half* __restrict__ At, int lda_t, int toff,
    const __half* __restrict__ B, int ldb,
    const float* __restrict__ bias, float* __restrict__ C, int ldc,
    int chunks, int use_atomic, int permute)
{
    extern __shared__ __half sm[];
    GemmCore g;
    g.init(sm);
    const int r0 = blockIdx.y << 7;
    const int c0 = blockIdx.x << 7;
    const int kbase = blockIdx.z * chunks * 64;

    auto aRow = [&](int c) -> const __half* {
        if (c < h_chunks) return Ah + (size_t)r0 * lda_h + kbase + c * 64 + g.lch * 8;
        return At + (size_t)r0 * lda_t + toff + (c - h_chunks) * 64 + g.lch * 8;
    };
    auto aLda = [&](int c) { return (c < h_chunks) ? lda_h : lda_t; };

    g.load_tile(0, aRow(0), aLda(0), B + (size_t)c0 * ldb + kbase + g.lch * 8, ldb);
    for (int c = 0; c < chunks; c++) {
        if (c + 1 < chunks) {
            g.load_tile(c + 1, aRow(c + 1), aLda(c + 1),
                        B + (size_t)c0 * ldb + kbase + (c + 1) * 64 + g.lch * 8, ldb);
            asm volatile("cp.async.wait_group 1;" ::: "memory");
        } else {
            asm volatile("cp.async.wait_group 0;" ::: "memory");
        }
        __syncthreads();
        g.compute(c);
        __syncthreads();
    }
    g.store(r0, c0, bias, C, ldc, use_atomic, permute);
}

// merged q/k/v projection GEMM: grid (72, 16); proj = blockIdx.x / 24
__global__ void __launch_bounds__(128, 2) gemm_qkv(
    const __half* __restrict__ Ah, const __half* __restrict__ At,
    const __half* __restrict__ Wbase,
    const float* __restrict__ b0, const float* __restrict__ b1, const float* __restrict__ b2,
    float* __restrict__ C0, float* __restrict__ C1, float* __restrict__ C2)
{
    extern __shared__ __half sm[];
    GemmCore g;
    g.init(sm);
    const int proj = blockIdx.x / 24;
    const int c0 = (blockIdx.x % 24) << 7;
    const int r0 = blockIdx.y << 7;
    const __half* B = Wbase + (size_t)proj * DMODEL * LDB_BIG;
    const float* bias = (proj == 0) ? b0 : (proj == 1) ? b1 : b2;
    float* C = (proj == 0) ? C0 : (proj == 1) ? C1 : C2;
    const int toff = proj * 256;

    auto aRow = [&](int c) -> const __half* {
        if (c < H_CHUNKS) return Ah + (size_t)r0 * K2 + c * 64 + g.lch * 8;
        return At + (size_t)r0 * 768 + toff + (c - H_CHUNKS) * 64 + g.lch * 8;
    };
    auto aLda = [&](int c) { return (c < H_CHUNKS) ? K2 : 768; };

    g.load_tile(0, aRow(0), aLda(0), B + (size_t)c0 * LDB_BIG + g.lch * 8, LDB_BIG);
    for (int c = 0; c < BIG_CHUNKS; c++) {
        if (c + 1 < BIG_CHUNKS) {
            g.load_tile(c + 1, aRow(c + 1), aLda(c + 1),
                        B + (size_t)c0 * LDB_BIG + (c + 1) * 64 + g.lch * 8, LDB_BIG);
            asm volatile("cp.async.wait_group 1;" ::: "memory");
        } else {
            asm volatile("cp.async.wait_group 0;" ::: "memory");
        }
        __syncthreads();
        g.compute(c);
        __syncthreads();
    }
    g.store(r0, c0, bias, C, DMODEL, 0, 0);
}

// ============================================================================
// LN(64) + RoPE -> bf16 hi/lo planes, head-major
// ============================================================================
__global__ void ln_rope_split(const float* __restrict__ x,
                              const float* __restrict__ gamma,
                              const float* __restrict__ beta,
                              const float* __restrict__ cosb,
                              const float* __restrict__ sinb,
                              __nv_bfloat16* __restrict__ hi_out,
                              __nv_bfloat16* __restrict__ lo_out,
                              float qscale)
{
    int gw = (blockIdx.x * blockDim.x + threadIdx.x) >> 5;
    int lane = threadIdx.x & 31;
    if (gw >= S_TOT * NHEADS) return;
    int pos = gw / NHEADS, head = gw % NHEADS;
    const float* row = x + (size_t)pos * DMODEL + head * HDIM;

    float2 v = ((const float2*)row)[lane];
    float sum = v.x + v.y;
#pragma unroll
    for (int o = 16; o; o >>= 1) sum += __shfl_xor_sync(0xffffffffu, sum, o);
    float mu = sum * (1.f / 64.f);
    float dx = v.x - mu, dy = v.y - mu;
    float vs = dx * dx + dy * dy;
#pragma unroll
    for (int o = 16; o; o >>= 1) vs += __shfl_xor_sync(0xffffffffu, vs, o);
    float inv = rsqrtf(vs * (1.f / 64.f) + 1e-5f);

    float y0 = dx * inv * gamma[lane * 2]     + beta[lane * 2];
    float y1 = dy * inv * gamma[lane * 2 + 1] + beta[lane * 2 + 1];

    if (pos >= TLEN) {
        int r = pos - TLEN;
        float c0 = cosb[r * HDIM + lane * 2], c1 = cosb[r * HDIM + lane * 2 + 1];
        float s0 = sinb[r * HDIM + lane * 2], s1 = sinb[r * HDIM + lane * 2 + 1];
        float t0 = y0 * c0 - y1 * s0;
        float t1 = y1 * c1 + y0 * s1;
        y0 = t0; y1 = t1;
    }
    y0 *= qscale; y1 *= qscale;

    size_t base = ((size_t)head * S_TOT + pos) * HDIM;
    uint32_t hi, lo;
    split2bf(y0, y1, hi, lo);
    *reinterpret_cast<uint32_t*>(hi_out + base + lane * 2) = hi;
    *reinterpret_cast<uint32_t*>(lo_out + base + lane * 2) = lo;
}

// ============================================================================
// V transpose + split (bf16)
// ============================================================================
__global__ void vt_split()
{
    __shared__ float tile[64][65];
    int head = blockIdx.y, p0 = blockIdx.x * 64;
    int tid = threadIdx.x;
#pragma unroll
    for (int i = 0; i < 16; i++) {
        int idx = tid + i * 256;
        int p = idx >> 6, d = idx & 63;
        tile[p][d] = g_v[(size_t)(p0 + p) * DMODEL + head * HDIM + d];
    }
    __syncthreads();
#pragma unroll
    for (int i = 0; i < 16; i++) {
        int idx = tid + i * 256;
        int d = idx >> 6, p = idx & 63;
        float x = tile[p][d];
        __nv_bfloat16 hi = __float2bfloat16(x);
        __nv_bfloat16 lo = __float2bfloat16(x - __bfloat162float(hi));
        size_t o = ((size_t)head * HDIM + d) * S_TOT + p0 + p;
        g_vthi[o] = hi;
        g_vtlo[o] = lo;
    }
}

// ============================================================================
// HMMA flash attention (bf16 3-term)
// ============================================================================
#define ATT_SQH 0
#define ATT_SQL 18432
#define ATT_SK  36864
#define ATT_SV  110592
#define ATT_SMEM 180224

__global__ void __launch_bounds__(256) attn_hmma()
{
    extern __shared__ char smc[];
    const int head = blockIdx.y;
    const int q0 = blockIdx.x * 128;
    const int tid = threadIdx.x;
    const int lane = tid & 31;
    const int wid = tid >> 5;

    const uint32_t smb = s2u(smc);

    {
        const __nv_bfloat16* Qh = g_qhi + ((size_t)head * S_TOT + q0) * HDIM;
        const __nv_bfloat16* Ql = g_qlo + ((size_t)head * S_TOT + q0) * HDIM;
#pragma unroll
        for (int i = 0; i < 4; i++) {
            int idx = tid + i * 256;
            int row = idx >> 3, ch = idx & 7;
            cpa16(smb + ATT_SQH + row * 144 + ch * 16, Qh + row * HDIM + ch * 8);
            cpa16(smb + ATT_SQL + row * 144 + ch * 16, Ql + row * HDIM + ch * 8);
        }
        cpa_commit();
    }

    auto load_kv = [&](int c) {
        int buf = c & 1;
        const __nv_bfloat16* Kh = g_khi + ((size_t)head * S_TOT + c * 128) * HDIM;
        const __nv_bfloat16* Kl = g_klo + ((size_t)head * S_TOT + c * 128) * HDIM;
        uint32_t kb = smb + ATT_SK + buf * 36864;
#pragma unroll
        for (int i = 0; i < 4; i++) {
            int idx = tid + i * 256;
            int row = idx >> 3, ch = idx & 7;
            cpa16(kb + row * 144 + ch * 16, Kh + row * HDIM + ch * 8);
            cpa16(kb + 18432 + row * 144 + ch * 16, Kl + row * HDIM + ch * 8);
        }
        const __nv_bfloat16* Vh = g_vthi + (size_t)head * HDIM * S_TOT + c * 128;
        const __nv_bfloat16* Vl = g_vtlo + (size_t)head * HDIM * S_TOT + c * 128;
        uint32_t vb = smb + ATT_SV + buf * 34816;
#pragma unroll
        for (int i = 0; i < 4; i++) {
            int idx = tid + i * 256;
            int d = idx >> 4, ch = idx & 15;
            cpa16(vb + d * 272 + ch * 16, Vh + (size_t)d * S_TOT + ch * 8);
            cpa16(vb + 17408 + d * 272 + ch * 16, Vl + (size_t)d * S_TOT + ch * 8);
        }
        cpa_commit();
    };

    load_kv(0);

    uint32_t aQh[4][4], aQl[4][4];
    float O[8][4];
#pragma unroll
    for (int j = 0; j < 8; j++)
#pragma unroll
        for (int e = 0; e < 4; e++) O[j][e] = 0.f;
    float m0 = -1e30f, m1 = -1e30f, l0 = 0.f, l1 = 0.f;

    for (int c = 0; c < S_TOT / 128; c++) {
        if (c + 1 < S_TOT / 128) {
            load_kv(c + 1);
            asm volatile("cp.async.wait_group 1;" ::: "memory");
        } else {
            asm volatile("cp.async.wait_group 0;" ::: "memory");
        }
        __syncthreads();

        if (c == 0) {
            uint32_t qa = smb + (uint32_t)((wid * 16 + (lane & 15)) * 144)
                          + ((lane >> 4) << 4);
#pragma unroll
            for (int kc = 0; kc < 4; kc++) {
                ldsm4(aQh[kc], qa + ATT_SQH + kc * 32);
                ldsm4(aQl[kc], qa + ATT_SQL + kc * 32);
            }
        }

        int buf = c & 1;
        float s[16][4];
#pragma unroll
        for (int j = 0; j < 16; j++)
#pragma unroll
            for (int e = 0; e < 4; e++) s[j][e] = 0.f;

        uint32_t kb = smb + ATT_SK + buf * 36864 + (uint32_t)((lane & 7) * 144)
                      + (((lane >> 3) & 1) << 4);
#pragma unroll
        for (int kc = 0; kc < 4; kc++) {
#pragma unroll
            for (int j = 0; j < 16; j++) {
                uint32_t bh[2], bl[2];
                uint32_t a = kb + j * (8 * 144) + kc * 32;
                ldsm2(bh, a);
                mma_bf16(s[j], aQh[kc], bh);
                mma_bf16(s[j], aQl[kc], bh);
                ldsm2(bl, a + 18432);
                mma_bf16(s[j], aQh[kc], bl);
            }
        }

        float mx0 = -1e30f, mx1 = -1e30f;
#pragma unroll
        for (int j = 0; j < 16; j++) {
            mx0 = fmaxf(mx0, fmaxf(s[j][0], s[j][1]));
            mx1 = fmaxf(mx1, fmaxf(s[j][2], s[j][3]));
        }
        mx0 = fmaxf(mx0, __shfl_xor_sync(0xffffffffu, mx0, 1));
        mx0 = fmaxf(mx0, __shfl_xor_sync(0xffffffffu, mx0, 2));
        mx1 = fmaxf(mx1, __shfl_xor_sync(0xffffffffu, mx1, 1));
        mx1 = fmaxf(mx1, __shfl_xor_sync(0xffffffffu, mx1, 2));
        float mn0 = fmaxf(m0, mx0), mn1 = fmaxf(m1, mx1);
        float cr0 = __expf(m0 - mn0), cr1 = __expf(m1 - mn1);
        m0 = mn0; m1 = mn1;

        float rs0 = 0.f, rs1 = 0.f;
#pragma unroll
        for (int j = 0; j < 16; j++) {
            s[j][0] = __expf(s[j][0] - mn0);
            s[j][1] = __expf(s[j][1] - mn0);
            s[j][2] = __expf(s[j][2] - mn1);
            s[j][3] = __expf(s[j][3] - mn1);
            rs0 += s[j][0] + s[j][1];
            rs1 += s[j][2] + s[j][3];
        }
        rs0 += __shfl_xor_sync(0xffffffffu, rs0, 1);
        rs0 += __shfl_xor_sync(0xffffffffu, rs0, 2);
        rs1 += __shfl_xor_sync(0xffffffffu, rs1, 1);
        rs1 += __shfl_xor_sync(0xffffffffu, rs1, 2);
        l0 = l0 * cr0 + rs0;
        l1 = l1 * cr1 + rs1;

#pragma unroll
        for (int j = 0; j < 8; j++) {
            O[j][0] *= cr0; O[j][1] *= cr0;
            O[j][2] *= cr1; O[j][3] *= cr1;
        }

        uint32_t vb = smb + ATT_SV + buf * 34816 + (uint32_t)((lane & 7) * 272)
                      + (((lane >> 3) & 1) << 4);
#pragma unroll
        for (int ck = 0; ck < 8; ck++) {
            uint32_t ah[4], al[4];
            split2bf(s[2 * ck][0],     s[2 * ck][1],     ah[0], al[0]);
            split2bf(s[2 * ck][2],     s[2 * ck][3],     ah[1], al[1]);
            split2bf(s[2 * ck + 1][0], s[2 * ck + 1][1], ah[2], al[2]);
            split2bf(s[2 * ck + 1][2], s[2 * ck + 1][3], ah[3], al[3]);
#pragma unroll
            for (int jd = 0; jd < 8; jd++) {
                uint32_t bh[2], bl[2];
                uint32_t a = vb + jd * (8 * 272) + ck * 32;
                ldsm2(bh, a);
                mma_bf16(O[jd], ah, bh);
                mma_bf16(O[jd], al, bh);
                ldsm2(bl, a + 17408);
                mma_bf16(O[jd], ah, bl);
            }
        }
        __syncthreads();
    }

    float i0 = 1.f / l0, i1 = 1.f / l1;
    int r = q0 + wid * 16 + (lane >> 2);
    int cb = head * HDIM + (lane & 3) * 2;
#pragma unroll
    for (int jd = 0; jd < 8; jd++) {
        float* p0 = g_attn + (size_t)r * DMODEL + cb + jd * 8;
        float* p1 = g_attn + (size_t)(r + 8) * DMODEL + cb + jd * 8;
        p0[0] = O[jd][0] * i0; p0[1] = O[jd][1] * i0;
        p1[0] = O[jd][2] * i1; p1[1] = O[jd][3] * i1;
    }
}

// ============================================================================
extern "C" void kernel_launch(void* const* d_in, const int* in_sizes, int n_in,
                              void* d_out, int out_size)
{
    const float* hid = (const float*)d_in[0];
    const float* enc = (const float*)d_in[1];
    const float* rc  = (const float*)d_in[2];
    const float* rs  = (const float*)d_in[3];
    const float* Wq  = (const float*)d_in[4];  const float* bq = (const float*)d_in[5];
    const float* Wk  = (const float*)d_in[6];  const float* bk = (const float*)d_in[7];
    const float* Wv  = (const float*)d_in[8];  const float* bv = (const float*)d_in[9];
    const float* Wo  = (const float*)d_in[10]; const float* bo = (const float*)d_in[11];
    const float* lqd = (const float*)d_in[12]; const float* lqu = (const float*)d_in[13];
    const float* lkd = (const float*)d_in[14]; const float* lku = (const float*)d_in[15];
    const float* lvd = (const float*)d_in[16]; const float* lvu = (const float*)d_in[17];
    const float* lpd = (const float*)d_in[18]; const float* lpu = (const float*)d_in[19];
    const float* gq  = (const float*)d_in[20]; const float* btq = (const float*)d_in[21];
    const float* gk  = (const float*)d_in[22]; const float* btk = (const float*)d_in[23];

    static int attr_done = 0;
    if (!attr_done) {
        cudaFuncSetAttribute(attn_hmma, cudaFuncAttributeMaxDynamicSharedMemorySize,
                             ATT_SMEM);
        cudaFuncSetAttribute(gemm_hmma, cudaFuncAttributeMaxDynamicSharedMemorySize,
                             GEMM_SMEM);
        cudaFuncSetAttribute(gemm_qkv, cudaFuncAttributeMaxDynamicSharedMemorySize,
                             GEMM_SMEM);
        attr_done = 1;
    }

    float *pq, *pk, *pv, *pt, *pa;
    __half *pab, *ptb, *pldb, *pwbase;
    __nv_bfloat16 *pqh, *pql, *pkh, *pkl;
    cudaGetSymbolAddress((void**)&pq, g_q);
    cudaGetSymbolAddress((void**)&pk, g_k);
    cudaGetSymbolAddress((void**)&pv, g_v);
    cudaGetSymbolAddress((void**)&pt, g_t);
    cudaGetSymbolAddress((void**)&pa, g_attn);
    cudaGetSymbolAddress((void**)&pab, g_ab);
    cudaGetSymbolAddress((void**)&ptb, g_tb);
    cudaGetSymbolAddress((void**)&pldb, g_ldb);
    cudaGetSymbolAddress((void**)&pwbase, g_wb);
    cudaGetSymbolAddress((void**)&pqh, g_qhi);
    cudaGetSymbolAddress((void**)&pql, g_qlo);
    cudaGetSymbolAddress((void**)&pkh, g_khi);
    cudaGetSymbolAddress((void**)&pkl, g_klo);

    const int nHD = S_TOT * DMODEL;
    const int nW  = DMODEL * DMODEL;
    const int nLD = RANK_ * DMODEL;
    const int nLU = DMODEL * RANK_;

    dim3 qkv_grid(72, S_TOT / 128, 1);               // merged q/k/v: 1152 CTAs
    dim3 big_grid(DMODEL / 128, S_TOT / 128, 1);     // out-proj: 384 CTAs
    dim3 lora3_grid(3, S_TOT / 128, 8);
    dim3 lora1_grid(1, S_TOT / 128, 8);
    const int LORA_CH = H_CHUNKS / 8;                // 12

    // ---- A operand (h) + batched weight splits ----
    split_concat_kernel<<<(nHD + 255) / 256, 256>>>(hid, enc);
    split3_kernel<<<(3 * nW + 255) / 256, 256>>>(Wq, Wk, Wv, pwbase,
                                                 (size_t)DMODEL * LDB_BIG,
                                                 DMODEL, LDB_BIG, 0, nW);
    split3_kernel<<<(3 * nLU + 255) / 256, 256>>>(lqu, lku, lvu, pwbase,
                                                  (size_t)DMODEL * LDB_BIG,
                                                  RANK_, LDB_BIG, K2, nLU);
    split3_kernel<<<(3 * nLD + 255) / 256, 256>>>(lqd, lkd, lvd, pldb,
                                                  (size_t)RANK_ * K2,
                                                  DMODEL, K2, 0, nLD);

    // ---- batched lora-down for q,k,v ----
    cudaMemsetAsync(pt, 0, S_TOT * 3 * RANK_ * sizeof(float));
    gemm_hmma<<<lora3_grid, 128, GEMM_SMEM>>>(pab, K2, H_CHUNKS, nullptr, 0, 0,
                                              pldb, K2, nullptr, pt, 3 * RANK_,
                                              LORA_CH, 1, 0);
    tsplit_kernel<<<(S_TOT * 3 * RANK_ + 255) / 256, 256>>>(3);

    // ---- merged q/k/v projection GEMM ----
    gemm_qkv<<<qkv_grid, 128, GEMM_SMEM>>>(pab, ptb, pwbase, bq, bk, bv, pq, pk, pv);

    // ---- LN + RoPE -> bf16 split planes ----
    int ln_blocks = (S_TOT * NHEADS * 32 + 255) / 256;
    ln_rope_split<<<ln_blocks, 256>>>(pq, gq, btq, rc, rs, pqh, pql, 0.125f);
    ln_rope_split<<<ln_blocks, 256>>>(pk, gk, btk, rc, rs, pkh, pkl, 1.0f);
    vt_split<<<dim3(S_TOT / 64, NHEADS), 256>>>();

    attn_hmma<<<dim3(S_TOT / 128, NHEADS), 256, ATT_SMEM>>>();

    // ---- output projection (fused permute) ----
    split_a_kernel<<<(nHD + 255) / 256, 256>>>(pa);
    split_kernel_h<<<(nW + 255) / 256, 256>>>(Wo, pwbase, DMODEL, LDB_BIG, 0, 0, nW);
    split_kernel_h<<<(nLU + 255) / 256, 256>>>(lpu, pwbase, RANK_, LDB_BIG, K2, 0, nLU);
    split_kernel_h<<<(nLD + 255) / 256, 256>>>(lpd, pldb, DMODEL, K2, 0, 0, nLD);
    cudaMemsetAsync(pt, 0, S_TOT * RANK_ * sizeof(float));
    gemm_hmma<<<lora1_grid, 128, GEMM_SMEM>>>(pab, K2, H_CHUNKS, nullptr, 0, 0,
                                              pldb, K2, nullptr, pt, RANK_,
                                              LORA_CH, 1, 0);
    tsplit_kernel<<<(S_TOT * RANK_ + 255) / 256, 256>>>(1);
    gemm_hmma<<<big_grid, 128, GEMM_SMEM>>>(pab, K2, H_CHUNKS, ptb, 768, 0,
                                            pwbase, LDB_BIG, bo, (float*)d_out, DMODEL,
                                            BIG_CHUNKS, 0, 1);
}

// round 10
// speedup vs baseline: 1.1664x; 1.0953x over previous
#include <cuda_runtime.h>
#include <cuda_bf16.h>
#include <cuda_fp16.h>
#include <cstdint>

#define S_TOT 2048
#define DMODEL 3072
#define NHEADS 48
#define HDIM 64
#define RANK_ 128
#define TLEN 226
#define VLEN 1822

#define K2 (2 * DMODEL)       // 6144
#define LDB_BIG (K2 + 256)    // 6400
#define BIG_CHUNKS (LDB_BIG / 64)   // 100
#define H_CHUNKS (K2 / 64)          // 96

// ---------------- fp32 scratch ----------------------------------------------
__device__ __align__(256) float g_q[S_TOT * DMODEL];
__device__ __align__(256) float g_k[S_TOT * DMODEL];
__device__ __align__(256) float g_v[S_TOT * DMODEL];
__device__ __align__(256) float g_t[S_TOT * 3 * RANK_];
__device__ __align__(256) float g_attn[S_TOT * DMODEL];

// ---------------- fp16 split operand buffers ---------------------------------
__device__ __align__(256) __half g_ab[(size_t)S_TOT * K2];
__device__ __align__(256) __half g_tb[(size_t)S_TOT * 768];
__device__ __align__(256) __half g_wb[3][(size_t)DMODEL * LDB_BIG];
__device__ __align__(256) __half g_ldb[(size_t)(3 * RANK_) * K2];

// ---------------- attention fp16 planes (head-major) ------------------------
__device__ __align__(256) __half g_qhi[(size_t)NHEADS * S_TOT * HDIM];
__device__ __align__(256) __half g_qlo[(size_t)NHEADS * S_TOT * HDIM];
__device__ __align__(256) __half g_khi[(size_t)NHEADS * S_TOT * HDIM];
__device__ __align__(256) __half g_vthi[(size_t)NHEADS * HDIM * S_TOT];

// ============================================================================
// helpers
// ============================================================================
__device__ __forceinline__ uint32_t s2u(const void* p) {
    return (uint32_t)__cvta_generic_to_shared(p);
}
__device__ __forceinline__ void cpa16(uint32_t s, const void* g) {
    asm volatile("cp.async.cg.shared.global [%0], [%1], 16;" :: "r"(s), "l"(g));
}
__device__ __forceinline__ void cpa_commit() {
    asm volatile("cp.async.commit_group;" ::: "memory");
}
__device__ __forceinline__ void ldsm4(uint32_t* r, uint32_t a) {
    asm volatile("ldmatrix.sync.aligned.m8n8.x4.shared.b16 {%0,%1,%2,%3}, [%4];"
                 : "=r"(r[0]), "=r"(r[1]), "=r"(r[2]), "=r"(r[3]) : "r"(a));
}
__device__ __forceinline__ void ldsm2(uint32_t* r, uint32_t a) {
    asm volatile("ldmatrix.sync.aligned.m8n8.x2.shared.b16 {%0,%1}, [%2];"
                 : "=r"(r[0]), "=r"(r[1]) : "r"(a));
}
__device__ __forceinline__ void mma_f16(float* c, const uint32_t* a, const uint32_t* b) {
    asm volatile(
        "mma.sync.aligned.m16n8k16.row.col.f32.f16.f16.f32 "
        "{%0,%1,%2,%3}, {%4,%5,%6,%7}, {%8,%9}, {%0,%1,%2,%3};"
        : "+f"(c[0]), "+f"(c[1]), "+f"(c[2]), "+f"(c[3])
        : "r"(a[0]), "r"(a[1]), "r"(a[2]), "r"(a[3]), "r"(b[0]), "r"(b[1]));
}
__device__ __forceinline__ void split2h(float x, float y, uint32_t& hi, uint32_t& lo) {
    __half2 h = __floats2half2_rn(x, y);
    float hx = __half2float(__low2half(h)), hy = __half2float(__high2half(h));
    __half2 l = __floats2half2_rn(x - hx, y - hy);
    hi = *reinterpret_cast<uint32_t*>(&h);
    lo = *reinterpret_cast<uint32_t*>(&l);
}

// ============================================================================
// fp16 split kernels
// ============================================================================
__global__ void split_kernel_h(const float* __restrict__ src,
                               __half* __restrict__ dst,
                               int K, int dstStride, int dstOff, int amode, int n)
{
    int i = blockIdx.x * 256 + threadIdx.x;
    if (i >= n) return;
    int r = i / K, k = i % K;
    float x = src[i];
    __half hi = __float2half_rn(x);
    __half sec = amode ? __float2half_rn(x - __half2float(hi)) : hi;
    __half* d = dst + (size_t)r * dstStride + dstOff;
    d[k] = hi;
    d[K + k] = sec;
}

__global__ void split3_kernel(const float* __restrict__ s0,
                              const float* __restrict__ s1,
                              const float* __restrict__ s2,
                              __half* __restrict__ dst, size_t dstProjStride,
                              int K, int dstStride, int dstOff, int n)
{
    int i = blockIdx.x * 256 + threadIdx.x;
    if (i >= 3 * n) return;
    int p = i / n, j = i % n;
    const float* src = (p == 0) ? s0 : (p == 1) ? s1 : s2;
    int r = j / K, k = j % K;
    float x = src[j];
    __half hi = __float2half_rn(x);
    __half* d = dst + p * dstProjStride + (size_t)r * dstStride + dstOff;
    d[k] = hi;
    d[K + k] = hi;
}

__global__ void split_concat_kernel(const float* __restrict__ hid,
                                    const float* __restrict__ enc)
{
    int i = blockIdx.x * 256 + threadIdx.x;
    if (i >= S_TOT * DMODEL) return;
    int r = i / DMODEL, k = i % DMODEL;
    float x = (r < TLEN) ? enc[i] : hid[i - TLEN * DMODEL];
    __half hi = __float2half_rn(x);
    __half lo = __float2half_rn(x - __half2float(hi));
    __half* d = g_ab + (size_t)r * K2;
    d[k] = hi;
    d[DMODEL + k] = lo;
}

__global__ void split_a_kernel(const float* __restrict__ src)
{
    int i = blockIdx.x * 256 + threadIdx.x;
    if (i >= S_TOT * DMODEL) return;
    int r = i / DMODEL, k = i % DMODEL;
    float x = src[i];
    __half hi = __float2half_rn(x);
    __half lo = __float2half_rn(x - __half2float(hi));
    __half* d = g_ab + (size_t)r * K2;
    d[k] = hi;
    d[DMODEL + k] = lo;
}

__global__ void tsplit_kernel(int nproj)
{
    int n = S_TOT * nproj * RANK_;
    int i = blockIdx.x * 256 + threadIdx.x;
    if (i >= n) return;
    int kw = nproj * RANK_;
    int r = i / kw, k = i % kw;
    int p = k >> 7, kk = k & 127;
    float x = g_t[(size_t)r * kw + k];
    __half hi = __float2half_rn(x);
    __half lo = __float2half_rn(x - __half2float(hi));
    __half* d = g_tb + (size_t)r * 768 + p * 256;
    d[kk] = hi;
    d[128 + kk] = lo;
}

// ============================================================================
// GEMM core (BK=64, 4 warps 2x2, warp tile 64x64)
// ============================================================================
#define GEMM_SMEM (4 * 128 * 72 * 2)   // 73728 bytes

struct GemmCore {
    float acc[4][8][4];
    __half *smA, *smB;
    int tid, lane, wid, wm0, wn0, lrow, lch;

    __device__ __forceinline__ void init(__half* sm) {
        smA = sm; smB = sm + 2 * 128 * 72;
        tid = threadIdx.x; lane = tid & 31; wid = tid >> 5;
        wm0 = (wid & 1) * 64; wn0 = (wid >> 1) * 64;
        lrow = tid >> 3; lch = tid & 7;
#pragma unroll
        for (int i = 0; i < 4; i++)
#pragma unroll
            for (int j = 0; j < 8; j++)
#pragma unroll
                for (int e = 0; e < 4; e++) acc[i][j][e] = 0.f;
    }

    __device__ __forceinline__ void load_tile(int c, const __half* gaRow, int alda,
                                              const __half* gbRow, int ldb) {
        int b = c & 1;
        uint32_t sa = s2u(smA) + b * (128 * 144) + lrow * 144 + lch * 16;
        uint32_t sb = s2u(smB) + b * (128 * 144) + lrow * 144 + lch * 16;
#pragma unroll
        for (int i = 0; i < 8; i++) {
            int row = lrow + i * 16;
            cpa16(sa + i * (16 * 144), gaRow + (size_t)row * alda);
            cpa16(sb + i * (16 * 144), gbRow + (size_t)row * ldb);
        }
        cpa_commit();
    }

    __device__ __forceinline__ void compute(int c) {
        int b = c & 1;
        uint32_t saw = s2u(smA) + b * (128 * 144)
                       + (uint32_t)((wm0 + (lane & 15)) * 144) + ((lane >> 4) << 4);
        uint32_t sbw = s2u(smB) + b * (128 * 144)
                       + (uint32_t)((wn0 + (lane & 7)) * 144) + (((lane >> 3) & 1) << 4);
#pragma unroll
        for (int s = 0; s < 4; s++) {
            uint32_t af[4][4], bf[8][2];
#pragma unroll
            for (int i = 0; i < 4; i++) ldsm4(af[i], saw + i * (16 * 144) + s * 32);
#pragma unroll
            for (int j = 0; j < 8; j++) ldsm2(bf[j], sbw + j * (8 * 144) + s * 32);
#pragma unroll
            for (int i = 0; i < 4; i++)
#pragma unroll
                for (int j = 0; j < 8; j++)
                    mma_f16(acc[i][j], af[i], bf[j]);
        }
    }

    __device__ __forceinline__ void store(int r0, int c0, const float* bias,
                                          float* C, int ldc, int use_atomic, int permute) {
#pragma unroll
        for (int i = 0; i < 4; i++) {
#pragma unroll
            for (int j = 0; j < 8; j++) {
                int mm = r0 + wm0 + i * 16 + (lane >> 2);
                int nn = c0 + wn0 + j * 8 + (lane & 3) * 2;
                int row0 = mm, row1 = mm + 8;
                if (permute) {
                    row0 = (row0 < TLEN) ? row0 + VLEN : row0 - TLEN;
                    row1 = (row1 < TLEN) ? row1 + VLEN : row1 - TLEN;
                }
                float* p0 = C + (size_t)row0 * ldc + nn;
                float* p1 = C + (size_t)row1 * ldc + nn;
                if (use_atomic) {
                    atomicAdd(p0,     acc[i][j][0]);
                    atomicAdd(p0 + 1, acc[i][j][1]);
                    atomicAdd(p1,     acc[i][j][2]);
                    atomicAdd(p1 + 1, acc[i][j][3]);
                } else {
                    float b0v = bias ? bias[nn] : 0.f;
                    float b1v = bias ? bias[nn + 1] : 0.f;
                    p0[0] = acc[i][j][0] + b0v;
                    p0[1] = acc[i][j][1] + b1v;
                    p1[0] = acc[i][j][2] + b0v;
                    p1[1] = acc[i][j][3] + b1v;
                }
            }
        }
    }
};

__global__ void __launch_bounds__(128, 2) gemm_hmma(
    const __half* __restrict__ Ah, int lda_h, int h_chunks,
    const __half* __restrict__ At, int lda_t, int toff,
    const __half* __restrict__ B, int ldb,
    const float* __restrict__ bias, float* __restrict__ C, int ldc,
    int chunks, int use_atomic, int permute)
{
    extern __shared__ __half sm[];
    GemmCore g;
    g.init(sm);
    const int r0 = blockIdx.y << 7;
    const int c0 = blockIdx.x << 7;
    const int kbase = blockIdx.z * chunks * 64;

    auto aRow = [&](int c) -> const __half* {
        if (c < h_chunks) return Ah + (size_t)r0 * lda_h + kbase + c * 64 + g.lch * 8;
        return At + (size_t)r0 * lda_t + toff + (c - h_chunks) * 64 + g.lch * 8;
    };
    auto aLda = [&](int c) { return (c < h_chunks) ? lda_h : lda_t; };

    g.load_tile(0, aRow(0), aLda(0), B + (size_t)c0 * ldb + kbase + g.lch * 8, ldb);
    for (int c = 0; c < chunks; c++) {
        if (c + 1 < chunks) {
            g.load_tile(c + 1, aRow(c + 1), aLda(c + 1),
                        B + (size_t)c0 * ldb + kbase + (c + 1) * 64 + g.lch * 8, ldb);
            asm volatile("cp.async.wait_group 1;" ::: "memory");
        } else {
            asm volatile("cp.async.wait_group 0;" ::: "memory");
        }
        __syncthreads();
        g.compute(c);
        __syncthreads();
    }
    g.store(r0, c0, bias, C, ldc, use_atomic, permute);
}

__global__ void __launch_bounds__(128, 2) gemm_qkv(
    const __half* __restrict__ Ah, const __half* __restrict__ At,
    const __half* __restrict__ Wbase,
    const float* __restrict__ b0, const float* __restrict__ b1, const float* __restrict__ b2,
    float* __restrict__ C0, float* __restrict__ C1, float* __restrict__ C2)
{
    extern __shared__ __half sm[];
    GemmCore g;
    g.init(sm);
    const int proj = blockIdx.x / 24;
    const int c0 = (blockIdx.x % 24) << 7;
    const int r0 = blockIdx.y << 7;
    const __half* B = Wbase + (size_t)proj * DMODEL * LDB_BIG;
    const float* bias = (proj == 0) ? b0 : (proj == 1) ? b1 : b2;
    float* C = (proj == 0) ? C0 : (proj == 1) ? C1 : C2;
    const int toff = proj * 256;

    auto aRow = [&](int c) -> const __half* {
        if (c < H_CHUNKS) return Ah + (size_t)r0 * K2 + c * 64 + g.lch * 8;
        return At + (size_t)r0 * 768 + toff + (c - H_CHUNKS) * 64 + g.lch * 8;
    };
    auto aLda = [&](int c) { return (c < H_CHUNKS) ? K2 : 768; };

    g.load_tile(0, aRow(0), aLda(0), B + (size_t)c0 * LDB_BIG + g.lch * 8, LDB_BIG);
    for (int c = 0; c < BIG_CHUNKS; c++) {
        if (c + 1 < BIG_CHUNKS) {
            g.load_tile(c + 1, aRow(c + 1), aLda(c + 1),
                        B + (size_t)c0 * LDB_BIG + (c + 1) * 64 + g.lch * 8, LDB_BIG);
            asm volatile("cp.async.wait_group 1;" ::: "memory");
        } else {
            asm volatile("cp.async.wait_group 0;" ::: "memory");
        }
        __syncthreads();
        g.compute(c);
        __syncthreads();
    }
    g.store(r0, c0, bias, C, DMODEL, 0, 0);
}

// ============================================================================
// LN(64) + RoPE -> fp16 hi/lo planes (lo optional), head-major
// ============================================================================
__global__ void ln_rope_split(const float* __restrict__ x,
                              const float* __restrict__ gamma,
                              const float* __restrict__ beta,
                              const float* __restrict__ cosb,
                              const float* __restrict__ sinb,
                              __half* __restrict__ hi_out,
                              __half* __restrict__ lo_out,
                              float qscale)
{
    int gw = (blockIdx.x * blockDim.x + threadIdx.x) >> 5;
    int lane = threadIdx.x & 31;
    if (gw >= S_TOT * NHEADS) return;
    int pos = gw / NHEADS, head = gw % NHEADS;
    const float* row = x + (size_t)pos * DMODEL + head * HDIM;

    float2 v = ((const float2*)row)[lane];
    float sum = v.x + v.y;
#pragma unroll
    for (int o = 16; o; o >>= 1) sum += __shfl_xor_sync(0xffffffffu, sum, o);
    float mu = sum * (1.f / 64.f);
    float dx = v.x - mu, dy = v.y - mu;
    float vs = dx * dx + dy * dy;
#pragma unroll
    for (int o = 16; o; o >>= 1) vs += __shfl_xor_sync(0xffffffffu, vs, o);
    float inv = rsqrtf(vs * (1.f / 64.f) + 1e-5f);

    float y0 = dx * inv * gamma[lane * 2]     + beta[lane * 2];
    float y1 = dy * inv * gamma[lane * 2 + 1] + beta[lane * 2 + 1];

    if (pos >= TLEN) {
        int r = pos - TLEN;
        float c0 = cosb[r * HDIM + lane * 2], c1 = cosb[r * HDIM + lane * 2 + 1];
        float s0 = sinb[r * HDIM + lane * 2], s1 = sinb[r * HDIM + lane * 2 + 1];
        float t0 = y0 * c0 - y1 * s0;
        float t1 = y1 * c1 + y0 * s1;
        y0 = t0; y1 = t1;
    }
    y0 *= qscale; y1 *= qscale;

    size_t base = ((size_t)head * S_TOT + pos) * HDIM;
    uint32_t hi, lo;
    split2h(y0, y1, hi, lo);
    *reinterpret_cast<uint32_t*>(hi_out + base + lane * 2) = hi;
    if (lo_out)
        *reinterpret_cast<uint32_t*>(lo_out + base + lane * 2) = lo;
}

// ============================================================================
// V transpose: g_v -> fp16 Vt plane [head][d][pos]
// ============================================================================
__global__ void vt_split()
{
    __shared__ float tile[64][65];
    int head = blockIdx.y, p0 = blockIdx.x * 64;
    int tid = threadIdx.x;
#pragma unroll
    for (int i = 0; i < 16; i++) {
        int idx = tid + i * 256;
        int p = idx >> 6, d = idx & 63;
        tile[p][d] = g_v[(size_t)(p0 + p) * DMODEL + head * HDIM + d];
    }
    __syncthreads();
#pragma unroll
    for (int i = 0; i < 16; i++) {
        int idx = tid + i * 256;
        int d = idx >> 6, p = idx & 63;
        size_t o = ((size_t)head * HDIM + d) * S_TOT + p0 + p;
        g_vthi[o] = __float2half_rn(tile[p][d]);
    }
}

// ============================================================================
// HMMA flash attention: fp16 2-term, KT=64, 2 CTAs/SM.
// smem: Qhi 18432 | Qlo 18432 | K 2x9216 | V 2x9216 = 73728
// ============================================================================
#define ASQH 0
#define ASQL 18432
#define ASK  36864
#define ASV  55296
#define ATT_SMEM 73728
#define N_KCH (S_TOT / 64)   // 32

__global__ void __launch_bounds__(256, 2) attn_hmma()
{
    extern __shared__ char smc[];
    const int head = blockIdx.y;
    const int q0 = blockIdx.x * 128;
    const int tid = threadIdx.x;
    const int lane = tid & 31;
    const int wid = tid >> 5;
    const uint32_t smb = s2u(smc);

    // Q tile (hi/lo fp16), group 0
    {
        const __half* Qh = g_qhi + ((size_t)head * S_TOT + q0) * HDIM;
        const __half* Ql = g_qlo + ((size_t)head * S_TOT + q0) * HDIM;
#pragma unroll
        for (int i = 0; i < 4; i++) {
            int idx = tid + i * 256;
            int row = idx >> 3, ch = idx & 7;
            cpa16(smb + ASQH + row * 144 + ch * 16, Qh + row * HDIM + ch * 8);
            cpa16(smb + ASQL + row * 144 + ch * 16, Ql + row * HDIM + ch * 8);
        }
        cpa_commit();
    }

    auto load_kv = [&](int c) {
        int buf = c & 1;
        const __half* Kh = g_khi + ((size_t)head * S_TOT + c * 64) * HDIM;
        uint32_t kb = smb + ASK + buf * 9216;
#pragma unroll
        for (int i = 0; i < 2; i++) {
            int idx = tid + i * 256;
            int row = idx >> 3, ch = idx & 7;
            cpa16(kb + row * 144 + ch * 16, Kh + row * HDIM + ch * 8);
        }
        const __half* Vh = g_vthi + (size_t)head * HDIM * S_TOT + c * 64;
        uint32_t vb = smb + ASV + buf * 9216;
#pragma unroll
        for (int i = 0; i < 2; i++) {
            int idx = tid + i * 256;
            int d = idx >> 3, ch = idx & 7;
            cpa16(vb + d * 144 + ch * 16, Vh + (size_t)d * S_TOT + ch * 8);
        }
        cpa_commit();
    };

    load_kv(0);

    uint32_t aQh[4][4], aQl[4][4];
    float O[8][4];
#pragma unroll
    for (int j = 0; j < 8; j++)
#pragma unroll
        for (int e = 0; e < 4; e++) O[j][e] = 0.f;
    float m0 = -1e30f, m1 = -1e30f, l0 = 0.f, l1 = 0.f;

    for (int c = 0; c < N_KCH; c++) {
        if (c + 1 < N_KCH) {
            load_kv(c + 1);
            asm volatile("cp.async.wait_group 1;" ::: "memory");
        } else {
            asm volatile("cp.async.wait_group 0;" ::: "memory");
        }
        __syncthreads();

        if (c == 0) {
            uint32_t qa = smb + (uint32_t)((wid * 16 + (lane & 15)) * 144)
                          + ((lane >> 4) << 4);
#pragma unroll
            for (int kc = 0; kc < 4; kc++) {
                ldsm4(aQh[kc], qa + ASQH + kc * 32);
                ldsm4(aQl[kc], qa + ASQL + kc * 32);
            }
        }

        int buf = c & 1;
        float s[8][4];
#pragma unroll
        for (int j = 0; j < 8; j++)
#pragma unroll
            for (int e = 0; e < 4; e++) s[j][e] = 0.f;

        uint32_t kb = smb + ASK + buf * 9216 + (uint32_t)((lane & 7) * 144)
                      + (((lane >> 3) & 1) << 4);
#pragma unroll
        for (int kc = 0; kc < 4; kc++) {
#pragma unroll
            for (int j = 0; j < 8; j++) {
                uint32_t bh[2];
                ldsm2(bh, kb + j * (8 * 144) + kc * 32);
                mma_f16(s[j], aQh[kc], bh);
                mma_f16(s[j], aQl[kc], bh);
            }
        }

        // online softmax (rows r = lane>>2 and r+8)
        float mx0 = -1e30f, mx1 = -1e30f;
#pragma unroll
        for (int j = 0; j < 8; j++) {
            mx0 = fmaxf(mx0, fmaxf(s[j][0], s[j][1]));
            mx1 = fmaxf(mx1, fmaxf(s[j][2], s[j][3]));
        }
        mx0 = fmaxf(mx0, __shfl_xor_sync(0xffffffffu, mx0, 1));
        mx0 = fmaxf(mx0, __shfl_xor_sync(0xffffffffu, mx0, 2));
        mx1 = fmaxf(mx1, __shfl_xor_sync(0xffffffffu, mx1, 1));
        mx1 = fmaxf(mx1, __shfl_xor_sync(0xffffffffu, mx1, 2));
        float mn0 = fmaxf(m0, mx0), mn1 = fmaxf(m1, mx1);
        float cr0 = __expf(m0 - mn0), cr1 = __expf(m1 - mn1);
        m0 = mn0; m1 = mn1;

        float rs0 = 0.f, rs1 = 0.f;
#pragma unroll
        for (int j = 0; j < 8; j++) {
            s[j][0] = __expf(s[j][0] - mn0);
            s[j][1] = __expf(s[j][1] - mn0);
            s[j][2] = __expf(s[j][2] - mn1);
            s[j][3] = __expf(s[j][3] - mn1);
            rs0 += s[j][0] + s[j][1];
            rs1 += s[j][2] + s[j][3];
        }
        rs0 += __shfl_xor_sync(0xffffffffu, rs0, 1);
        rs0 += __shfl_xor_sync(0xffffffffu, rs0, 2);
        rs1 += __shfl_xor_sync(0xffffffffu, rs1, 1);
        rs1 += __shfl_xor_sync(0xffffffffu, rs1, 2);
        l0 = l0 * cr0 + rs0;
        l1 = l1 * cr1 + rs1;

#pragma unroll
        for (int j = 0; j < 8; j++) {
            O[j][0] *= cr0; O[j][1] *= cr0;
            O[j][2] *= cr1; O[j][3] *= cr1;
        }

        // PV: fp16 split of P, V hi-plane only
        uint32_t vb = smb + ASV + buf * 9216 + (uint32_t)((lane & 7) * 144)
                      + (((lane >> 3) & 1) << 4);
#pragma unroll
        for (int ck = 0; ck < 4; ck++) {
            uint32_t ah[4], al[4];
            split2h(s[2 * ck][0],     s[2 * ck][1],     ah[0], al[0]);
            split2h(s[2 * ck][2],     s[2 * ck][3],     ah[1], al[1]);
            split2h(s[2 * ck + 1][0], s[2 * ck + 1][1], ah[2], al[2]);
            split2h(s[2 * ck + 1][2], s[2 * ck + 1][3], ah[3], al[3]);
#pragma unroll
            for (int jd = 0; jd < 8; jd++) {
                uint32_t bh[2];
                ldsm2(bh, vb + jd * (8 * 144) + ck * 32);
                mma_f16(O[jd], ah, bh);
                mma_f16(O[jd], al, bh);
            }
        }
        __syncthreads();
    }

    float i0 = 1.f / l0, i1 = 1.f / l1;
    int r = q0 + wid * 16 + (lane >> 2);
    int cb = head * HDIM + (lane & 3) * 2;
#pragma unroll
    for (int jd = 0; jd < 8; jd++) {
        float* p0 = g_attn + (size_t)r * DMODEL + cb + jd * 8;
        float* p1 = g_attn + (size_t)(r + 8) * DMODEL + cb + jd * 8;
        p0[0] = O[jd][0] * i0; p0[1] = O[jd][1] * i0;
        p1[0] = O[jd][2] * i1; p1[1] = O[jd][3] * i1;
    }
}

// ============================================================================
extern "C" void kernel_launch(void* const* d_in, const int* in_sizes, int n_in,
                              void* d_out, int out_size)
{
    const float* hid = (const float*)d_in[0];
    const float* enc = (const float*)d_in[1];
    const float* rc  = (const float*)d_in[2];
    const float* rs  = (const float*)d_in[3];
    const float* Wq  = (const float*)d_in[4];  const float* bq = (const float*)d_in[5];
    const float* Wk  = (const float*)d_in[6];  const float* bk = (const float*)d_in[7];
    const float* Wv  = (const float*)d_in[8];  const float* bv = (const float*)d_in[9];
    const float* Wo  = (const float*)d_in[10]; const float* bo = (const float*)d_in[11];
    const float* lqd = (const float*)d_in[12]; const float* lqu = (const float*)d_in[13];
    const float* lkd = (const float*)d_in[14]; const float* lku = (const float*)d_in[15];
    const float* lvd = (const float*)d_in[16]; const float* lvu = (const float*)d_in[17];
    const float* lpd = (const float*)d_in[18]; const float* lpu = (const float*)d_in[19];
    const float* gq  = (const float*)d_in[20]; const float* btq = (const float*)d_in[21];
    const float* gk  = (const float*)d_in[22]; const float* btk = (const float*)d_in[23];

    static int attr_done = 0;
    if (!attr_done) {
        cudaFuncSetAttribute(attn_hmma, cudaFuncAttributeMaxDynamicSharedMemorySize,
                             ATT_SMEM);
        cudaFuncSetAttribute(gemm_hmma, cudaFuncAttributeMaxDynamicSharedMemorySize,
                             GEMM_SMEM);
        cudaFuncSetAttribute(gemm_qkv, cudaFuncAttributeMaxDynamicSharedMemorySize,
                             GEMM_SMEM);
        attr_done = 1;
    }

    float *pq, *pk, *pv, *pt, *pa;
    __half *pab, *ptb, *pldb, *pwbase;
    __half *pqh, *pql, *pkh;
    cudaGetSymbolAddress((void**)&pq, g_q);
    cudaGetSymbolAddress((void**)&pk, g_k);
    cudaGetSymbolAddress((void**)&pv, g_v);
    cudaGetSymbolAddress((void**)&pt, g_t);
    cudaGetSymbolAddress((void**)&pa, g_attn);
    cudaGetSymbolAddress((void**)&pab, g_ab);
    cudaGetSymbolAddress((void**)&ptb, g_tb);
    cudaGetSymbolAddress((void**)&pldb, g_ldb);
    cudaGetSymbolAddress((void**)&pwbase, g_wb);
    cudaGetSymbolAddress((void**)&pqh, g_qhi);
    cudaGetSymbolAddress((void**)&pql, g_qlo);
    cudaGetSymbolAddress((void**)&pkh, g_khi);

    const int nHD = S_TOT * DMODEL;
    const int nW  = DMODEL * DMODEL;
    const int nLD = RANK_ * DMODEL;
    const int nLU = DMODEL * RANK_;

    dim3 qkv_grid(72, S_TOT / 128, 1);
    dim3 big_grid(DMODEL / 128, S_TOT / 128, 1);
    dim3 lora3_grid(3, S_TOT / 128, 8);
    dim3 lora1_grid(1, S_TOT / 128, 8);
    const int LORA_CH = H_CHUNKS / 8;

    // ---- A operand + batched weight splits ----
    split_concat_kernel<<<(nHD + 255) / 256, 256>>>(hid, enc);
    split3_kernel<<<(3 * nW + 255) / 256, 256>>>(Wq, Wk, Wv, pwbase,
                                                 (size_t)DMODEL * LDB_BIG,
                                                 DMODEL, LDB_BIG, 0, nW);
    split3_kernel<<<(3 * nLU + 255) / 256, 256>>>(lqu, lku, lvu, pwbase,
                                                  (size_t)DMODEL * LDB_BIG,
                                                  RANK_, LDB_BIG, K2, nLU);
    split3_kernel<<<(3 * nLD + 255) / 256, 256>>>(lqd, lkd, lvd, pldb,
                                                  (size_t)RANK_ * K2,
                                                  DMODEL, K2, 0, nLD);

    // ---- batched lora-down for q,k,v ----
    cudaMemsetAsync(pt, 0, S_TOT * 3 * RANK_ * sizeof(float));
    gemm_hmma<<<lora3_grid, 128, GEMM_SMEM>>>(pab, K2, H_CHUNKS, nullptr, 0, 0,
                                              pldb, K2, nullptr, pt, 3 * RANK_,
                                              LORA_CH, 1, 0);
    tsplit_kernel<<<(S_TOT * 3 * RANK_ + 255) / 256, 256>>>(3);

    // ---- merged q/k/v projection GEMM ----
    gemm_qkv<<<qkv_grid, 128, GEMM_SMEM>>>(pab, ptb, pwbase, bq, bk, bv, pq, pk, pv);

    // ---- LN + RoPE -> fp16 planes (Q hi+lo, K hi only) ----
    int ln_blocks = (S_TOT * NHEADS * 32 + 255) / 256;
    ln_rope_split<<<ln_blocks, 256>>>(pq, gq, btq, rc, rs, pqh, pql, 0.125f);
    ln_rope_split<<<ln_blocks, 256>>>(pk, gk, btk, rc, rs, pkh, nullptr, 1.0f);
    vt_split<<<dim3(S_TOT / 64, NHEADS), 256>>>();

    attn_hmma<<<dim3(S_TOT / 128, NHEADS), 256, ATT_SMEM>>>();

    // ---- output projection (fused permute) ----
    split_a_kernel<<<(nHD + 255) / 256, 256>>>(pa);
    split_kernel_h<<<(nW + 255) / 256, 256>>>(Wo, pwbase, DMODEL, LDB_BIG, 0, 0, nW);
    split_kernel_h<<<(nLU + 255) / 256, 256>>>(lpu, pwbase, RANK_, LDB_BIG, K2, 0, nLU);
    split_kernel_h<<<(nLD + 255) / 256, 256>>>(lpd, pldb, DMODEL, K2, 0, 0, nLD);
    cudaMemsetAsync(pt, 0, S_TOT * RANK_ * sizeof(float));
    gemm_hmma<<<lora1_grid, 128, GEMM_SMEM>>>(pab, K2, H_CHUNKS, nullptr, 0, 0,
                                              pldb, K2, nullptr, pt, RANK_,
                                              LORA_CH, 1, 0);
    tsplit_kernel<<<(S_TOT * RANK_ + 255) / 256, 256>>>(1);
    gemm_hmma<<<big_grid, 128, GEMM_SMEM>>>(pab, K2, H_CHUNKS, ptb, 768, 0,
                                            pwbase, LDB_BIG, bo, (float*)d_out, DMODEL,
                                            BIG_CHUNKS, 0, 1);
}

// round 11
// speedup vs baseline: 1.1823x; 1.0137x over previous
#include <cuda_runtime.h>
#include <cuda_bf16.h>
#include <cuda_fp16.h>
#include <cstdint>

#define S_TOT 2048
#define DMODEL 3072
#define NHEADS 48
#define HDIM 64
#define RANK_ 128
#define TLEN 226
#define VLEN 1822

#define K2 (2 * DMODEL)       // 6144
#define LDB_BIG (K2 + 256)    // 6400
#define BIG_CHUNKS (LDB_BIG / 64)   // 100
#define H_CHUNKS (K2 / 64)          // 96

// ---------------- fp32 scratch ----------------------------------------------
__device__ __align__(256) float g_q[S_TOT * DMODEL];
__device__ __align__(256) float g_k[S_TOT * DMODEL];
__device__ __align__(256) float g_v[S_TOT * DMODEL];
__device__ __align__(256) float g_t[S_TOT * 3 * RANK_];

// ---------------- fp16 split operand buffers ---------------------------------
__device__ __align__(256) __half g_ab[(size_t)S_TOT * K2];
__device__ __align__(256) __half g_tb[(size_t)S_TOT * 768];
__device__ __align__(256) __half g_wb[3][(size_t)DMODEL * LDB_BIG];
__device__ __align__(256) __half g_ldb[(size_t)(3 * RANK_) * K2];

// ---------------- attention fp16 planes (head-major) ------------------------
__device__ __align__(256) __half g_qhi[(size_t)NHEADS * S_TOT * HDIM];
__device__ __align__(256) __half g_qlo[(size_t)NHEADS * S_TOT * HDIM];
__device__ __align__(256) __half g_khi[(size_t)NHEADS * S_TOT * HDIM];
__device__ __align__(256) __half g_vthi[(size_t)NHEADS * HDIM * S_TOT];

// ============================================================================
// helpers
// ============================================================================
__device__ __forceinline__ uint32_t s2u(const void* p) {
    return (uint32_t)__cvta_generic_to_shared(p);
}
__device__ __forceinline__ void cpa16(uint32_t s, const void* g) {
    asm volatile("cp.async.cg.shared.global [%0], [%1], 16;" :: "r"(s), "l"(g));
}
__device__ __forceinline__ void cpa_commit() {
    asm volatile("cp.async.commit_group;" ::: "memory");
}
__device__ __forceinline__ void ldsm4(uint32_t* r, uint32_t a) {
    asm volatile("ldmatrix.sync.aligned.m8n8.x4.shared.b16 {%0,%1,%2,%3}, [%4];"
                 : "=r"(r[0]), "=r"(r[1]), "=r"(r[2]), "=r"(r[3]) : "r"(a));
}
__device__ __forceinline__ void ldsm2(uint32_t* r, uint32_t a) {
    asm volatile("ldmatrix.sync.aligned.m8n8.x2.shared.b16 {%0,%1}, [%2];"
                 : "=r"(r[0]), "=r"(r[1]) : "r"(a));
}
__device__ __forceinline__ void mma_f16(float* c, const uint32_t* a, const uint32_t* b) {
    asm volatile(
        "mma.sync.aligned.m16n8k16.row.col.f32.f16.f16.f32 "
        "{%0,%1,%2,%3}, {%4,%5,%6,%7}, {%8,%9}, {%0,%1,%2,%3};"
        : "+f"(c[0]), "+f"(c[1]), "+f"(c[2]), "+f"(c[3])
        : "r"(a[0]), "r"(a[1]), "r"(a[2]), "r"(a[3]), "r"(b[0]), "r"(b[1]));
}
__device__ __forceinline__ void split2h(float x, float y, uint32_t& hi, uint32_t& lo) {
    __half2 h = __floats2half2_rn(x, y);
    float hx = __half2float(__low2half(h)), hy = __half2float(__high2half(h));
    __half2 l = __floats2half2_rn(x - hx, y - hy);
    hi = *reinterpret_cast<uint32_t*>(&h);
    lo = *reinterpret_cast<uint32_t*>(&l);
}

// ============================================================================
// fp16 split kernels
// ============================================================================
__global__ void split_kernel_h(const float* __restrict__ src,
                               __half* __restrict__ dst,
                               int K, int dstStride, int dstOff, int amode, int n)
{
    int i = blockIdx.x * 256 + threadIdx.x;
    if (i >= n) return;
    int r = i / K, k = i % K;
    float x = src[i];
    __half hi = __float2half_rn(x);
    __half sec = amode ? __float2half_rn(x - __half2float(hi)) : hi;
    __half* d = dst + (size_t)r * dstStride + dstOff;
    d[k] = hi;
    d[K + k] = sec;
}

__global__ void split3_kernel(const float* __restrict__ s0,
                              const float* __restrict__ s1,
                              const float* __restrict__ s2,
                              __half* __restrict__ dst, size_t dstProjStride,
                              int K, int dstStride, int dstOff, int n)
{
    int i = blockIdx.x * 256 + threadIdx.x;
    if (i >= 3 * n) return;
    int p = i / n, j = i % n;
    const float* src = (p == 0) ? s0 : (p == 1) ? s1 : s2;
    int r = j / K, k = j % K;
    float x = src[j];
    __half hi = __float2half_rn(x);
    __half* d = dst + p * dstProjStride + (size_t)r * dstStride + dstOff;
    d[k] = hi;
    d[K + k] = hi;
}

__global__ void split_concat_kernel(const float* __restrict__ hid,
                                    const float* __restrict__ enc)
{
    int i = blockIdx.x * 256 + threadIdx.x;
    if (i >= S_TOT * DMODEL) return;
    int r = i / DMODEL, k = i % DMODEL;
    float x = (r < TLEN) ? enc[i] : hid[i - TLEN * DMODEL];
    __half hi = __float2half_rn(x);
    __half lo = __float2half_rn(x - __half2float(hi));
    __half* d = g_ab + (size_t)r * K2;
    d[k] = hi;
    d[DMODEL + k] = lo;
}

__global__ void tsplit_kernel(int nproj)
{
    int n = S_TOT * nproj * RANK_;
    int i = blockIdx.x * 256 + threadIdx.x;
    if (i >= n) return;
    int kw = nproj * RANK_;
    int r = i / kw, k = i % kw;
    int p = k >> 7, kk = k & 127;
    float x = g_t[(size_t)r * kw + k];
    __half hi = __float2half_rn(x);
    __half lo = __float2half_rn(x - __half2float(hi));
    __half* d = g_tb + (size_t)r * 768 + p * 256;
    d[kk] = hi;
    d[128 + kk] = lo;
}

// ============================================================================
// GEMM core (BK=64, 4 warps 2x2, warp tile 64x64)
// ============================================================================
#define GEMM_SMEM (4 * 128 * 72 * 2)   // 73728 bytes

struct GemmCore {
    float acc[4][8][4];
    __half *smA, *smB;
    int tid, lane, wid, wm0, wn0, lrow, lch;

    __device__ __forceinline__ void init(__half* sm) {
        smA = sm; smB = sm + 2 * 128 * 72;
        tid = threadIdx.x; lane = tid & 31; wid = tid >> 5;
        wm0 = (wid & 1) * 64; wn0 = (wid >> 1) * 64;
        lrow = tid >> 3; lch = tid & 7;
#pragma unroll
        for (int i = 0; i < 4; i++)
#pragma unroll
            for (int j = 0; j < 8; j++)
#pragma unroll
                for (int e = 0; e < 4; e++) acc[i][j][e] = 0.f;
    }

    __device__ __forceinline__ void load_tile(int c, const __half* gaRow, int alda,
                                              const __half* gbRow, int ldb) {
        int b = c & 1;
        uint32_t sa = s2u(smA) + b * (128 * 144) + lrow * 144 + lch * 16;
        uint32_t sb = s2u(smB) + b * (128 * 144) + lrow * 144 + lch * 16;
#pragma unroll
        for (int i = 0; i < 8; i++) {
            int row = lrow + i * 16;
            cpa16(sa + i * (16 * 144), gaRow + (size_t)row * alda);
            cpa16(sb + i * (16 * 144), gbRow + (size_t)row * ldb);
        }
        cpa_commit();
    }

    __device__ __forceinline__ void compute(int c) {
        int b = c & 1;
        uint32_t saw = s2u(smA) + b * (128 * 144)
                       + (uint32_t)((wm0 + (lane & 15)) * 144) + ((lane >> 4) << 4);
        uint32_t sbw = s2u(smB) + b * (128 * 144)
                       + (uint32_t)((wn0 + (lane & 7)) * 144) + (((lane >> 3) & 1) << 4);
#pragma unroll
        for (int s = 0; s < 4; s++) {
            uint32_t af[4][4], bf[8][2];
#pragma unroll
            for (int i = 0; i < 4; i++) ldsm4(af[i], saw + i * (16 * 144) + s * 32);
#pragma unroll
            for (int j = 0; j < 8; j++) ldsm2(bf[j], sbw + j * (8 * 144) + s * 32);
#pragma unroll
            for (int i = 0; i < 4; i++)
#pragma unroll
                for (int j = 0; j < 8; j++)
                    mma_f16(acc[i][j], af[i], bf[j]);
        }
    }

    __device__ __forceinline__ void store(int r0, int c0, const float* bias,
                                          float* C, int ldc, int use_atomic, int permute) {
#pragma unroll
        for (int i = 0; i < 4; i++) {
#pragma unroll
            for (int j = 0; j < 8; j++) {
                int mm = r0 + wm0 + i * 16 + (lane >> 2);
                int nn = c0 + wn0 + j * 8 + (lane & 3) * 2;
                int row0 = mm, row1 = mm + 8;
                if (permute) {
                    row0 = (row0 < TLEN) ? row0 + VLEN : row0 - TLEN;
                    row1 = (row1 < TLEN) ? row1 + VLEN : row1 - TLEN;
                }
                float* p0 = C + (size_t)row0 * ldc + nn;
                float* p1 = C + (size_t)row1 * ldc + nn;
                float b0v = bias ? bias[nn] : 0.f;
                float b1v = bias ? bias[nn + 1] : 0.f;
                if (use_atomic) {
                    atomicAdd(p0,     acc[i][j][0] + b0v);
                    atomicAdd(p0 + 1, acc[i][j][1] + b1v);
                    atomicAdd(p1,     acc[i][j][2] + b0v);
                    atomicAdd(p1 + 1, acc[i][j][3] + b1v);
                } else {
                    p0[0] = acc[i][j][0] + b0v;
                    p0[1] = acc[i][j][1] + b1v;
                    p1[0] = acc[i][j][2] + b0v;
                    p1[1] = acc[i][j][3] + b1v;
                }
            }
        }
    }
};

// generic GEMM with split-K-aware two-source A (tail condition on GLOBAL chunk)
__global__ void __launch_bounds__(128, 2) gemm_hmma(
    const __half* __restrict__ Ah, int lda_h, int h_chunks,
    const __half* __restrict__ At, int lda_t, int toff,
    const __half* __restrict__ B, int ldb,
    const float* __restrict__ bias, float* __restrict__ C, int ldc,
    int chunks, int use_atomic, int permute)
{
    extern __shared__ __half sm[];
    GemmCore g;
    g.init(sm);
    const int r0 = blockIdx.y << 7;
    const int c0 = blockIdx.x << 7;
    const int kb64 = blockIdx.z * chunks;   // global chunk base

    auto aRow = [&](int c) -> const __half* {
        int gc = kb64 + c;
        if (gc < h_chunks) return Ah + (size_t)r0 * lda_h + gc * 64 + g.lch * 8;
        return At + (size_t)r0 * lda_t + toff + (gc - h_chunks) * 64 + g.lch * 8;
    };
    auto aLda = [&](int c) { return (kb64 + c < h_chunks) ? lda_h : lda_t; };
    auto bRow = [&](int c) -> const __half* {
        return B + (size_t)c0 * ldb + (kb64 + c) * 64 + g.lch * 8;
    };

    g.load_tile(0, aRow(0), aLda(0), bRow(0), ldb);
    for (int c = 0; c < chunks; c++) {
        if (c + 1 < chunks) {
            g.load_tile(c + 1, aRow(c + 1), aLda(c + 1), bRow(c + 1), ldb);
            asm volatile("cp.async.wait_group 1;" ::: "memory");
        } else {
            asm volatile("cp.async.wait_group 0;" ::: "memory");
        }
        __syncthreads();
        g.compute(c);
        __syncthreads();
    }
    const float* biasz = (blockIdx.z == 0) ? bias : nullptr;
    g.store(r0, c0, biasz, C, ldc, use_atomic, permute);
}

// merged q/k/v projection GEMM: grid (72, 16); proj = blockIdx.x / 24
__global__ void __launch_bounds__(128, 2) gemm_qkv(
    const __half* __restrict__ Ah, const __half* __restrict__ At,
    const __half* __restrict__ Wbase,
    const float* __restrict__ b0, const float* __restrict__ b1, const float* __restrict__ b2,
    float* __restrict__ C0, float* __restrict__ C1, float* __restrict__ C2)
{
    extern __shared__ __half sm[];
    GemmCore g;
    g.init(sm);
    const int proj = blockIdx.x / 24;
    const int c0 = (blockIdx.x % 24) << 7;
    const int r0 = blockIdx.y << 7;
    const __half* B = Wbase + (size_t)proj * DMODEL * LDB_BIG;
    const float* bias = (proj == 0) ? b0 : (proj == 1) ? b1 : b2;
    float* C = (proj == 0) ? C0 : (proj == 1) ? C1 : C2;
    const int toff = proj * 256;

    auto aRow = [&](int c) -> const __half* {
        if (c < H_CHUNKS) return Ah + (size_t)r0 * K2 + c * 64 + g.lch * 8;
        return At + (size_t)r0 * 768 + toff + (c - H_CHUNKS) * 64 + g.lch * 8;
    };
    auto aLda = [&](int c) { return (c < H_CHUNKS) ? K2 : 768; };

    g.load_tile(0, aRow(0), aLda(0), B + (size_t)c0 * LDB_BIG + g.lch * 8, LDB_BIG);
    for (int c = 0; c < BIG_CHUNKS; c++) {
        if (c + 1 < BIG_CHUNKS) {
            g.load_tile(c + 1, aRow(c + 1), aLda(c + 1),
                        B + (size_t)c0 * LDB_BIG + (c + 1) * 64 + g.lch * 8, LDB_BIG);
            asm volatile("cp.async.wait_group 1;" ::: "memory");
        } else {
            asm volatile("cp.async.wait_group 0;" ::: "memory");
        }
        __syncthreads();
        g.compute(c);
        __syncthreads();
    }
    g.store(r0, c0, bias, C, DMODEL, 0, 0);
}

// ============================================================================
// LN(64) + RoPE -> fp16 hi/lo planes (lo optional), head-major
// ============================================================================
__global__ void ln_rope_split(const float* __restrict__ x,
                              const float* __restrict__ gamma,
                              const float* __restrict__ beta,
                              const float* __restrict__ cosb,
                              const float* __restrict__ sinb,
                              __half* __restrict__ hi_out,
                              __half* __restrict__ lo_out,
                              float qscale)
{
    int gw = (blockIdx.x * blockDim.x + threadIdx.x) >> 5;
    int lane = threadIdx.x & 31;
    if (gw >= S_TOT * NHEADS) return;
    int pos = gw / NHEADS, head = gw % NHEADS;
    const float* row = x + (size_t)pos * DMODEL + head * HDIM;

    float2 v = ((const float2*)row)[lane];
    float sum = v.x + v.y;
#pragma unroll
    for (int o = 16; o; o >>= 1) sum += __shfl_xor_sync(0xffffffffu, sum, o);
    float mu = sum * (1.f / 64.f);
    float dx = v.x - mu, dy = v.y - mu;
    float vs = dx * dx + dy * dy;
#pragma unroll
    for (int o = 16; o; o >>= 1) vs += __shfl_xor_sync(0xffffffffu, vs, o);
    float inv = rsqrtf(vs * (1.f / 64.f) + 1e-5f);

    float y0 = dx * inv * gamma[lane * 2]     + beta[lane * 2];
    float y1 = dy * inv * gamma[lane * 2 + 1] + beta[lane * 2 + 1];

    if (pos >= TLEN) {
        int r = pos - TLEN;
        float c0 = cosb[r * HDIM + lane * 2], c1 = cosb[r * HDIM + lane * 2 + 1];
        float s0 = sinb[r * HDIM + lane * 2], s1 = sinb[r * HDIM + lane * 2 + 1];
        float t0 = y0 * c0 - y1 * s0;
        float t1 = y1 * c1 + y0 * s1;
        y0 = t0; y1 = t1;
    }
    y0 *= qscale; y1 *= qscale;

    size_t base = ((size_t)head * S_TOT + pos) * HDIM;
    uint32_t hi, lo;
    split2h(y0, y1, hi, lo);
    *reinterpret_cast<uint32_t*>(hi_out + base + lane * 2) = hi;
    if (lo_out)
        *reinterpret_cast<uint32_t*>(lo_out + base + lane * 2) = lo;
}

// ============================================================================
// V transpose: g_v -> fp16 Vt plane [head][d][pos]
// ============================================================================
__global__ void vt_split()
{
    __shared__ float tile[64][65];
    int head = blockIdx.y, p0 = blockIdx.x * 64;
    int tid = threadIdx.x;
#pragma unroll
    for (int i = 0; i < 16; i++) {
        int idx = tid + i * 256;
        int p = idx >> 6, d = idx & 63;
        tile[p][d] = g_v[(size_t)(p0 + p) * DMODEL + head * HDIM + d];
    }
    __syncthreads();
#pragma unroll
    for (int i = 0; i < 16; i++) {
        int idx = tid + i * 256;
        int d = idx >> 6, p = idx & 63;
        size_t o = ((size_t)head * HDIM + d) * S_TOT + p0 + p;
        g_vthi[o] = __float2half_rn(tile[p][d]);
    }
}

// ============================================================================
// HMMA flash attention: fp16 2-term, KT=64, 2 CTAs/SM.
// Epilogue writes fp16 hi/lo split of O DIRECTLY into g_ab (A operand for out-proj).
// ============================================================================
#define ASQH 0
#define ASQL 18432
#define ASK  36864
#define ASV  55296
#define ATT_SMEM 73728
#define N_KCH (S_TOT / 64)   // 32

__global__ void __launch_bounds__(256, 2) attn_hmma()
{
    extern __shared__ char smc[];
    const int head = blockIdx.y;
    const int q0 = blockIdx.x * 128;
    const int tid = threadIdx.x;
    const int lane = tid & 31;
    const int wid = tid >> 5;
    const uint32_t smb = s2u(smc);

    {
        const __half* Qh = g_qhi + ((size_t)head * S_TOT + q0) * HDIM;
        const __half* Ql = g_qlo + ((size_t)head * S_TOT + q0) * HDIM;
#pragma unroll
        for (int i = 0; i < 4; i++) {
            int idx = tid + i * 256;
            int row = idx >> 3, ch = idx & 7;
            cpa16(smb + ASQH + row * 144 + ch * 16, Qh + row * HDIM + ch * 8);
            cpa16(smb + ASQL + row * 144 + ch * 16, Ql + row * HDIM + ch * 8);
        }
        cpa_commit();
    }

    auto load_kv = [&](int c) {
        int buf = c & 1;
        const __half* Kh = g_khi + ((size_t)head * S_TOT + c * 64) * HDIM;
        uint32_t kb = smb + ASK + buf * 9216;
#pragma unroll
        for (int i = 0; i < 2; i++) {
            int idx = tid + i * 256;
            int row = idx >> 3, ch = idx & 7;
            cpa16(kb + row * 144 + ch * 16, Kh + row * HDIM + ch * 8);
        }
        const __half* Vh = g_vthi + (size_t)head * HDIM * S_TOT + c * 64;
        uint32_t vb = smb + ASV + buf * 9216;
#pragma unroll
        for (int i = 0; i < 2; i++) {
            int idx = tid + i * 256;
            int d = idx >> 3, ch = idx & 7;
            cpa16(vb + d * 144 + ch * 16, Vh + (size_t)d * S_TOT + ch * 8);
        }
        cpa_commit();
    };

    load_kv(0);

    uint32_t aQh[4][4], aQl[4][4];
    float O[8][4];
#pragma unroll
    for (int j = 0; j < 8; j++)
#pragma unroll
        for (int e = 0; e < 4; e++) O[j][e] = 0.f;
    float m0 = -1e30f, m1 = -1e30f, l0 = 0.f, l1 = 0.f;

    for (int c = 0; c < N_KCH; c++) {
        if (c + 1 < N_KCH) {
            load_kv(c + 1);
            asm volatile("cp.async.wait_group 1;" ::: "memory");
        } else {
            asm volatile("cp.async.wait_group 0;" ::: "memory");
        }
        __syncthreads();

        if (c == 0) {
            uint32_t qa = smb + (uint32_t)((wid * 16 + (lane & 15)) * 144)
                          + ((lane >> 4) << 4);
#pragma unroll
            for (int kc = 0; kc < 4; kc++) {
                ldsm4(aQh[kc], qa + ASQH + kc * 32);
                ldsm4(aQl[kc], qa + ASQL + kc * 32);
            }
        }

        int buf = c & 1;
        float s[8][4];
#pragma unroll
        for (int j = 0; j < 8; j++)
#pragma unroll
            for (int e = 0; e < 4; e++) s[j][e] = 0.f;

        uint32_t kb = smb + ASK + buf * 9216 + (uint32_t)((lane & 7) * 144)
                      + (((lane >> 3) & 1) << 4);
#pragma unroll
        for (int kc = 0; kc < 4; kc++) {
#pragma unroll
            for (int j = 0; j < 8; j++) {
                uint32_t bh[2];
                ldsm2(bh, kb + j * (8 * 144) + kc * 32);
                mma_f16(s[j], aQh[kc], bh);
                mma_f16(s[j], aQl[kc], bh);
            }
        }

        float mx0 = -1e30f, mx1 = -1e30f;
#pragma unroll
        for (int j = 0; j < 8; j++) {
            mx0 = fmaxf(mx0, fmaxf(s[j][0], s[j][1]));
            mx1 = fmaxf(mx1, fmaxf(s[j][2], s[j][3]));
        }
        mx0 = fmaxf(mx0, __shfl_xor_sync(0xffffffffu, mx0, 1));
        mx0 = fmaxf(mx0, __shfl_xor_sync(0xffffffffu, mx0, 2));
        mx1 = fmaxf(mx1, __shfl_xor_sync(0xffffffffu, mx1, 1));
        mx1 = fmaxf(mx1, __shfl_xor_sync(0xffffffffu, mx1, 2));
        float mn0 = fmaxf(m0, mx0), mn1 = fmaxf(m1, mx1);
        float cr0 = __expf(m0 - mn0), cr1 = __expf(m1 - mn1);
        m0 = mn0; m1 = mn1;

        float rs0 = 0.f, rs1 = 0.f;
#pragma unroll
        for (int j = 0; j < 8; j++) {
            s[j][0] = __expf(s[j][0] - mn0);
            s[j][1] = __expf(s[j][1] - mn0);
            s[j][2] = __expf(s[j][2] - mn1);
            s[j][3] = __expf(s[j][3] - mn1);
            rs0 += s[j][0] + s[j][1];
            rs1 += s[j][2] + s[j][3];
        }
        rs0 += __shfl_xor_sync(0xffffffffu, rs0, 1);
        rs0 += __shfl_xor_sync(0xffffffffu, rs0, 2);
        rs1 += __shfl_xor_sync(0xffffffffu, rs1, 1);
        rs1 += __shfl_xor_sync(0xffffffffu, rs1, 2);
        l0 = l0 * cr0 + rs0;
        l1 = l1 * cr1 + rs1;

#pragma unroll
        for (int j = 0; j < 8; j++) {
            O[j][0] *= cr0; O[j][1] *= cr0;
            O[j][2] *= cr1; O[j][3] *= cr1;
        }

        uint32_t vb = smb + ASV + buf * 9216 + (uint32_t)((lane & 7) * 144)
                      + (((lane >> 3) & 1) << 4);
#pragma unroll
        for (int ck = 0; ck < 4; ck++) {
            uint32_t ah[4], al[4];
            split2h(s[2 * ck][0],     s[2 * ck][1],     ah[0], al[0]);
            split2h(s[2 * ck][2],     s[2 * ck][3],     ah[1], al[1]);
            split2h(s[2 * ck + 1][0], s[2 * ck + 1][1], ah[2], al[2]);
            split2h(s[2 * ck + 1][2], s[2 * ck + 1][3], ah[3], al[3]);
#pragma unroll
            for (int jd = 0; jd < 8; jd++) {
                uint32_t bh[2];
                ldsm2(bh, vb + jd * (8 * 144) + ck * 32);
                mma_f16(O[jd], ah, bh);
                mma_f16(O[jd], al, bh);
            }
        }
        __syncthreads();
    }

    // ---- epilogue: write fp16 hi/lo split of O directly into g_ab ----
    float i0 = 1.f / l0, i1 = 1.f / l1;
    int r = q0 + wid * 16 + (lane >> 2);
    int cb = head * HDIM + (lane & 3) * 2;
    __half* row0 = g_ab + (size_t)r * K2;
    __half* row1 = g_ab + (size_t)(r + 8) * K2;
#pragma unroll
    for (int jd = 0; jd < 8; jd++) {
        int col = cb + jd * 8;
        uint32_t hi, lo;
        split2h(O[jd][0] * i0, O[jd][1] * i0, hi, lo);
        *reinterpret_cast<uint32_t*>(row0 + col) = hi;
        *reinterpret_cast<uint32_t*>(row0 + DMODEL + col) = lo;
        split2h(O[jd][2] * i1, O[jd][3] * i1, hi, lo);
        *reinterpret_cast<uint32_t*>(row1 + col) = hi;
        *reinterpret_cast<uint32_t*>(row1 + DMODEL + col) = lo;
    }
}

// ============================================================================
extern "C" void kernel_launch(void* const* d_in, const int* in_sizes, int n_in,
                              void* d_out, int out_size)
{
    const float* hid = (const float*)d_in[0];
    const float* enc = (const float*)d_in[1];
    const float* rc  = (const float*)d_in[2];
    const float* rs  = (const float*)d_in[3];
    const float* Wq  = (const float*)d_in[4];  const float* bq = (const float*)d_in[5];
    const float* Wk  = (const float*)d_in[6];  const float* bk = (const float*)d_in[7];
    const float* Wv  = (const float*)d_in[8];  const float* bv = (const float*)d_in[9];
    const float* Wo  = (const float*)d_in[10]; const float* bo = (const float*)d_in[11];
    const float* lqd = (const float*)d_in[12]; const float* lqu = (const float*)d_in[13];
    const float* lkd = (const float*)d_in[14]; const float* lku = (const float*)d_in[15];
    const float* lvd = (const float*)d_in[16]; const float* lvu = (const float*)d_in[17];
    const float* lpd = (const float*)d_in[18]; const float* lpu = (const float*)d_in[19];
    const float* gq  = (const float*)d_in[20]; const float* btq = (const float*)d_in[21];
    const float* gk  = (const float*)d_in[22]; const float* btk = (const float*)d_in[23];

    static int attr_done = 0;
    if (!attr_done) {
        cudaFuncSetAttribute(attn_hmma, cudaFuncAttributeMaxDynamicSharedMemorySize,
                             ATT_SMEM);
        cudaFuncSetAttribute(gemm_hmma, cudaFuncAttributeMaxDynamicSharedMemorySize,
                             GEMM_SMEM);
        cudaFuncSetAttribute(gemm_qkv, cudaFuncAttributeMaxDynamicSharedMemorySize,
                             GEMM_SMEM);
        attr_done = 1;
    }

    float *pq, *pk, *pv, *pt;
    __half *pab, *ptb, *pldb, *pwbase;
    __half *pqh, *pql, *pkh;
    cudaGetSymbolAddress((void**)&pq, g_q);
    cudaGetSymbolAddress((void**)&pk, g_k);
    cudaGetSymbolAddress((void**)&pv, g_v);
    cudaGetSymbolAddress((void**)&pt, g_t);
    cudaGetSymbolAddress((void**)&pab, g_ab);
    cudaGetSymbolAddress((void**)&ptb, g_tb);
    cudaGetSymbolAddress((void**)&pldb, g_ldb);
    cudaGetSymbolAddress((void**)&pwbase, g_wb);
    cudaGetSymbolAddress((void**)&pqh, g_qhi);
    cudaGetSymbolAddress((void**)&pql, g_qlo);
    cudaGetSymbolAddress((void**)&pkh, g_khi);

    const int nHD = S_TOT * DMODEL;
    const int nW  = DMODEL * DMODEL;
    const int nLD = RANK_ * DMODEL;
    const int nLU = DMODEL * RANK_;

    dim3 qkv_grid(72, S_TOT / 128, 1);
    dim3 oproj_grid(DMODEL / 128, S_TOT / 128, 2);   // split-K = 2
    dim3 lora3_grid(3, S_TOT / 128, 8);
    dim3 lora1_grid(1, S_TOT / 128, 8);
    const int LORA_CH = H_CHUNKS / 8;

    // ---- A operand + batched weight splits ----
    split_concat_kernel<<<(nHD + 255) / 256, 256>>>(hid, enc);
    split3_kernel<<<(3 * nW + 255) / 256, 256>>>(Wq, Wk, Wv, pwbase,
                                                 (size_t)DMODEL * LDB_BIG,
                                                 DMODEL, LDB_BIG, 0, nW);
    split3_kernel<<<(3 * nLU + 255) / 256, 256>>>(lqu, lku, lvu, pwbase,
                                                  (size_t)DMODEL * LDB_BIG,
                                                  RANK_, LDB_BIG, K2, nLU);
    split3_kernel<<<(3 * nLD + 255) / 256, 256>>>(lqd, lkd, lvd, pldb,
                                                  (size_t)RANK_ * K2,
                                                  DMODEL, K2, 0, nLD);

    // ---- batched lora-down for q,k,v ----
    cudaMemsetAsync(pt, 0, S_TOT * 3 * RANK_ * sizeof(float));
    gemm_hmma<<<lora3_grid, 128, GEMM_SMEM>>>(pab, K2, BIG_CHUNKS /*no tail*/, nullptr, 0, 0,
                                              pldb, K2, nullptr, pt, 3 * RANK_,
                                              LORA_CH, 1, 0);
    tsplit_kernel<<<(S_TOT * 3 * RANK_ + 255) / 256, 256>>>(3);

    // ---- merged q/k/v projection GEMM ----
    gemm_qkv<<<qkv_grid, 128, GEMM_SMEM>>>(pab, ptb, pwbase, bq, bk, bv, pq, pk, pv);

    // ---- LN + RoPE -> fp16 planes (Q hi+lo, K hi only) ----
    int ln_blocks = (S_TOT * NHEADS * 32 + 255) / 256;
    ln_rope_split<<<ln_blocks, 256>>>(pq, gq, btq, rc, rs, pqh, pql, 0.125f);
    ln_rope_split<<<ln_blocks, 256>>>(pk, gk, btk, rc, rs, pkh, nullptr, 1.0f);
    vt_split<<<dim3(S_TOT / 64, NHEADS), 256>>>();

    // ---- attention (writes fp16 split of O directly into g_ab) ----
    attn_hmma<<<dim3(S_TOT / 128, NHEADS), 256, ATT_SMEM>>>();

    // ---- output projection ----
    split_kernel_h<<<(nW + 255) / 256, 256>>>(Wo, pwbase, DMODEL, LDB_BIG, 0, 0, nW);
    split_kernel_h<<<(nLU + 255) / 256, 256>>>(lpu, pwbase, RANK_, LDB_BIG, K2, 0, nLU);
    split_kernel_h<<<(nLD + 255) / 256, 256>>>(lpd, pldb, DMODEL, K2, 0, 0, nLD);
    cudaMemsetAsync(pt, 0, S_TOT * RANK_ * sizeof(float));
    gemm_hmma<<<lora1_grid, 128, GEMM_SMEM>>>(pab, K2, BIG_CHUNKS /*no tail*/, nullptr, 0, 0,
                                              pldb, K2, nullptr, pt, RANK_,
                                              LORA_CH, 1, 0);
    tsplit_kernel<<<(S_TOT * RANK_ + 255) / 256, 256>>>(1);
    // split-K=2 out-proj: zero d_out, atomic accumulate (bias on z==0), fused permute
    cudaMemsetAsync(d_out, 0, (size_t)out_size * sizeof(float));
    gemm_hmma<<<oproj_grid, 128, GEMM_SMEM>>>(pab, K2, H_CHUNKS, ptb, 768, 0,
                                              pwbase, LDB_BIG, bo, (float*)d_out, DMODEL,
                                              BIG_CHUNKS / 2, 1, 1);
}

// round 12
// speedup vs baseline: 1.2496x; 1.0569x over previous
#include <cuda_runtime.h>
#include <cuda_bf16.h>
#include <cuda_fp16.h>
#include <cstdint>

#define S_TOT 2048
#define DMODEL 3072
#define NHEADS 48
#define HDIM 64
#define RANK_ 128
#define TLEN 226
#define VLEN 1822

#define K2 (2 * DMODEL)       // 6144
#define LDB_BIG (K2 + 256)    // 6400
#define BIG_CHUNKS (LDB_BIG / 64)   // 100
#define H_CHUNKS (K2 / 64)          // 96
#define HI_CHUNKS (DMODEL / 64)     // 48 (hi-plane-only K for LoRA-down)

// ---------------- fp32 scratch ----------------------------------------------
__device__ __align__(256) float g_q[S_TOT * DMODEL];
__device__ __align__(256) float g_k[S_TOT * DMODEL];
__device__ __align__(256) float g_v[S_TOT * DMODEL];
__device__ __align__(256) float g_t[S_TOT * 3 * RANK_];

// ---------------- fp16 split operand buffers ---------------------------------
__device__ __align__(256) __half g_ab[(size_t)S_TOT * K2];
__device__ __align__(256) __half g_tb[(size_t)S_TOT * 768];
__device__ __align__(256) __half g_wb[3][(size_t)DMODEL * LDB_BIG];
__device__ __align__(256) __half g_ldb[(size_t)(3 * RANK_) * K2];

// ---------------- attention fp16 planes (head-major) ------------------------
__device__ __align__(256) __half g_qhi[(size_t)NHEADS * S_TOT * HDIM];
__device__ __align__(256) __half g_qlo[(size_t)NHEADS * S_TOT * HDIM];
__device__ __align__(256) __half g_khi[(size_t)NHEADS * S_TOT * HDIM];
__device__ __align__(256) __half g_vthi[(size_t)NHEADS * HDIM * S_TOT];

// ============================================================================
// helpers
// ============================================================================
__device__ __forceinline__ uint32_t s2u(const void* p) {
    return (uint32_t)__cvta_generic_to_shared(p);
}
__device__ __forceinline__ void cpa16(uint32_t s, const void* g) {
    asm volatile("cp.async.cg.shared.global [%0], [%1], 16;" :: "r"(s), "l"(g));
}
__device__ __forceinline__ void cpa_commit() {
    asm volatile("cp.async.commit_group;" ::: "memory");
}
__device__ __forceinline__ void ldsm4(uint32_t* r, uint32_t a) {
    asm volatile("ldmatrix.sync.aligned.m8n8.x4.shared.b16 {%0,%1,%2,%3}, [%4];"
                 : "=r"(r[0]), "=r"(r[1]), "=r"(r[2]), "=r"(r[3]) : "r"(a));
}
__device__ __forceinline__ void ldsm2(uint32_t* r, uint32_t a) {
    asm volatile("ldmatrix.sync.aligned.m8n8.x2.shared.b16 {%0,%1}, [%2];"
                 : "=r"(r[0]), "=r"(r[1]) : "r"(a));
}
__device__ __forceinline__ void mma_f16(float* c, const uint32_t* a, const uint32_t* b) {
    asm volatile(
        "mma.sync.aligned.m16n8k16.row.col.f32.f16.f16.f32 "
        "{%0,%1,%2,%3}, {%4,%5,%6,%7}, {%8,%9}, {%0,%1,%2,%3};"
        : "+f"(c[0]), "+f"(c[1]), "+f"(c[2]), "+f"(c[3])
        : "r"(a[0]), "r"(a[1]), "r"(a[2]), "r"(a[3]), "r"(b[0]), "r"(b[1]));
}
__device__ __forceinline__ void split2h(float x, float y, uint32_t& hi, uint32_t& lo) {
    __half2 h = __floats2half2_rn(x, y);
    float hx = __half2float(__low2half(h)), hy = __half2float(__high2half(h));
    __half2 l = __floats2half2_rn(x - hx, y - hy);
    hi = *reinterpret_cast<uint32_t*>(&h);
    lo = *reinterpret_cast<uint32_t*>(&l);
}
__device__ __forceinline__ uint32_t pack2h(float x, float y) {
    __half2 h = __floats2half2_rn(x, y);
    return *reinterpret_cast<uint32_t*>(&h);
}

// ============================================================================
// fp16 split kernels
// ============================================================================
__global__ void split_kernel_h(const float* __restrict__ src,
                               __half* __restrict__ dst,
                               int K, int dstStride, int dstOff, int amode, int n)
{
    int i = blockIdx.x * 256 + threadIdx.x;
    if (i >= n) return;
    int r = i / K, k = i % K;
    float x = src[i];
    __half hi = __float2half_rn(x);
    __half sec = amode ? __float2half_rn(x - __half2float(hi)) : hi;
    __half* d = dst + (size_t)r * dstStride + dstOff;
    d[k] = hi;
    d[K + k] = sec;
}

__global__ void split3_kernel(const float* __restrict__ s0,
                              const float* __restrict__ s1,
                              const float* __restrict__ s2,
                              __half* __restrict__ dst, size_t dstProjStride,
                              int K, int dstStride, int dstOff, int n)
{
    int i = blockIdx.x * 256 + threadIdx.x;
    if (i >= 3 * n) return;
    int p = i / n, j = i % n;
    const float* src = (p == 0) ? s0 : (p == 1) ? s1 : s2;
    int r = j / K, k = j % K;
    float x = src[j];
    __half hi = __float2half_rn(x);
    __half* d = dst + p * dstProjStride + (size_t)r * dstStride + dstOff;
    d[k] = hi;
    d[K + k] = hi;
}

__global__ void split_concat_kernel(const float* __restrict__ hid,
                                    const float* __restrict__ enc)
{
    int i = blockIdx.x * 256 + threadIdx.x;
    if (i >= S_TOT * DMODEL) return;
    int r = i / DMODEL, k = i % DMODEL;
    float x = (r < TLEN) ? enc[i] : hid[i - TLEN * DMODEL];
    __half hi = __float2half_rn(x);
    __half lo = __float2half_rn(x - __half2float(hi));
    __half* d = g_ab + (size_t)r * K2;
    d[k] = hi;
    d[DMODEL + k] = lo;
}

__global__ void tsplit_kernel(int nproj)
{
    int n = S_TOT * nproj * RANK_;
    int i = blockIdx.x * 256 + threadIdx.x;
    if (i >= n) return;
    int kw = nproj * RANK_;
    int r = i / kw, k = i % kw;
    int p = k >> 7, kk = k & 127;
    float x = g_t[(size_t)r * kw + k];
    __half hi = __float2half_rn(x);
    __half lo = __float2half_rn(x - __half2float(hi));
    __half* d = g_tb + (size_t)r * 768 + p * 256;
    d[kk] = hi;
    d[128 + kk] = lo;
}

// ============================================================================
// GEMM core (BK=64, 4 warps 2x2, warp tile 64x64)
// ============================================================================
#define GEMM_SMEM (4 * 128 * 72 * 2)   // 73728 bytes

struct GemmCore {
    float acc[4][8][4];
    __half *smA, *smB;
    int tid, lane, wid, wm0, wn0, lrow, lch;

    __device__ __forceinline__ void init(__half* sm) {
        smA = sm; smB = sm + 2 * 128 * 72;
        tid = threadIdx.x; lane = tid & 31; wid = tid >> 5;
        wm0 = (wid & 1) * 64; wn0 = (wid >> 1) * 64;
        lrow = tid >> 3; lch = tid & 7;
#pragma unroll
        for (int i = 0; i < 4; i++)
#pragma unroll
            for (int j = 0; j < 8; j++)
#pragma unroll
                for (int e = 0; e < 4; e++) acc[i][j][e] = 0.f;
    }

    __device__ __forceinline__ void load_tile(int c, const __half* gaRow, int alda,
                                              const __half* gbRow, int ldb) {
        int b = c & 1;
        uint32_t sa = s2u(smA) + b * (128 * 144) + lrow * 144 + lch * 16;
        uint32_t sb = s2u(smB) + b * (128 * 144) + lrow * 144 + lch * 16;
#pragma unroll
        for (int i = 0; i < 8; i++) {
            int row = lrow + i * 16;
            cpa16(sa + i * (16 * 144), gaRow + (size_t)row * alda);
            cpa16(sb + i * (16 * 144), gbRow + (size_t)row * ldb);
        }
        cpa_commit();
    }

    __device__ __forceinline__ void compute(int c) {
        int b = c & 1;
        uint32_t saw = s2u(smA) + b * (128 * 144)
                       + (uint32_t)((wm0 + (lane & 15)) * 144) + ((lane >> 4) << 4);
        uint32_t sbw = s2u(smB) + b * (128 * 144)
                       + (uint32_t)((wn0 + (lane & 7)) * 144) + (((lane >> 3) & 1) << 4);
#pragma unroll
        for (int s = 0; s < 4; s++) {
            uint32_t af[4][4], bf[8][2];
#pragma unroll
            for (int i = 0; i < 4; i++) ldsm4(af[i], saw + i * (16 * 144) + s * 32);
#pragma unroll
            for (int j = 0; j < 8; j++) ldsm2(bf[j], sbw + j * (8 * 144) + s * 32);
#pragma unroll
            for (int i = 0; i < 4; i++)
#pragma unroll
                for (int j = 0; j < 8; j++)
                    mma_f16(acc[i][j], af[i], bf[j]);
        }
    }

    __device__ __forceinline__ void store(int r0, int c0, const float* bias,
                                          float* C, int ldc, int use_atomic, int permute) {
#pragma unroll
        for (int i = 0; i < 4; i++) {
#pragma unroll
            for (int j = 0; j < 8; j++) {
                int mm = r0 + wm0 + i * 16 + (lane >> 2);
                int nn = c0 + wn0 + j * 8 + (lane & 3) * 2;
                int row0 = mm, row1 = mm + 8;
                if (permute) {
                    row0 = (row0 < TLEN) ? row0 + VLEN : row0 - TLEN;
                    row1 = (row1 < TLEN) ? row1 + VLEN : row1 - TLEN;
                }
                float* p0 = C + (size_t)row0 * ldc + nn;
                float* p1 = C + (size_t)row1 * ldc + nn;
                float b0v = bias ? bias[nn] : 0.f;
                float b1v = bias ? bias[nn + 1] : 0.f;
                if (use_atomic) {
                    atomicAdd(p0,     acc[i][j][0] + b0v);
                    atomicAdd(p0 + 1, acc[i][j][1] + b1v);
                    atomicAdd(p1,     acc[i][j][2] + b0v);
                    atomicAdd(p1 + 1, acc[i][j][3] + b1v);
                } else {
                    p0[0] = acc[i][j][0] + b0v;
                    p0[1] = acc[i][j][1] + b1v;
                    p1[0] = acc[i][j][2] + b0v;
                    p1[1] = acc[i][j][3] + b1v;
                }
            }
        }
    }
};

// generic GEMM with split-K-aware two-source A (tail condition on GLOBAL chunk)
__global__ void __launch_bounds__(128, 2) gemm_hmma(
    const __half* __restrict__ Ah, int lda_h, int h_chunks,
    const __half* __restrict__ At, int lda_t, int toff,
    const __half* __restrict__ B, int ldb,
    const float* __restrict__ bias, float* __restrict__ C, int ldc,
    int chunks, int use_atomic, int permute)
{
    extern __shared__ __half sm[];
    GemmCore g;
    g.init(sm);
    const int r0 = blockIdx.y << 7;
    const int c0 = blockIdx.x << 7;
    const int kb64 = blockIdx.z * chunks;

    auto aRow = [&](int c) -> const __half* {
        int gc = kb64 + c;
        if (gc < h_chunks) return Ah + (size_t)r0 * lda_h + gc * 64 + g.lch * 8;
        return At + (size_t)r0 * lda_t + toff + (gc - h_chunks) * 64 + g.lch * 8;
    };
    auto aLda = [&](int c) { return (kb64 + c < h_chunks) ? lda_h : lda_t; };
    auto bRow = [&](int c) -> const __half* {
        return B + (size_t)c0 * ldb + (kb64 + c) * 64 + g.lch * 8;
    };

    g.load_tile(0, aRow(0), aLda(0), bRow(0), ldb);
    for (int c = 0; c < chunks; c++) {
        if (c + 1 < chunks) {
            g.load_tile(c + 1, aRow(c + 1), aLda(c + 1), bRow(c + 1), ldb);
            asm volatile("cp.async.wait_group 1;" ::: "memory");
        } else {
            asm volatile("cp.async.wait_group 0;" ::: "memory");
        }
        __syncthreads();
        g.compute(c);
        __syncthreads();
    }
    const float* biasz = (blockIdx.z == 0) ? bias : nullptr;
    g.store(r0, c0, biasz, C, ldc, use_atomic, permute);
}

// merged q/k/v projection GEMM
__global__ void __launch_bounds__(128, 2) gemm_qkv(
    const __half* __restrict__ Ah, const __half* __restrict__ At,
    const __half* __restrict__ Wbase,
    const float* __restrict__ b0, const float* __restrict__ b1, const float* __restrict__ b2,
    float* __restrict__ C0, float* __restrict__ C1, float* __restrict__ C2)
{
    extern __shared__ __half sm[];
    GemmCore g;
    g.init(sm);
    const int proj = blockIdx.x / 24;
    const int c0 = (blockIdx.x % 24) << 7;
    const int r0 = blockIdx.y << 7;
    const __half* B = Wbase + (size_t)proj * DMODEL * LDB_BIG;
    const float* bias = (proj == 0) ? b0 : (proj == 1) ? b1 : b2;
    float* C = (proj == 0) ? C0 : (proj == 1) ? C1 : C2;
    const int toff = proj * 256;

    auto aRow = [&](int c) -> const __half* {
        if (c < H_CHUNKS) return Ah + (size_t)r0 * K2 + c * 64 + g.lch * 8;
        return At + (size_t)r0 * 768 + toff + (c - H_CHUNKS) * 64 + g.lch * 8;
    };
    auto aLda = [&](int c) { return (c < H_CHUNKS) ? K2 : 768; };

    g.load_tile(0, aRow(0), aLda(0), B + (size_t)c0 * LDB_BIG + g.lch * 8, LDB_BIG);
    for (int c = 0; c < BIG_CHUNKS; c++) {
        if (c + 1 < BIG_CHUNKS) {
            g.load_tile(c + 1, aRow(c + 1), aLda(c + 1),
                        B + (size_t)c0 * LDB_BIG + (c + 1) * 64 + g.lch * 8, LDB_BIG);
            asm volatile("cp.async.wait_group 1;" ::: "memory");
        } else {
            asm volatile("cp.async.wait_group 0;" ::: "memory");
        }
        __syncthreads();
        g.compute(c);
        __syncthreads();
    }
    g.store(r0, c0, bias, C, DMODEL, 0, 0);
}

// ============================================================================
// LN(64) + RoPE -> fp16 hi/lo planes (lo optional), head-major
// ============================================================================
__global__ void ln_rope_split(const float* __restrict__ x,
                              const float* __restrict__ gamma,
                              const float* __restrict__ beta,
                              const float* __restrict__ cosb,
                              const float* __restrict__ sinb,
                              __half* __restrict__ hi_out,
                              __half* __restrict__ lo_out,
                              float qscale)
{
    int gw = (blockIdx.x * blockDim.x + threadIdx.x) >> 5;
    int lane = threadIdx.x & 31;
    if (gw >= S_TOT * NHEADS) return;
    int pos = gw / NHEADS, head = gw % NHEADS;
    const float* row = x + (size_t)pos * DMODEL + head * HDIM;

    float2 v = ((const float2*)row)[lane];
    float sum = v.x + v.y;
#pragma unroll
    for (int o = 16; o; o >>= 1) sum += __shfl_xor_sync(0xffffffffu, sum, o);
    float mu = sum * (1.f / 64.f);
    float dx = v.x - mu, dy = v.y - mu;
    float vs = dx * dx + dy * dy;
#pragma unroll
    for (int o = 16; o; o >>= 1) vs += __shfl_xor_sync(0xffffffffu, vs, o);
    float inv = rsqrtf(vs * (1.f / 64.f) + 1e-5f);

    float y0 = dx * inv * gamma[lane * 2]     + beta[lane * 2];
    float y1 = dy * inv * gamma[lane * 2 + 1] + beta[lane * 2 + 1];

    if (pos >= TLEN) {
        int r = pos - TLEN;
        float c0 = cosb[r * HDIM + lane * 2], c1 = cosb[r * HDIM + lane * 2 + 1];
        float s0 = sinb[r * HDIM + lane * 2], s1 = sinb[r * HDIM + lane * 2 + 1];
        float t0 = y0 * c0 - y1 * s0;
        float t1 = y1 * c1 + y0 * s1;
        y0 = t0; y1 = t1;
    }
    y0 *= qscale; y1 *= qscale;

    size_t base = ((size_t)head * S_TOT + pos) * HDIM;
    uint32_t hi, lo;
    split2h(y0, y1, hi, lo);
    *reinterpret_cast<uint32_t*>(hi_out + base + lane * 2) = hi;
    if (lo_out)
        *reinterpret_cast<uint32_t*>(lo_out + base + lane * 2) = lo;
}

// ============================================================================
// V transpose: g_v -> fp16 Vt plane [head][d][pos]
// ============================================================================
__global__ void vt_split()
{
    __shared__ float tile[64][65];
    int head = blockIdx.y, p0 = blockIdx.x * 64;
    int tid = threadIdx.x;
#pragma unroll
    for (int i = 0; i < 16; i++) {
        int idx = tid + i * 256;
        int p = idx >> 6, d = idx & 63;
        tile[p][d] = g_v[(size_t)(p0 + p) * DMODEL + head * HDIM + d];
    }
    __syncthreads();
#pragma unroll
    for (int i = 0; i < 16; i++) {
        int idx = tid + i * 256;
        int d = idx >> 6, p = idx & 63;
        size_t o = ((size_t)head * HDIM + d) * S_TOT + p0 + p;
        g_vthi[o] = __float2half_rn(tile[p][d]);
    }
}

// ============================================================================
// HMMA flash attention: scores fp16 2-term, PV fp16 1-term, KT=64, 2 CTAs/SM.
// Epilogue writes fp16 hi/lo split of O directly into g_ab.
// ============================================================================
#define ASQH 0
#define ASQL 18432
#define ASK  36864
#define ASV  55296
#define ATT_SMEM 73728
#define N_KCH (S_TOT / 64)   // 32

__global__ void __launch_bounds__(256, 2) attn_hmma()
{
    extern __shared__ char smc[];
    const int head = blockIdx.y;
    const int q0 = blockIdx.x * 128;
    const int tid = threadIdx.x;
    const int lane = tid & 31;
    const int wid = tid >> 5;
    const uint32_t smb = s2u(smc);

    {
        const __half* Qh = g_qhi + ((size_t)head * S_TOT + q0) * HDIM;
        const __half* Ql = g_qlo + ((size_t)head * S_TOT + q0) * HDIM;
#pragma unroll
        for (int i = 0; i < 4; i++) {
            int idx = tid + i * 256;
            int row = idx >> 3, ch = idx & 7;
            cpa16(smb + ASQH + row * 144 + ch * 16, Qh + row * HDIM + ch * 8);
            cpa16(smb + ASQL + row * 144 + ch * 16, Ql + row * HDIM + ch * 8);
        }
        cpa_commit();
    }

    auto load_kv = [&](int c) {
        int buf = c & 1;
        const __half* Kh = g_khi + ((size_t)head * S_TOT + c * 64) * HDIM;
        uint32_t kb = smb + ASK + buf * 9216;
#pragma unroll
        for (int i = 0; i < 2; i++) {
            int idx = tid + i * 256;
            int row = idx >> 3, ch = idx & 7;
            cpa16(kb + row * 144 + ch * 16, Kh + row * HDIM + ch * 8);
        }
        const __half* Vh = g_vthi + (size_t)head * HDIM * S_TOT + c * 64;
        uint32_t vb = smb + ASV + buf * 9216;
#pragma unroll
        for (int i = 0; i < 2; i++) {
            int idx = tid + i * 256;
            int d = idx >> 3, ch = idx & 7;
            cpa16(vb + d * 144 + ch * 16, Vh + (size_t)d * S_TOT + ch * 8);
        }
        cpa_commit();
    };

    load_kv(0);

    uint32_t aQh[4][4], aQl[4][4];
    float O[8][4];
#pragma unroll
    for (int j = 0; j < 8; j++)
#pragma unroll
        for (int e = 0; e < 4; e++) O[j][e] = 0.f;
    float m0 = -1e30f, m1 = -1e30f, l0 = 0.f, l1 = 0.f;

    for (int c = 0; c < N_KCH; c++) {
        if (c + 1 < N_KCH) {
            load_kv(c + 1);
            asm volatile("cp.async.wait_group 1;" ::: "memory");
        } else {
            asm volatile("cp.async.wait_group 0;" ::: "memory");
        }
        __syncthreads();

        if (c == 0) {
            uint32_t qa = smb + (uint32_t)((wid * 16 + (lane & 15)) * 144)
                          + ((lane >> 4) << 4);
#pragma unroll
            for (int kc = 0; kc < 4; kc++) {
                ldsm4(aQh[kc], qa + ASQH + kc * 32);
                ldsm4(aQl[kc], qa + ASQL + kc * 32);
            }
        }

        int buf = c & 1;
        float s[8][4];
#pragma unroll
        for (int j = 0; j < 8; j++)
#pragma unroll
            for (int e = 0; e < 4; e++) s[j][e] = 0.f;

        uint32_t kb = smb + ASK + buf * 9216 + (uint32_t)((lane & 7) * 144)
                      + (((lane >> 3) & 1) << 4);
#pragma unroll
        for (int kc = 0; kc < 4; kc++) {
#pragma unroll
            for (int j = 0; j < 8; j++) {
                uint32_t bh[2];
                ldsm2(bh, kb + j * (8 * 144) + kc * 32);
                mma_f16(s[j], aQh[kc], bh);
                mma_f16(s[j], aQl[kc], bh);
            }
        }

        float mx0 = -1e30f, mx1 = -1e30f;
#pragma unroll
        for (int j = 0; j < 8; j++) {
            mx0 = fmaxf(mx0, fmaxf(s[j][0], s[j][1]));
            mx1 = fmaxf(mx1, fmaxf(s[j][2], s[j][3]));
        }
        mx0 = fmaxf(mx0, __shfl_xor_sync(0xffffffffu, mx0, 1));
        mx0 = fmaxf(mx0, __shfl_xor_sync(0xffffffffu, mx0, 2));
        mx1 = fmaxf(mx1, __shfl_xor_sync(0xffffffffu, mx1, 1));
        mx1 = fmaxf(mx1, __shfl_xor_sync(0xffffffffu, mx1, 2));
        float mn0 = fmaxf(m0, mx0), mn1 = fmaxf(m1, mx1);
        float cr0 = __expf(m0 - mn0), cr1 = __expf(m1 - mn1);
        m0 = mn0; m1 = mn1;

        float rs0 = 0.f, rs1 = 0.f;
#pragma unroll
        for (int j = 0; j < 8; j++) {
            s[j][0] = __expf(s[j][0] - mn0);
            s[j][1] = __expf(s[j][1] - mn0);
            s[j][2] = __expf(s[j][2] - mn1);
            s[j][3] = __expf(s[j][3] - mn1);
            rs0 += s[j][0] + s[j][1];
            rs1 += s[j][2] + s[j][3];
        }
        rs0 += __shfl_xor_sync(0xffffffffu, rs0, 1);
        rs0 += __shfl_xor_sync(0xffffffffu, rs0, 2);
        rs1 += __shfl_xor_sync(0xffffffffu, rs1, 1);
        rs1 += __shfl_xor_sync(0xffffffffu, rs1, 2);
        l0 = l0 * cr0 + rs0;
        l1 = l1 * cr1 + rs1;

#pragma unroll
        for (int j = 0; j < 8; j++) {
            O[j][0] *= cr0; O[j][1] *= cr0;
            O[j][2] *= cr1; O[j][3] *= cr1;
        }

        // PV: fp16 1-term (P hi only)
        uint32_t vb = smb + ASV + buf * 9216 + (uint32_t)((lane & 7) * 144)
                      + (((lane >> 3) & 1) << 4);
#pragma unroll
        for (int ck = 0; ck < 4; ck++) {
            uint32_t ah[4];
            ah[0] = pack2h(s[2 * ck][0],     s[2 * ck][1]);
            ah[1] = pack2h(s[2 * ck][2],     s[2 * ck][3]);
            ah[2] = pack2h(s[2 * ck + 1][0], s[2 * ck + 1][1]);
            ah[3] = pack2h(s[2 * ck + 1][2], s[2 * ck + 1][3]);
#pragma unroll
            for (int jd = 0; jd < 8; jd++) {
                uint32_t bh[2];
                ldsm2(bh, vb + jd * (8 * 144) + ck * 32);
                mma_f16(O[jd], ah, bh);
            }
        }
        __syncthreads();
    }

    // ---- epilogue: write fp16 hi/lo split of O directly into g_ab ----
    float i0 = 1.f / l0, i1 = 1.f / l1;
    int r = q0 + wid * 16 + (lane >> 2);
    int cb = head * HDIM + (lane & 3) * 2;
    __half* row0 = g_ab + (size_t)r * K2;
    __half* row1 = g_ab + (size_t)(r + 8) * K2;
#pragma unroll
    for (int jd = 0; jd < 8; jd++) {
        int col = cb + jd * 8;
        uint32_t hi, lo;
        split2h(O[jd][0] * i0, O[jd][1] * i0, hi, lo);
        *reinterpret_cast<uint32_t*>(row0 + col) = hi;
        *reinterpret_cast<uint32_t*>(row0 + DMODEL + col) = lo;
        split2h(O[jd][2] * i1, O[jd][3] * i1, hi, lo);
        *reinterpret_cast<uint32_t*>(row1 + col) = hi;
        *reinterpret_cast<uint32_t*>(row1 + DMODEL + col) = lo;
    }
}

// ============================================================================
extern "C" void kernel_launch(void* const* d_in, const int* in_sizes, int n_in,
                              void* d_out, int out_size)
{
    const float* hid = (const float*)d_in[0];
    const float* enc = (const float*)d_in[1];
    const float* rc  = (const float*)d_in[2];
    const float* rs  = (const float*)d_in[3];
    const float* Wq  = (const float*)d_in[4];  const float* bq = (const float*)d_in[5];
    const float* Wk  = (const float*)d_in[6];  const float* bk = (const float*)d_in[7];
    const float* Wv  = (const float*)d_in[8];  const float* bv = (const float*)d_in[9];
    const float* Wo  = (const float*)d_in[10]; const float* bo = (const float*)d_in[11];
    const float* lqd = (const float*)d_in[12]; const float* lqu = (const float*)d_in[13];
    const float* lkd = (const float*)d_in[14]; const float* lku = (const float*)d_in[15];
    const float* lvd = (const float*)d_in[16]; const float* lvu = (const float*)d_in[17];
    const float* lpd = (const float*)d_in[18]; const float* lpu = (const float*)d_in[19];
    const float* gq  = (const float*)d_in[20]; const float* btq = (const float*)d_in[21];
    const float* gk  = (const float*)d_in[22]; const float* btk = (const float*)d_in[23];

    static int attr_done = 0;
    if (!attr_done) {
        cudaFuncSetAttribute(attn_hmma, cudaFuncAttributeMaxDynamicSharedMemorySize,
                             ATT_SMEM);
        cudaFuncSetAttribute(gemm_hmma, cudaFuncAttributeMaxDynamicSharedMemorySize,
                             GEMM_SMEM);
        cudaFuncSetAttribute(gemm_qkv, cudaFuncAttributeMaxDynamicSharedMemorySize,
                             GEMM_SMEM);
        attr_done = 1;
    }

    float *pq, *pk, *pv, *pt;
    __half *pab, *ptb, *pldb, *pwbase;
    __half *pqh, *pql, *pkh;
    cudaGetSymbolAddress((void**)&pq, g_q);
    cudaGetSymbolAddress((void**)&pk, g_k);
    cudaGetSymbolAddress((void**)&pv, g_v);
    cudaGetSymbolAddress((void**)&pt, g_t);
    cudaGetSymbolAddress((void**)&pab, g_ab);
    cudaGetSymbolAddress((void**)&ptb, g_tb);
    cudaGetSymbolAddress((void**)&pldb, g_ldb);
    cudaGetSymbolAddress((void**)&pwbase, g_wb);
    cudaGetSymbolAddress((void**)&pqh, g_qhi);
    cudaGetSymbolAddress((void**)&pql, g_qlo);
    cudaGetSymbolAddress((void**)&pkh, g_khi);

    const int nHD = S_TOT * DMODEL;
    const int nW  = DMODEL * DMODEL;
    const int nLD = RANK_ * DMODEL;
    const int nLU = DMODEL * RANK_;

    dim3 qkv_grid(72, S_TOT / 128, 1);
    dim3 oproj_grid(DMODEL / 128, S_TOT / 128, 2);
    dim3 lora3_grid(3, S_TOT / 128, 8);
    dim3 lora1_grid(1, S_TOT / 128, 8);
    const int LORA_CH = HI_CHUNKS / 8;   // 6: 1-term (hi plane only, K=3072)

    // ---- A operand + batched weight splits ----
    split_concat_kernel<<<(nHD + 255) / 256, 256>>>(hid, enc);
    split3_kernel<<<(3 * nW + 255) / 256, 256>>>(Wq, Wk, Wv, pwbase,
                                                 (size_t)DMODEL * LDB_BIG,
                                                 DMODEL, LDB_BIG, 0, nW);
    split3_kernel<<<(3 * nLU + 255) / 256, 256>>>(lqu, lku, lvu, pwbase,
                                                  (size_t)DMODEL * LDB_BIG,
                                                  RANK_, LDB_BIG, K2, nLU);
    split3_kernel<<<(3 * nLD + 255) / 256, 256>>>(lqd, lkd, lvd, pldb,
                                                  (size_t)RANK_ * K2,
                                                  DMODEL, K2, 0, nLD);

    // ---- batched lora-down (1-term fp16: K=3072 hi planes) ----
    cudaMemsetAsync(pt, 0, S_TOT * 3 * RANK_ * sizeof(float));
    gemm_hmma<<<lora3_grid, 128, GEMM_SMEM>>>(pab, K2, BIG_CHUNKS /*no tail*/, nullptr, 0, 0,
                                              pldb, K2, nullptr, pt, 3 * RANK_,
                                              LORA_CH, 1, 0);
    tsplit_kernel<<<(S_TOT * 3 * RANK_ + 255) / 256, 256>>>(3);

    // ---- merged q/k/v projection GEMM ----
    gemm_qkv<<<qkv_grid, 128, GEMM_SMEM>>>(pab, ptb, pwbase, bq, bk, bv, pq, pk, pv);

    // ---- LN + RoPE -> fp16 planes ----
    int ln_blocks = (S_TOT * NHEADS * 32 + 255) / 256;
    ln_rope_split<<<ln_blocks, 256>>>(pq, gq, btq, rc, rs, pqh, pql, 0.125f);
    ln_rope_split<<<ln_blocks, 256>>>(pk, gk, btk, rc, rs, pkh, nullptr, 1.0f);
    vt_split<<<dim3(S_TOT / 64, NHEADS), 256>>>();

    // ---- attention (writes fp16 split of O into g_ab) ----
    attn_hmma<<<dim3(S_TOT / 128, NHEADS), 256, ATT_SMEM>>>();

    // ---- output projection ----
    split_kernel_h<<<(nW + 255) / 256, 256>>>(Wo, pwbase, DMODEL, LDB_BIG, 0, 0, nW);
    split_kernel_h<<<(nLU + 255) / 256, 256>>>(lpu, pwbase, RANK_, LDB_BIG, K2, 0, nLU);
    split_kernel_h<<<(nLD + 255) / 256, 256>>>(lpd, pldb, DMODEL, K2, 0, 0, nLD);
    cudaMemsetAsync(pt, 0, S_TOT * RANK_ * sizeof(float));
    gemm_hmma<<<lora1_grid, 128, GEMM_SMEM>>>(pab, K2, BIG_CHUNKS /*no tail*/, nullptr, 0, 0,
                                              pldb, K2, nullptr, pt, RANK_,
                                              LORA_CH, 1, 0);
    tsplit_kernel<<<(S_TOT * RANK_ + 255) / 256, 256>>>(1);
    cudaMemsetAsync(d_out, 0, (size_t)out_size * sizeof(float));
    gemm_hmma<<<oproj_grid, 128, GEMM_SMEM>>>(pab, K2, H_CHUNKS, ptb, 768, 0,
                                              pwbase, LDB_BIG, bo, (float*)d_out, DMODEL,
                                              BIG_CHUNKS / 2, 1, 1);
}

// round 13
// speedup vs baseline: 1.3301x; 1.0644x over previous
#include <cuda_runtime.h>
#include <cuda_bf16.h>
#include <cuda_fp16.h>
#include <cstdint>

#define S_TOT 2048
#define DMODEL 3072
#define NHEADS 48
#define HDIM 64
#define RANK_ 128
#define TLEN 226
#define VLEN 1822

#define K2 (2 * DMODEL)       // 6144: g_ab row stride ([hi|lo])
#define LDB2 (DMODEL + RANK_) // 3200: weight row stride ([W hi | lu hi])
#define MAIN_CH (DMODEL / 64) // 48 physical K chunks (hi plane)
#define ALL_CH (MAIN_CH + 2)  // 50: + lora tail (128 cols)

// ---------------- fp32 scratch ----------------------------------------------
__device__ __align__(256) float g_q[S_TOT * DMODEL];
__device__ __align__(256) float g_k[S_TOT * DMODEL];
__device__ __align__(256) float g_v[S_TOT * DMODEL];
__device__ __align__(256) float g_t[S_TOT * 3 * RANK_];

// ---------------- fp16 operand buffers ---------------------------------------
__device__ __align__(256) __half g_ab[(size_t)S_TOT * K2];        // A: [hi(3072)|lo(3072)]
__device__ __align__(256) __half g_tb[(size_t)S_TOT * 768];       // A tail: per-proj [hi128|lo128]
__device__ __align__(256) __half g_wb[3][(size_t)DMODEL * LDB2];  // B: [W hi | lu hi]
__device__ __align__(256) __half g_ldb[(size_t)(3 * RANK_) * DMODEL]; // lora-down hi

// ---------------- attention fp16 planes (head-major) ------------------------
__device__ __align__(256) __half g_qhi[(size_t)NHEADS * S_TOT * HDIM];
__device__ __align__(256) __half g_qlo[(size_t)NHEADS * S_TOT * HDIM];
__device__ __align__(256) __half g_khi[(size_t)NHEADS * S_TOT * HDIM];
__device__ __align__(256) __half g_vthi[(size_t)NHEADS * HDIM * S_TOT];

// ============================================================================
// helpers
// ============================================================================
__device__ __forceinline__ uint32_t s2u(const void* p) {
    return (uint32_t)__cvta_generic_to_shared(p);
}
__device__ __forceinline__ void cpa16(uint32_t s, const void* g) {
    asm volatile("cp.async.cg.shared.global [%0], [%1], 16;" :: "r"(s), "l"(g));
}
__device__ __forceinline__ void cpa_commit() {
    asm volatile("cp.async.commit_group;" ::: "memory");
}
__device__ __forceinline__ void ldsm4(uint32_t* r, uint32_t a) {
    asm volatile("ldmatrix.sync.aligned.m8n8.x4.shared.b16 {%0,%1,%2,%3}, [%4];"
                 : "=r"(r[0]), "=r"(r[1]), "=r"(r[2]), "=r"(r[3]) : "r"(a));
}
__device__ __forceinline__ void ldsm2(uint32_t* r, uint32_t a) {
    asm volatile("ldmatrix.sync.aligned.m8n8.x2.shared.b16 {%0,%1}, [%2];"
                 : "=r"(r[0]), "=r"(r[1]) : "r"(a));
}
__device__ __forceinline__ void mma_f16(float* c, const uint32_t* a, const uint32_t* b) {
    asm volatile(
        "mma.sync.aligned.m16n8k16.row.col.f32.f16.f16.f32 "
        "{%0,%1,%2,%3}, {%4,%5,%6,%7}, {%8,%9}, {%0,%1,%2,%3};"
        : "+f"(c[0]), "+f"(c[1]), "+f"(c[2]), "+f"(c[3])
        : "r"(a[0]), "r"(a[1]), "r"(a[2]), "r"(a[3]), "r"(b[0]), "r"(b[1]));
}
__device__ __forceinline__ void split2h(float x, float y, uint32_t& hi, uint32_t& lo) {
    __half2 h = __floats2half2_rn(x, y);
    float hx = __half2float(__low2half(h)), hy = __half2float(__high2half(h));
    __half2 l = __floats2half2_rn(x - hx, y - hy);
    hi = *reinterpret_cast<uint32_t*>(&h);
    lo = *reinterpret_cast<uint32_t*>(&l);
}
__device__ __forceinline__ uint32_t pack2h(float x, float y) {
    __half2 h = __floats2half2_rn(x, y);
    return *reinterpret_cast<uint32_t*>(&h);
}

// ============================================================================
// split kernels (B side: hi plane only)
// ============================================================================
__global__ void splitb1_kernel(const float* __restrict__ src,
                               __half* __restrict__ dst,
                               int K, int dstStride, int dstOff, int n)
{
    int i = blockIdx.x * 256 + threadIdx.x;
    if (i >= n) return;
    int r = i / K, k = i % K;
    dst[(size_t)r * dstStride + dstOff + k] = __float2half_rn(src[i]);
}

__global__ void splitb3_kernel(const float* __restrict__ s0,
                               const float* __restrict__ s1,
                               const float* __restrict__ s2,
                               __half* __restrict__ dst, size_t dstProjStride,
                               int K, int dstStride, int dstOff, int n)
{
    int i = blockIdx.x * 256 + threadIdx.x;
    if (i >= 3 * n) return;
    int p = i / n, j = i % n;
    const float* src = (p == 0) ? s0 : (p == 1) ? s1 : s2;
    int r = j / K, k = j % K;
    dst[p * dstProjStride + (size_t)r * dstStride + dstOff + k] = __float2half_rn(src[j]);
}

__global__ void split_concat_kernel(const float* __restrict__ hid,
                                    const float* __restrict__ enc)
{
    int i = blockIdx.x * 256 + threadIdx.x;
    if (i >= S_TOT * DMODEL) return;
    int r = i / DMODEL, k = i % DMODEL;
    float x = (r < TLEN) ? enc[i] : hid[i - TLEN * DMODEL];
    __half hi = __float2half_rn(x);
    __half lo = __float2half_rn(x - __half2float(hi));
    __half* d = g_ab + (size_t)r * K2;
    d[k] = hi;
    d[DMODEL + k] = lo;
}

__global__ void tsplit_kernel(int nproj)
{
    int n = S_TOT * nproj * RANK_;
    int i = blockIdx.x * 256 + threadIdx.x;
    if (i >= n) return;
    int kw = nproj * RANK_;
    int r = i / kw, k = i % kw;
    int p = k >> 7, kk = k & 127;
    float x = g_t[(size_t)r * kw + k];
    __half hi = __float2half_rn(x);
    __half lo = __float2half_rn(x - __half2float(hi));
    __half* d = g_tb + (size_t)r * 768 + p * 256;
    d[kk] = hi;
    d[128 + kk] = lo;
}

// ============================================================================
// GEMM core: BK=64 physical, B tile resident, A hi(+lo) passes.
// smem/stage: [Ahi 18432][Alo 18432][B 18432]; 2 stages = 110592 B.
// ============================================================================
#define TILE_B 18432
#define STAGE_B (3 * TILE_B)
#define GEMM_SMEM (2 * STAGE_B)   // 110592

struct GemmCore {
    float acc[4][8][4];
    uint32_t smb;
    int lane, wm0, wn0, lrow, lch;

    __device__ __forceinline__ void init(void* sm) {
        smb = s2u(sm);
        int tid = threadIdx.x;
        lane = tid & 31;
        int wid = tid >> 5;
        wm0 = (wid & 1) * 64; wn0 = (wid >> 1) * 64;
        lrow = tid >> 3; lch = tid & 7;
#pragma unroll
        for (int i = 0; i < 4; i++)
#pragma unroll
            for (int j = 0; j < 8; j++)
#pragma unroll
                for (int e = 0; e < 4; e++) acc[i][j][e] = 0.f;
    }

    // gaHi/gaLo/gb: row-base pointers pre-offset by lch*8; strides alda/ldb.
    __device__ __forceinline__ void load_tile(int buf,
                                              const __half* gaHi, const __half* gaLo,
                                              int alda, const __half* gb, int ldb,
                                              int two) {
        uint32_t base = smb + buf * STAGE_B + lrow * 144 + lch * 16;
#pragma unroll
        for (int i = 0; i < 8; i++) {
            int row = lrow + i * 16;
            cpa16(base + i * (16 * 144), gaHi + (size_t)row * alda);
            cpa16(base + TILE_B * 2 + i * (16 * 144), gb + (size_t)row * ldb);
        }
        if (two) {
#pragma unroll
            for (int i = 0; i < 8; i++) {
                int row = lrow + i * 16;
                cpa16(base + TILE_B + i * (16 * 144), gaLo + (size_t)row * alda);
            }
        }
        cpa_commit();
    }

    __device__ __forceinline__ void compute(int buf, int two) {
        uint32_t sawh = smb + buf * STAGE_B
                        + (uint32_t)((wm0 + (lane & 15)) * 144) + ((lane >> 4) << 4);
        uint32_t sbw = smb + buf * STAGE_B + 2 * TILE_B
                       + (uint32_t)((wn0 + (lane & 7)) * 144) + (((lane >> 3) & 1) << 4);
#pragma unroll
        for (int s = 0; s < 4; s++) {
            uint32_t ah[4][4], al[4][4], bf[8][2];
#pragma unroll
            for (int i = 0; i < 4; i++) ldsm4(ah[i], sawh + i * (16 * 144) + s * 32);
            if (two) {
#pragma unroll
                for (int i = 0; i < 4; i++)
                    ldsm4(al[i], sawh + TILE_B + i * (16 * 144) + s * 32);
            }
#pragma unroll
            for (int j = 0; j < 8; j++) ldsm2(bf[j], sbw + j * (8 * 144) + s * 32);
#pragma unroll
            for (int i = 0; i < 4; i++)
#pragma unroll
                for (int j = 0; j < 8; j++)
                    mma_f16(acc[i][j], ah[i], bf[j]);
            if (two) {
#pragma unroll
                for (int i = 0; i < 4; i++)
#pragma unroll
                    for (int j = 0; j < 8; j++)
                        mma_f16(acc[i][j], al[i], bf[j]);
            }
        }
    }

    __device__ __forceinline__ void store(int r0, int c0, const float* bias,
                                          float* C, int ldc, int use_atomic, int permute) {
#pragma unroll
        for (int i = 0; i < 4; i++) {
#pragma unroll
            for (int j = 0; j < 8; j++) {
                int mm = r0 + wm0 + i * 16 + (lane >> 2);
                int nn = c0 + wn0 + j * 8 + (lane & 3) * 2;
                int row0 = mm, row1 = mm + 8;
                if (permute) {
                    row0 = (row0 < TLEN) ? row0 + VLEN : row0 - TLEN;
                    row1 = (row1 < TLEN) ? row1 + VLEN : row1 - TLEN;
                }
                float* p0 = C + (size_t)row0 * ldc + nn;
                float* p1 = C + (size_t)row1 * ldc + nn;
                float b0v = bias ? bias[nn] : 0.f;
                float b1v = bias ? bias[nn + 1] : 0.f;
                if (use_atomic) {
                    atomicAdd(p0,     acc[i][j][0] + b0v);
                    atomicAdd(p0 + 1, acc[i][j][1] + b1v);
                    atomicAdd(p1,     acc[i][j][2] + b0v);
                    atomicAdd(p1 + 1, acc[i][j][3] + b1v);
                } else {
                    p0[0] = acc[i][j][0] + b0v;
                    p0[1] = acc[i][j][1] + b1v;
                    p1[0] = acc[i][j][2] + b0v;
                    p1[1] = acc[i][j][3] + b1v;
                }
            }
        }
    }
};

// generic GEMM: A = g_ab-style [hi|lo] (+ optional tail At), B = hi-plane.
// chunk gc: gc < MAIN_CH -> main cols gc*64 (B), A cols gc*64 / 3072+gc*64;
//           gc >= MAIN_CH -> tail ct=gc-48: B col 3072+ct*64, A from At.
__global__ void __launch_bounds__(128, 2) gemm_hmma(
    const __half* __restrict__ Ah,
    const __half* __restrict__ At, int toff,
    const __half* __restrict__ B, int ldb2,
    const float* __restrict__ bias, float* __restrict__ C, int ldc,
    int chunks, int two_term, int use_atomic, int permute)
{
    extern __shared__ __half sm[];
    GemmCore g;
    g.init(sm);
    const int r0 = blockIdx.y << 7;
    const int c0 = blockIdx.x << 7;
    const int gcb = blockIdx.z * chunks;

    auto ldTile = [&](int buf, int gc) {
        const __half *ahi, *alo;
        int alda;
        if (gc < MAIN_CH) {
            ahi = Ah + (size_t)r0 * K2 + gc * 64 + g.lch * 8;
            alo = Ah + (size_t)r0 * K2 + DMODEL + gc * 64 + g.lch * 8;
            alda = K2;
        } else {
            int ct = gc - MAIN_CH;
            ahi = At + (size_t)r0 * 768 + toff + ct * 64 + g.lch * 8;
            alo = At + (size_t)r0 * 768 + toff + 128 + ct * 64 + g.lch * 8;
            alda = 768;
        }
        int bcol = (gc < MAIN_CH) ? gc * 64 : DMODEL + (gc - MAIN_CH) * 64;
        const __half* gb = B + (size_t)c0 * ldb2 + bcol + g.lch * 8;
        g.load_tile(buf, ahi, alo, alda, gb, ldb2, two_term);
    };

    ldTile(0, gcb);
    for (int c = 0; c < chunks; c++) {
        if (c + 1 < chunks) {
            ldTile((c + 1) & 1, gcb + c + 1);
            asm volatile("cp.async.wait_group 1;" ::: "memory");
        } else {
            asm volatile("cp.async.wait_group 0;" ::: "memory");
        }
        __syncthreads();
        g.compute(c & 1, two_term);
        __syncthreads();
    }
    const float* biasz = (blockIdx.z == 0) ? bias : nullptr;
    g.store(r0, c0, biasz, C, ldc, use_atomic, permute);
}

// merged q/k/v projection GEMM: grid (72, 16); proj = blockIdx.x / 24
__global__ void __launch_bounds__(128, 2) gemm_qkv(
    const __half* __restrict__ Ah, const __half* __restrict__ At,
    const __half* __restrict__ Wbase,
    const float* __restrict__ b0, const float* __restrict__ b1, const float* __restrict__ b2,
    float* __restrict__ C0, float* __restrict__ C1, float* __restrict__ C2)
{
    extern __shared__ __half sm[];
    GemmCore g;
    g.init(sm);
    const int proj = blockIdx.x / 24;
    const int c0 = (blockIdx.x % 24) << 7;
    const int r0 = blockIdx.y << 7;
    const __half* B = Wbase + (size_t)proj * DMODEL * LDB2;
    const float* bias = (proj == 0) ? b0 : (proj == 1) ? b1 : b2;
    float* C = (proj == 0) ? C0 : (proj == 1) ? C1 : C2;
    const int toff = proj * 256;

    auto ldTile = [&](int buf, int gc) {
        const __half *ahi, *alo;
        int alda;
        if (gc < MAIN_CH) {
            ahi = Ah + (size_t)r0 * K2 + gc * 64 + g.lch * 8;
            alo = Ah + (size_t)r0 * K2 + DMODEL + gc * 64 + g.lch * 8;
            alda = K2;
        } else {
            int ct = gc - MAIN_CH;
            ahi = At + (size_t)r0 * 768 + toff + ct * 64 + g.lch * 8;
            alo = At + (size_t)r0 * 768 + toff + 128 + ct * 64 + g.lch * 8;
            alda = 768;
        }
        int bcol = (gc < MAIN_CH) ? gc * 64 : DMODEL + (gc - MAIN_CH) * 64;
        const __half* gb = B + (size_t)c0 * LDB2 + bcol + g.lch * 8;
        g.load_tile(buf, ahi, alo, alda, gb, LDB2, 1);
    };

    ldTile(0, 0);
    for (int c = 0; c < ALL_CH; c++) {
        if (c + 1 < ALL_CH) {
            ldTile((c + 1) & 1, c + 1);
            asm volatile("cp.async.wait_group 1;" ::: "memory");
        } else {
            asm volatile("cp.async.wait_group 0;" ::: "memory");
        }
        __syncthreads();
        g.compute(c & 1, 1);
        __syncthreads();
    }
    g.store(r0, c0, bias, C, DMODEL, 0, 0);
}

// ============================================================================
// LN(64) + RoPE -> fp16 hi/lo planes (lo optional), head-major
// ============================================================================
__global__ void ln_rope_split(const float* __restrict__ x,
                              const float* __restrict__ gamma,
                              const float* __restrict__ beta,
                              const float* __restrict__ cosb,
                              const float* __restrict__ sinb,
                              __half* __restrict__ hi_out,
                              __half* __restrict__ lo_out,
                              float qscale)
{
    int gw = (blockIdx.x * blockDim.x + threadIdx.x) >> 5;
    int lane = threadIdx.x & 31;
    if (gw >= S_TOT * NHEADS) return;
    int pos = gw / NHEADS, head = gw % NHEADS;
    const float* row = x + (size_t)pos * DMODEL + head * HDIM;

    float2 v = ((const float2*)row)[lane];
    float sum = v.x + v.y;
#pragma unroll
    for (int o = 16; o; o >>= 1) sum += __shfl_xor_sync(0xffffffffu, sum, o);
    float mu = sum * (1.f / 64.f);
    float dx = v.x - mu, dy = v.y - mu;
    float vs = dx * dx + dy * dy;
#pragma unroll
    for (int o = 16; o; o >>= 1) vs += __shfl_xor_sync(0xffffffffu, vs, o);
    float inv = rsqrtf(vs * (1.f / 64.f) + 1e-5f);

    float y0 = dx * inv * gamma[lane * 2]     + beta[lane * 2];
    float y1 = dy * inv * gamma[lane * 2 + 1] + beta[lane * 2 + 1];

    if (pos >= TLEN) {
        int r = pos - TLEN;
        float c0 = cosb[r * HDIM + lane * 2], c1 = cosb[r * HDIM + lane * 2 + 1];
        float s0 = sinb[r * HDIM + lane * 2], s1 = sinb[r * HDIM + lane * 2 + 1];
        float t0 = y0 * c0 - y1 * s0;
        float t1 = y1 * c1 + y0 * s1;
        y0 = t0; y1 = t1;
    }
    y0 *= qscale; y1 *= qscale;

    size_t base = ((size_t)head * S_TOT + pos) * HDIM;
    uint32_t hi, lo;
    split2h(y0, y1, hi, lo);
    *reinterpret_cast<uint32_t*>(hi_out + base + lane * 2) = hi;
    if (lo_out)
        *reinterpret_cast<uint32_t*>(lo_out + base + lane * 2) = lo;
}

// ============================================================================
// V transpose: g_v -> fp16 Vt plane [head][d][pos]
// ============================================================================
__global__ void vt_split()
{
    __shared__ float tile[64][65];
    int head = blockIdx.y, p0 = blockIdx.x * 64;
    int tid = threadIdx.x;
#pragma unroll
    for (int i = 0; i < 16; i++) {
        int idx = tid + i * 256;
        int p = idx >> 6, d = idx & 63;
        tile[p][d] = g_v[(size_t)(p0 + p) * DMODEL + head * HDIM + d];
    }
    __syncthreads();
#pragma unroll
    for (int i = 0; i < 16; i++) {
        int idx = tid + i * 256;
        int d = idx >> 6, p = idx & 63;
        size_t o = ((size_t)head * HDIM + d) * S_TOT + p0 + p;
        g_vthi[o] = __float2half_rn(tile[p][d]);
    }
}

// ============================================================================
// HMMA flash attention: scores fp16 2-term, PV fp16 1-term, KT=64, 2 CTAs/SM.
// ============================================================================
#define ASQH 0
#define ASQL 18432
#define ASK  36864
#define ASV  55296
#define ATT_SMEM 73728
#define N_KCH (S_TOT / 64)

__global__ void __launch_bounds__(256, 2) attn_hmma()
{
    extern __shared__ char smc[];
    const int head = blockIdx.y;
    const int q0 = blockIdx.x * 128;
    const int tid = threadIdx.x;
    const int lane = tid & 31;
    const int wid = tid >> 5;
    const uint32_t smb = s2u(smc);

    {
        const __half* Qh = g_qhi + ((size_t)head * S_TOT + q0) * HDIM;
        const __half* Ql = g_qlo + ((size_t)head * S_TOT + q0) * HDIM;
#pragma unroll
        for (int i = 0; i < 4; i++) {
            int idx = tid + i * 256;
            int row = idx >> 3, ch = idx & 7;
            cpa16(smb + ASQH + row * 144 + ch * 16, Qh + row * HDIM + ch * 8);
            cpa16(smb + ASQL + row * 144 + ch * 16, Ql + row * HDIM + ch * 8);
        }
        cpa_commit();
    }

    auto load_kv = [&](int c) {
        int buf = c & 1;
        const __half* Kh = g_khi + ((size_t)head * S_TOT + c * 64) * HDIM;
        uint32_t kb = smb + ASK + buf * 9216;
#pragma unroll
        for (int i = 0; i < 2; i++) {
            int idx = tid + i * 256;
            int row = idx >> 3, ch = idx & 7;
            cpa16(kb + row * 144 + ch * 16, Kh + row * HDIM + ch * 8);
        }
        const __half* Vh = g_vthi + (size_t)head * HDIM * S_TOT + c * 64;
        uint32_t vb = smb + ASV + buf * 9216;
#pragma unroll
        for (int i = 0; i < 2; i++) {
            int idx = tid + i * 256;
            int d = idx >> 3, ch = idx & 7;
            cpa16(vb + d * 144 + ch * 16, Vh + (size_t)d * S_TOT + ch * 8);
        }
        cpa_commit();
    };

    load_kv(0);

    uint32_t aQh[4][4], aQl[4][4];
    float O[8][4];
#pragma unroll
    for (int j = 0; j < 8; j++)
#pragma unroll
        for (int e = 0; e < 4; e++) O[j][e] = 0.f;
    float m0 = -1e30f, m1 = -1e30f, l0 = 0.f, l1 = 0.f;

    for (int c = 0; c < N_KCH; c++) {
        if (c + 1 < N_KCH) {
            load_kv(c + 1);
            asm volatile("cp.async.wait_group 1;" ::: "memory");
        } else {
            asm volatile("cp.async.wait_group 0;" ::: "memory");
        }
        __syncthreads();

        if (c == 0) {
            uint32_t qa = smb + (uint32_t)((wid * 16 + (lane & 15)) * 144)
                          + ((lane >> 4) << 4);
#pragma unroll
            for (int kc = 0; kc < 4; kc++) {
                ldsm4(aQh[kc], qa + ASQH + kc * 32);
                ldsm4(aQl[kc], qa + ASQL + kc * 32);
            }
        }

        int buf = c & 1;
        float s[8][4];
#pragma unroll
        for (int j = 0; j < 8; j++)
#pragma unroll
            for (int e = 0; e < 4; e++) s[j][e] = 0.f;

        uint32_t kb = smb + ASK + buf * 9216 + (uint32_t)((lane & 7) * 144)
                      + (((lane >> 3) & 1) << 4);
#pragma unroll
        for (int kc = 0; kc < 4; kc++) {
#pragma unroll
            for (int j = 0; j < 8; j++) {
                uint32_t bh[2];
                ldsm2(bh, kb + j * (8 * 144) + kc * 32);
                mma_f16(s[j], aQh[kc], bh);
                mma_f16(s[j], aQl[kc], bh);
            }
        }

        float mx0 = -1e30f, mx1 = -1e30f;
#pragma unroll
        for (int j = 0; j < 8; j++) {
            mx0 = fmaxf(mx0, fmaxf(s[j][0], s[j][1]));
            mx1 = fmaxf(mx1, fmaxf(s[j][2], s[j][3]));
        }
        mx0 = fmaxf(mx0, __shfl_xor_sync(0xffffffffu, mx0, 1));
        mx0 = fmaxf(mx0, __shfl_xor_sync(0xffffffffu, mx0, 2));
        mx1 = fmaxf(mx1, __shfl_xor_sync(0xffffffffu, mx1, 1));
        mx1 = fmaxf(mx1, __shfl_xor_sync(0xffffffffu, mx1, 2));
        float mn0 = fmaxf(m0, mx0), mn1 = fmaxf(m1, mx1);
        float cr0 = __expf(m0 - mn0), cr1 = __expf(m1 - mn1);
        m0 = mn0; m1 = mn1;

        float rs0 = 0.f, rs1 = 0.f;
#pragma unroll
        for (int j = 0; j < 8; j++) {
            s[j][0] = __expf(s[j][0] - mn0);
            s[j][1] = __expf(s[j][1] - mn0);
            s[j][2] = __expf(s[j][2] - mn1);
            s[j][3] = __expf(s[j][3] - mn1);
            rs0 += s[j][0] + s[j][1];
            rs1 += s[j][2] + s[j][3];
        }
        rs0 += __shfl_xor_sync(0xffffffffu, rs0, 1);
        rs0 += __shfl_xor_sync(0xffffffffu, rs0, 2);
        rs1 += __shfl_xor_sync(0xffffffffu, rs1, 1);
        rs1 += __shfl_xor_sync(0xffffffffu, rs1, 2);
        l0 = l0 * cr0 + rs0;
        l1 = l1 * cr1 + rs1;

#pragma unroll
        for (int j = 0; j < 8; j++) {
            O[j][0] *= cr0; O[j][1] *= cr0;
            O[j][2] *= cr1; O[j][3] *= cr1;
        }

        uint32_t vb = smb + ASV + buf * 9216 + (uint32_t)((lane & 7) * 144)
                      + (((lane >> 3) & 1) << 4);
#pragma unroll
        for (int ck = 0; ck < 4; ck++) {
            uint32_t ah[4];
            ah[0] = pack2h(s[2 * ck][0],     s[2 * ck][1]);
            ah[1] = pack2h(s[2 * ck][2],     s[2 * ck][3]);
            ah[2] = pack2h(s[2 * ck + 1][0], s[2 * ck + 1][1]);
            ah[3] = pack2h(s[2 * ck + 1][2], s[2 * ck + 1][3]);
#pragma unroll
            for (int jd = 0; jd < 8; jd++) {
                uint32_t bh[2];
                ldsm2(bh, vb + jd * (8 * 144) + ck * 32);
                mma_f16(O[jd], ah, bh);
            }
        }
        __syncthreads();
    }

    float i0 = 1.f / l0, i1 = 1.f / l1;
    int r = q0 + wid * 16 + (lane >> 2);
    int cb = head * HDIM + (lane & 3) * 2;
    __half* row0 = g_ab + (size_t)r * K2;
    __half* row1 = g_ab + (size_t)(r + 8) * K2;
#pragma unroll
    for (int jd = 0; jd < 8; jd++) {
        int col = cb + jd * 8;
        uint32_t hi, lo;
        split2h(O[jd][0] * i0, O[jd][1] * i0, hi, lo);
        *reinterpret_cast<uint32_t*>(row0 + col) = hi;
        *reinterpret_cast<uint32_t*>(row0 + DMODEL + col) = lo;
        split2h(O[jd][2] * i1, O[jd][3] * i1, hi, lo);
        *reinterpret_cast<uint32_t*>(row1 + col) = hi;
        *reinterpret_cast<uint32_t*>(row1 + DMODEL + col) = lo;
    }
}

// ============================================================================
extern "C" void kernel_launch(void* const* d_in, const int* in_sizes, int n_in,
                              void* d_out, int out_size)
{
    const float* hid = (const float*)d_in[0];
    const float* enc = (const float*)d_in[1];
    const float* rc  = (const float*)d_in[2];
    const float* rs  = (const float*)d_in[3];
    const float* Wq  = (const float*)d_in[4];  const float* bq = (const float*)d_in[5];
    const float* Wk  = (const float*)d_in[6];  const float* bk = (const float*)d_in[7];
    const float* Wv  = (const float*)d_in[8];  const float* bv = (const float*)d_in[9];
    const float* Wo  = (const float*)d_in[10]; const float* bo = (const float*)d_in[11];
    const float* lqd = (const float*)d_in[12]; const float* lqu = (const float*)d_in[13];
    const float* lkd = (const float*)d_in[14]; const float* lku = (const float*)d_in[15];
    const float* lvd = (const float*)d_in[16]; const float* lvu = (const float*)d_in[17];
    const float* lpd = (const float*)d_in[18]; const float* lpu = (const float*)d_in[19];
    const float* gq  = (const float*)d_in[20]; const float* btq = (const float*)d_in[21];
    const float* gk  = (const float*)d_in[22]; const float* btk = (const float*)d_in[23];

    static int attr_done = 0;
    if (!attr_done) {
        cudaFuncSetAttribute(attn_hmma, cudaFuncAttributeMaxDynamicSharedMemorySize,
                             ATT_SMEM);
        cudaFuncSetAttribute(gemm_hmma, cudaFuncAttributeMaxDynamicSharedMemorySize,
                             GEMM_SMEM);
        cudaFuncSetAttribute(gemm_qkv, cudaFuncAttributeMaxDynamicSharedMemorySize,
                             GEMM_SMEM);
        attr_done = 1;
    }

    float *pq, *pk, *pv, *pt;
    __half *pab, *ptb, *pldb, *pwbase;
    __half *pqh, *pql, *pkh;
    cudaGetSymbolAddress((void**)&pq, g_q);
    cudaGetSymbolAddress((void**)&pk, g_k);
    cudaGetSymbolAddress((void**)&pv, g_v);
    cudaGetSymbolAddress((void**)&pt, g_t);
    cudaGetSymbolAddress((void**)&pab, g_ab);
    cudaGetSymbolAddress((void**)&ptb, g_tb);
    cudaGetSymbolAddress((void**)&pldb, g_ldb);
    cudaGetSymbolAddress((void**)&pwbase, g_wb);
    cudaGetSymbolAddress((void**)&pqh, g_qhi);
    cudaGetSymbolAddress((void**)&pql, g_qlo);
    cudaGetSymbolAddress((void**)&pkh, g_khi);

    const int nHD = S_TOT * DMODEL;
    const int nW  = DMODEL * DMODEL;
    const int nLD = RANK_ * DMODEL;
    const int nLU = DMODEL * RANK_;

    dim3 qkv_grid(72, S_TOT / 128, 1);
    dim3 oproj_grid(DMODEL / 128, S_TOT / 128, 2);   // split-K 2: 25 chunks each
    dim3 lora3_grid(3, S_TOT / 128, 8);              // split-K 8: 6 chunks each
    dim3 lora1_grid(1, S_TOT / 128, 8);
    const int LORA_CH = MAIN_CH / 8;                 // 6

    // ---- A operand + hi-plane weight splits ----
    split_concat_kernel<<<(nHD + 255) / 256, 256>>>(hid, enc);
    splitb3_kernel<<<(3 * nW + 255) / 256, 256>>>(Wq, Wk, Wv, pwbase,
                                                  (size_t)DMODEL * LDB2,
                                                  DMODEL, LDB2, 0, nW);
    splitb3_kernel<<<(3 * nLU + 255) / 256, 256>>>(lqu, lku, lvu, pwbase,
                                                   (size_t)DMODEL * LDB2,
                                                   RANK_, LDB2, DMODEL, nLU);
    splitb3_kernel<<<(3 * nLD + 255) / 256, 256>>>(lqd, lkd, lvd, pldb,
                                                   (size_t)RANK_ * DMODEL,
                                                   DMODEL, DMODEL, 0, nLD);

    // ---- batched lora-down (1-term: A hi plane only, B=ld hi) ----
    cudaMemsetAsync(pt, 0, S_TOT * 3 * RANK_ * sizeof(float));
    gemm_hmma<<<lora3_grid, 128, GEMM_SMEM>>>(pab, nullptr, 0, pldb, DMODEL,
                                              nullptr, pt, 3 * RANK_,
                                              LORA_CH, 0, 1, 0);
    tsplit_kernel<<<(S_TOT * 3 * RANK_ + 255) / 256, 256>>>(3);

    // ---- merged q/k/v projection GEMM ----
    gemm_qkv<<<qkv_grid, 128, GEMM_SMEM>>>(pab, ptb, pwbase, bq, bk, bv, pq, pk, pv);

    // ---- LN + RoPE -> fp16 planes ----
    int ln_blocks = (S_TOT * NHEADS * 32 + 255) / 256;
    ln_rope_split<<<ln_blocks, 256>>>(pq, gq, btq, rc, rs, pqh, pql, 0.125f);
    ln_rope_split<<<ln_blocks, 256>>>(pk, gk, btk, rc, rs, pkh, nullptr, 1.0f);
    vt_split<<<dim3(S_TOT / 64, NHEADS), 256>>>();

    // ---- attention (writes fp16 split of O into g_ab) ----
    attn_hmma<<<dim3(S_TOT / 128, NHEADS), 256, ATT_SMEM>>>();

    // ---- output projection ----
    splitb1_kernel<<<(nW + 255) / 256, 256>>>(Wo, pwbase, DMODEL, LDB2, 0, nW);
    splitb1_kernel<<<(nLU + 255) / 256, 256>>>(lpu, pwbase, RANK_, LDB2, DMODEL, nLU);
    splitb1_kernel<<<(nLD + 255) / 256, 256>>>(lpd, pldb, DMODEL, DMODEL, 0, nLD);
    cudaMemsetAsync(pt, 0, S_TOT * RANK_ * sizeof(float));
    gemm_hmma<<<lora1_grid, 128, GEMM_SMEM>>>(pab, nullptr, 0, pldb, DMODEL,
                                              nullptr, pt, RANK_,
                                              LORA_CH, 0, 1, 0);
    tsplit_kernel<<<(S_TOT * RANK_ + 255) / 256, 256>>>(1);
    cudaMemsetAsync(d_out, 0, (size_t)out_size * sizeof(float));
    gemm_hmma<<<oproj_grid, 128, GEMM_SMEM>>>(pab, ptb, 0, pwbase, LDB2,
                                              bo, (float*)d_out, DMODEL,
                                              ALL_CH / 2, 1, 1, 1);
}

// round 14
// speedup vs baseline: 1.3820x; 1.0390x over previous
#include <cuda_runtime.h>
#include <cuda_bf16.h>
#include <cuda_fp16.h>
#include <cstdint>

#define S_TOT 2048
#define DMODEL 3072
#define NHEADS 48
#define HDIM 64
#define RANK_ 128
#define TLEN 226
#define VLEN 1822

#define K2 (2 * DMODEL)       // 6144: g_ab row stride ([hi|lo])
#define LDB2 (DMODEL + RANK_) // 3200: weight row stride ([W hi | lu hi])
#define MAIN_CH (DMODEL / 64) // 48
#define ALL_CH (MAIN_CH + 2)  // 50

// ---------------- fp32 scratch ----------------------------------------------
__device__ __align__(256) float g_v[S_TOT * DMODEL];
__device__ __align__(256) float g_t[S_TOT * 3 * RANK_];

// ---------------- fp16 operand buffers ---------------------------------------
__device__ __align__(256) __half g_ab[(size_t)S_TOT * K2];
__device__ __align__(256) __half g_tb[(size_t)S_TOT * 768];
__device__ __align__(256) __half g_wb[3][(size_t)DMODEL * LDB2];
__device__ __align__(256) __half g_ldb[(size_t)(3 * RANK_) * DMODEL];

// ---------------- attention fp16 planes (head-major) ------------------------
__device__ __align__(256) __half g_qhi[(size_t)NHEADS * S_TOT * HDIM];
__device__ __align__(256) __half g_qlo[(size_t)NHEADS * S_TOT * HDIM];
__device__ __align__(256) __half g_khi[(size_t)NHEADS * S_TOT * HDIM];
__device__ __align__(256) __half g_vthi[(size_t)NHEADS * HDIM * S_TOT];

// ============================================================================
// helpers
// ============================================================================
__device__ __forceinline__ uint32_t s2u(const void* p) {
    return (uint32_t)__cvta_generic_to_shared(p);
}
__device__ __forceinline__ void cpa16(uint32_t s, const void* g) {
    asm volatile("cp.async.cg.shared.global [%0], [%1], 16;" :: "r"(s), "l"(g));
}
__device__ __forceinline__ void cpa_commit() {
    asm volatile("cp.async.commit_group;" ::: "memory");
}
__device__ __forceinline__ void ldsm4(uint32_t* r, uint32_t a) {
    asm volatile("ldmatrix.sync.aligned.m8n8.x4.shared.b16 {%0,%1,%2,%3}, [%4];"
                 : "=r"(r[0]), "=r"(r[1]), "=r"(r[2]), "=r"(r[3]) : "r"(a));
}
__device__ __forceinline__ void ldsm2(uint32_t* r, uint32_t a) {
    asm volatile("ldmatrix.sync.aligned.m8n8.x2.shared.b16 {%0,%1}, [%2];"
                 : "=r"(r[0]), "=r"(r[1]) : "r"(a));
}
__device__ __forceinline__ void mma_f16(float* c, const uint32_t* a, const uint32_t* b) {
    asm volatile(
        "mma.sync.aligned.m16n8k16.row.col.f32.f16.f16.f32 "
        "{%0,%1,%2,%3}, {%4,%5,%6,%7}, {%8,%9}, {%0,%1,%2,%3};"
        : "+f"(c[0]), "+f"(c[1]), "+f"(c[2]), "+f"(c[3])
        : "r"(a[0]), "r"(a[1]), "r"(a[2]), "r"(a[3]), "r"(b[0]), "r"(b[1]));
}
__device__ __forceinline__ void split2h(float x, float y, uint32_t& hi, uint32_t& lo) {
    __half2 h = __floats2half2_rn(x, y);
    float hx = __half2float(__low2half(h)), hy = __half2float(__high2half(h));
    __half2 l = __floats2half2_rn(x - hx, y - hy);
    hi = *reinterpret_cast<uint32_t*>(&h);
    lo = *reinterpret_cast<uint32_t*>(&l);
}
__device__ __forceinline__ uint32_t pack2h(float x, float y) {
    __half2 h = __floats2half2_rn(x, y);
    return *reinterpret_cast<uint32_t*>(&h);
}

// ============================================================================
// split kernels
// ============================================================================
__global__ void splitb1_kernel(const float* __restrict__ src,
                               __half* __restrict__ dst,
                               int K, int dstStride, int dstOff, int n)
{
    int i = blockIdx.x * 256 + threadIdx.x;
    if (i >= n) return;
    int r = i / K, k = i % K;
    dst[(size_t)r * dstStride + dstOff + k] = __float2half_rn(src[i]);
}

__global__ void splitb3_kernel(const float* __restrict__ s0,
                               const float* __restrict__ s1,
                               const float* __restrict__ s2,
                               __half* __restrict__ dst, size_t dstProjStride,
                               int K, int dstStride, int dstOff, int n)
{
    int i = blockIdx.x * 256 + threadIdx.x;
    if (i >= 3 * n) return;
    int p = i / n, j = i % n;
    const float* src = (p == 0) ? s0 : (p == 1) ? s1 : s2;
    int r = j / K, k = j % K;
    dst[p * dstProjStride + (size_t)r * dstStride + dstOff + k] = __float2half_rn(src[j]);
}

__global__ void split_concat_kernel(const float* __restrict__ hid,
                                    const float* __restrict__ enc)
{
    int i = blockIdx.x * 256 + threadIdx.x;
    if (i >= S_TOT * DMODEL) return;
    int r = i / DMODEL, k = i % DMODEL;
    float x = (r < TLEN) ? enc[i] : hid[i - TLEN * DMODEL];
    __half hi = __float2half_rn(x);
    __half lo = __float2half_rn(x - __half2float(hi));
    __half* d = g_ab + (size_t)r * K2;
    d[k] = hi;
    d[DMODEL + k] = lo;
}

__global__ void tsplit_kernel(int nproj)
{
    int n = S_TOT * nproj * RANK_;
    int i = blockIdx.x * 256 + threadIdx.x;
    if (i >= n) return;
    int kw = nproj * RANK_;
    int r = i / kw, k = i % kw;
    int p = k >> 7, kk = k & 127;
    float x = g_t[(size_t)r * kw + k];
    __half hi = __float2half_rn(x);
    __half lo = __float2half_rn(x - __half2float(hi));
    __half* d = g_tb + (size_t)r * 768 + p * 256;
    d[kk] = hi;
    d[128 + kk] = lo;
}

// ============================================================================
// GEMM core: BK=64 physical, B tile resident, A hi(+lo) passes.
// ============================================================================
#define TILE_B 18432
#define STAGE_B (3 * TILE_B)
#define GEMM_SMEM (2 * STAGE_B)   // 110592

struct GemmCore {
    float acc[4][8][4];
    uint32_t smb;
    int lane, wm0, wn0, lrow, lch;

    __device__ __forceinline__ void init(void* sm) {
        smb = s2u(sm);
        int tid = threadIdx.x;
        lane = tid & 31;
        int wid = tid >> 5;
        wm0 = (wid & 1) * 64; wn0 = (wid >> 1) * 64;
        lrow = tid >> 3; lch = tid & 7;
#pragma unroll
        for (int i = 0; i < 4; i++)
#pragma unroll
            for (int j = 0; j < 8; j++)
#pragma unroll
                for (int e = 0; e < 4; e++) acc[i][j][e] = 0.f;
    }

    __device__ __forceinline__ void load_tile(int buf,
                                              const __half* gaHi, const __half* gaLo,
                                              int alda, const __half* gb, int ldb,
                                              int two) {
        uint32_t base = smb + buf * STAGE_B + lrow * 144 + lch * 16;
#pragma unroll
        for (int i = 0; i < 8; i++) {
            int row = lrow + i * 16;
            cpa16(base + i * (16 * 144), gaHi + (size_t)row * alda);
            cpa16(base + TILE_B * 2 + i * (16 * 144), gb + (size_t)row * ldb);
        }
        if (two) {
#pragma unroll
            for (int i = 0; i < 8; i++) {
                int row = lrow + i * 16;
                cpa16(base + TILE_B + i * (16 * 144), gaLo + (size_t)row * alda);
            }
        }
        cpa_commit();
    }

    __device__ __forceinline__ void compute(int buf, int two) {
        uint32_t sawh = smb + buf * STAGE_B
                        + (uint32_t)((wm0 + (lane & 15)) * 144) + ((lane >> 4) << 4);
        uint32_t sbw = smb + buf * STAGE_B + 2 * TILE_B
                       + (uint32_t)((wn0 + (lane & 7)) * 144) + (((lane >> 3) & 1) << 4);
#pragma unroll
        for (int s = 0; s < 4; s++) {
            uint32_t ah[4][4], al[4][4], bf[8][2];
#pragma unroll
            for (int i = 0; i < 4; i++) ldsm4(ah[i], sawh + i * (16 * 144) + s * 32);
            if (two) {
#pragma unroll
                for (int i = 0; i < 4; i++)
                    ldsm4(al[i], sawh + TILE_B + i * (16 * 144) + s * 32);
            }
#pragma unroll
            for (int j = 0; j < 8; j++) ldsm2(bf[j], sbw + j * (8 * 144) + s * 32);
#pragma unroll
            for (int i = 0; i < 4; i++)
#pragma unroll
                for (int j = 0; j < 8; j++)
                    mma_f16(acc[i][j], ah[i], bf[j]);
            if (two) {
#pragma unroll
                for (int i = 0; i < 4; i++)
#pragma unroll
                    for (int j = 0; j < 8; j++)
                        mma_f16(acc[i][j], al[i], bf[j]);
            }
        }
    }

    __device__ __forceinline__ void store(int r0, int c0, const float* bias,
                                          float* C, int ldc, int use_atomic, int permute) {
#pragma unroll
        for (int i = 0; i < 4; i++) {
#pragma unroll
            for (int j = 0; j < 8; j++) {
                int mm = r0 + wm0 + i * 16 + (lane >> 2);
                int nn = c0 + wn0 + j * 8 + (lane & 3) * 2;
                int row0 = mm, row1 = mm + 8;
                if (permute) {
                    row0 = (row0 < TLEN) ? row0 + VLEN : row0 - TLEN;
                    row1 = (row1 < TLEN) ? row1 + VLEN : row1 - TLEN;
                }
                float* p0 = C + (size_t)row0 * ldc + nn;
                float* p1 = C + (size_t)row1 * ldc + nn;
                float b0v = bias ? bias[nn] : 0.f;
                float b1v = bias ? bias[nn + 1] : 0.f;
                if (use_atomic) {
                    atomicAdd(p0,     acc[i][j][0] + b0v);
                    atomicAdd(p0 + 1, acc[i][j][1] + b1v);
                    atomicAdd(p1,     acc[i][j][2] + b0v);
                    atomicAdd(p1 + 1, acc[i][j][3] + b1v);
                } else {
                    p0[0] = acc[i][j][0] + b0v;
                    p0[1] = acc[i][j][1] + b1v;
                    p1[0] = acc[i][j][2] + b0v;
                    p1[1] = acc[i][j][3] + b1v;
                }
            }
        }
    }
};

// generic GEMM; chunks clamped to total_ch for uneven split-K.
__global__ void __launch_bounds__(128, 2) gemm_hmma(
    const __half* __restrict__ Ah,
    const __half* __restrict__ At, int toff,
    const __half* __restrict__ B, int ldb2,
    const float* __restrict__ bias, float* __restrict__ C, int ldc,
    int chunks, int total_ch, int two_term, int use_atomic, int permute)
{
    extern __shared__ __half sm[];
    GemmCore g;
    g.init(sm);
    const int r0 = blockIdx.y << 7;
    const int c0 = blockIdx.x << 7;
    const int gcb = blockIdx.z * chunks;
    int ch = chunks;
    if (gcb + ch > total_ch) ch = total_ch - gcb;

    auto ldTile = [&](int buf, int gc) {
        const __half *ahi, *alo;
        int alda;
        if (gc < MAIN_CH) {
            ahi = Ah + (size_t)r0 * K2 + gc * 64 + g.lch * 8;
            alo = Ah + (size_t)r0 * K2 + DMODEL + gc * 64 + g.lch * 8;
            alda = K2;
        } else {
            int ct = gc - MAIN_CH;
            ahi = At + (size_t)r0 * 768 + toff + ct * 64 + g.lch * 8;
            alo = At + (size_t)r0 * 768 + toff + 128 + ct * 64 + g.lch * 8;
            alda = 768;
        }
        int bcol = (gc < MAIN_CH) ? gc * 64 : DMODEL + (gc - MAIN_CH) * 64;
        const __half* gb = B + (size_t)c0 * ldb2 + bcol + g.lch * 8;
        g.load_tile(buf, ahi, alo, alda, gb, ldb2, two_term);
    };

    ldTile(0, gcb);
    for (int c = 0; c < ch; c++) {
        if (c + 1 < ch) {
            ldTile((c + 1) & 1, gcb + c + 1);
            asm volatile("cp.async.wait_group 1;" ::: "memory");
        } else {
            asm volatile("cp.async.wait_group 0;" ::: "memory");
        }
        __syncthreads();
        g.compute(c & 1, two_term);
        __syncthreads();
    }
    const float* biasz = (blockIdx.z == 0) ? bias : nullptr;
    g.store(r0, c0, biasz, C, ldc, use_atomic, permute);
}

// ============================================================================
// merged q/k/v projection GEMM with fused LN+RoPE+fp16-plane epilogue.
// proj 0 -> LN+RoPE -> qhi/qlo (scaled 0.125); proj 1 -> LN+RoPE -> khi;
// proj 2 -> plain fp32 store to g_v.
// ============================================================================
__global__ void __launch_bounds__(128, 2) gemm_qkv(
    const __half* __restrict__ Ah, const __half* __restrict__ At,
    const __half* __restrict__ Wbase,
    const float* __restrict__ b0, const float* __restrict__ b1, const float* __restrict__ b2,
    const float* __restrict__ gq, const float* __restrict__ btq,
    const float* __restrict__ gk, const float* __restrict__ btk,
    const float* __restrict__ rc, const float* __restrict__ rs,
    float* __restrict__ Cv)
{
    extern __shared__ __half sm[];
    GemmCore g;
    g.init(sm);
    const int proj = blockIdx.x / 24;
    const int c0 = (blockIdx.x % 24) << 7;
    const int r0 = blockIdx.y << 7;
    const __half* B = Wbase + (size_t)proj * DMODEL * LDB2;
    const int toff = proj * 256;

    auto ldTile = [&](int buf, int gc) {
        const __half *ahi, *alo;
        int alda;
        if (gc < MAIN_CH) {
            ahi = Ah + (size_t)r0 * K2 + gc * 64 + g.lch * 8;
            alo = Ah + (size_t)r0 * K2 + DMODEL + gc * 64 + g.lch * 8;
            alda = K2;
        } else {
            int ct = gc - MAIN_CH;
            ahi = At + (size_t)r0 * 768 + toff + ct * 64 + g.lch * 8;
            alo = At + (size_t)r0 * 768 + toff + 128 + ct * 64 + g.lch * 8;
            alda = 768;
        }
        int bcol = (gc < MAIN_CH) ? gc * 64 : DMODEL + (gc - MAIN_CH) * 64;
        const __half* gb = B + (size_t)c0 * LDB2 + bcol + g.lch * 8;
        g.load_tile(buf, ahi, alo, alda, gb, LDB2, 1);
    };

    ldTile(0, 0);
    for (int c = 0; c < ALL_CH; c++) {
        if (c + 1 < ALL_CH) {
            ldTile((c + 1) & 1, c + 1);
            asm volatile("cp.async.wait_group 1;" ::: "memory");
        } else {
            asm volatile("cp.async.wait_group 0;" ::: "memory");
        }
        __syncthreads();
        g.compute(c & 1, 1);
        __syncthreads();
    }

    if (proj == 2) {
        g.store(r0, c0, b2, Cv, DMODEL, 0, 0);
        return;
    }

    // ---- fused LN + RoPE + fp16 plane split (one head per warp column) ----
    const float* bias = (proj == 0) ? b0 : b1;
    const float* gamma = (proj == 0) ? gq : gk;
    const float* beta  = (proj == 0) ? btq : btk;
    const float qscale = (proj == 0) ? 0.125f : 1.0f;
    const int head = (c0 + g.wn0) >> 6;
    const int lq = g.lane & 3, rq = g.lane >> 2;

#pragma unroll
    for (int i = 0; i < 4; i++) {
#pragma unroll
        for (int half = 0; half < 2; half++) {
            int pos = r0 + g.wm0 + i * 16 + rq + half * 8;
            float v[16];
            float sum = 0.f, sq = 0.f;
#pragma unroll
            for (int j = 0; j < 8; j++) {
                int d0 = j * 8 + lq * 2;
                float x0 = g.acc[i][j][2 * half]     + bias[c0 + g.wn0 + d0];
                float x1 = g.acc[i][j][2 * half + 1] + bias[c0 + g.wn0 + d0 + 1];
                v[2 * j] = x0; v[2 * j + 1] = x1;
                sum += x0 + x1;
                sq += x0 * x0 + x1 * x1;
            }
            sum += __shfl_xor_sync(0xffffffffu, sum, 1);
            sum += __shfl_xor_sync(0xffffffffu, sum, 2);
            sq  += __shfl_xor_sync(0xffffffffu, sq, 1);
            sq  += __shfl_xor_sync(0xffffffffu, sq, 2);
            float mu = sum * (1.f / 64.f);
            float var = fmaxf(sq * (1.f / 64.f) - mu * mu, 0.f);
            float inv = rsqrtf(var + 1e-5f);

            size_t base = ((size_t)head * S_TOT + pos) * HDIM;
            int rope = (pos >= TLEN);
            int rr = pos - TLEN;
#pragma unroll
            for (int j = 0; j < 8; j++) {
                int d0 = j * 8 + lq * 2;
                float y0 = (v[2 * j]     - mu) * inv * gamma[d0]     + beta[d0];
                float y1 = (v[2 * j + 1] - mu) * inv * gamma[d0 + 1] + beta[d0 + 1];
                if (rope) {
                    float cc0 = rc[rr * HDIM + d0], cc1 = rc[rr * HDIM + d0 + 1];
                    float ss0 = rs[rr * HDIM + d0], ss1 = rs[rr * HDIM + d0 + 1];
                    float t0 = y0 * cc0 - y1 * ss0;
                    float t1 = y1 * cc1 + y0 * ss1;
                    y0 = t0; y1 = t1;
                }
                y0 *= qscale; y1 *= qscale;
                if (proj == 0) {
                    uint32_t hi, lo;
                    split2h(y0, y1, hi, lo);
                    *reinterpret_cast<uint32_t*>(g_qhi + base + d0) = hi;
                    *reinterpret_cast<uint32_t*>(g_qlo + base + d0) = lo;
                } else {
                    *reinterpret_cast<uint32_t*>(g_khi + base + d0) = pack2h(y0, y1);
                }
            }
        }
    }
}

// ============================================================================
// V transpose: g_v -> fp16 Vt plane [head][d][pos]
// ============================================================================
__global__ void vt_split()
{
    __shared__ float tile[64][65];
    int head = blockIdx.y, p0 = blockIdx.x * 64;
    int tid = threadIdx.x;
#pragma unroll
    for (int i = 0; i < 16; i++) {
        int idx = tid + i * 256;
        int p = idx >> 6, d = idx & 63;
        tile[p][d] = g_v[(size_t)(p0 + p) * DMODEL + head * HDIM + d];
    }
    __syncthreads();
#pragma unroll
    for (int i = 0; i < 16; i++) {
        int idx = tid + i * 256;
        int d = idx >> 6, p = idx & 63;
        size_t o = ((size_t)head * HDIM + d) * S_TOT + p0 + p;
        g_vthi[o] = __float2half_rn(tile[p][d]);
    }
}

// ============================================================================
// HMMA flash attention (unchanged from R13)
// ============================================================================
#define ASQH 0
#define ASQL 18432
#define ASK  36864
#define ASV  55296
#define ATT_SMEM 73728
#define N_KCH (S_TOT / 64)

__global__ void __launch_bounds__(256, 2) attn_hmma()
{
    extern __shared__ char smc[];
    const int head = blockIdx.y;
    const int q0 = blockIdx.x * 128;
    const int tid = threadIdx.x;
    const int lane = tid & 31;
    const int wid = tid >> 5;
    const uint32_t smb = s2u(smc);

    {
        const __half* Qh = g_qhi + ((size_t)head * S_TOT + q0) * HDIM;
        const __half* Ql = g_qlo + ((size_t)head * S_TOT + q0) * HDIM;
#pragma unroll
        for (int i = 0; i < 4; i++) {
            int idx = tid + i * 256;
            int row = idx >> 3, ch = idx & 7;
            cpa16(smb + ASQH + row * 144 + ch * 16, Qh + row * HDIM + ch * 8);
            cpa16(smb + ASQL + row * 144 + ch * 16, Ql + row * HDIM + ch * 8);
        }
        cpa_commit();
    }

    auto load_kv = [&](int c) {
        int buf = c & 1;
        const __half* Kh = g_khi + ((size_t)head * S_TOT + c * 64) * HDIM;
        uint32_t kb = smb + ASK + buf * 9216;
#pragma unroll
        for (int i = 0; i < 2; i++) {
            int idx = tid + i * 256;
            int row = idx >> 3, ch = idx & 7;
            cpa16(kb + row * 144 + ch * 16, Kh + row * HDIM + ch * 8);
        }
        const __half* Vh = g_vthi + (size_t)head * HDIM * S_TOT + c * 64;
        uint32_t vb = smb + ASV + buf * 9216;
#pragma unroll
        for (int i = 0; i < 2; i++) {
            int idx = tid + i * 256;
            int d = idx >> 3, ch = idx & 7;
            cpa16(vb + d * 144 + ch * 16, Vh + (size_t)d * S_TOT + ch * 8);
        }
        cpa_commit();
    };

    load_kv(0);

    uint32_t aQh[4][4], aQl[4][4];
    float O[8][4];
#pragma unroll
    for (int j = 0; j < 8; j++)
#pragma unroll
        for (int e = 0; e < 4; e++) O[j][e] = 0.f;
    float m0 = -1e30f, m1 = -1e30f, l0 = 0.f, l1 = 0.f;

    for (int c = 0; c < N_KCH; c++) {
        if (c + 1 < N_KCH) {
            load_kv(c + 1);
            asm volatile("cp.async.wait_group 1;" ::: "memory");
        } else {
            asm volatile("cp.async.wait_group 0;" ::: "memory");
        }
        __syncthreads();

        if (c == 0) {
            uint32_t qa = smb + (uint32_t)((wid * 16 + (lane & 15)) * 144)
                          + ((lane >> 4) << 4);
#pragma unroll
            for (int kc = 0; kc < 4; kc++) {
                ldsm4(aQh[kc], qa + ASQH + kc * 32);
                ldsm4(aQl[kc], qa + ASQL + kc * 32);
            }
        }

        int buf = c & 1;
        float s[8][4];
#pragma unroll
        for (int j = 0; j < 8; j++)
#pragma unroll
            for (int e = 0; e < 4; e++) s[j][e] = 0.f;

        uint32_t kb = smb + ASK + buf * 9216 + (uint32_t)((lane & 7) * 144)
                      + (((lane >> 3) & 1) << 4);
#pragma unroll
        for (int kc = 0; kc < 4; kc++) {
#pragma unroll
            for (int j = 0; j < 8; j++) {
                uint32_t bh[2];
                ldsm2(bh, kb + j * (8 * 144) + kc * 32);
                mma_f16(s[j], aQh[kc], bh);
                mma_f16(s[j], aQl[kc], bh);
            }
        }

        float mx0 = -1e30f, mx1 = -1e30f;
#pragma unroll
        for (int j = 0; j < 8; j++) {
            mx0 = fmaxf(mx0, fmaxf(s[j][0], s[j][1]));
            mx1 = fmaxf(mx1, fmaxf(s[j][2], s[j][3]));
        }
        mx0 = fmaxf(mx0, __shfl_xor_sync(0xffffffffu, mx0, 1));
        mx0 = fmaxf(mx0, __shfl_xor_sync(0xffffffffu, mx0, 2));
        mx1 = fmaxf(mx1, __shfl_xor_sync(0xffffffffu, mx1, 1));
        mx1 = fmaxf(mx1, __shfl_xor_sync(0xffffffffu, mx1, 2));
        float mn0 = fmaxf(m0, mx0), mn1 = fmaxf(m1, mx1);
        float cr0 = __expf(m0 - mn0), cr1 = __expf(m1 - mn1);
        m0 = mn0; m1 = mn1;

        float rs0 = 0.f, rs1 = 0.f;
#pragma unroll
        for (int j = 0; j < 8; j++) {
            s[j][0] = __expf(s[j][0] - mn0);
            s[j][1] = __expf(s[j][1] - mn0);
            s[j][2] = __expf(s[j][2] - mn1);
            s[j][3] = __expf(s[j][3] - mn1);
            rs0 += s[j][0] + s[j][1];
            rs1 += s[j][2] + s[j][3];
        }
        rs0 += __shfl_xor_sync(0xffffffffu, rs0, 1);
        rs0 += __shfl_xor_sync(0xffffffffu, rs0, 2);
        rs1 += __shfl_xor_sync(0xffffffffu, rs1, 1);
        rs1 += __shfl_xor_sync(0xffffffffu, rs1, 2);
        l0 = l0 * cr0 + rs0;
        l1 = l1 * cr1 + rs1;

#pragma unroll
        for (int j = 0; j < 8; j++) {
            O[j][0] *= cr0; O[j][1] *= cr0;
            O[j][2] *= cr1; O[j][3] *= cr1;
        }

        uint32_t vb = smb + ASV + buf * 9216 + (uint32_t)((lane & 7) * 144)
                      + (((lane >> 3) & 1) << 4);
#pragma unroll
        for (int ck = 0; ck < 4; ck++) {
            uint32_t ah[4];
            ah[0] = pack2h(s[2 * ck][0],     s[2 * ck][1]);
            ah[1] = pack2h(s[2 * ck][2],     s[2 * ck][3]);
            ah[2] = pack2h(s[2 * ck + 1][0], s[2 * ck + 1][1]);
            ah[3] = pack2h(s[2 * ck + 1][2], s[2 * ck + 1][3]);
#pragma unroll
            for (int jd = 0; jd < 8; jd++) {
                uint32_t bh[2];
                ldsm2(bh, vb + jd * (8 * 144) + ck * 32);
                mma_f16(O[jd], ah, bh);
            }
        }
        __syncthreads();
    }

    float i0 = 1.f / l0, i1 = 1.f / l1;
    int r = q0 + wid * 16 + (lane >> 2);
    int cb = head * HDIM + (lane & 3) * 2;
    __half* row0 = g_ab + (size_t)r * K2;
    __half* row1 = g_ab + (size_t)(r + 8) * K2;
#pragma unroll
    for (int jd = 0; jd < 8; jd++) {
        int col = cb + jd * 8;
        uint32_t hi, lo;
        split2h(O[jd][0] * i0, O[jd][1] * i0, hi, lo);
        *reinterpret_cast<uint32_t*>(row0 + col) = hi;
        *reinterpret_cast<uint32_t*>(row0 + DMODEL + col) = lo;
        split2h(O[jd][2] * i1, O[jd][3] * i1, hi, lo);
        *reinterpret_cast<uint32_t*>(row1 + col) = hi;
        *reinterpret_cast<uint32_t*>(row1 + DMODEL + col) = lo;
    }
}

// ============================================================================
extern "C" void kernel_launch(void* const* d_in, const int* in_sizes, int n_in,
                              void* d_out, int out_size)
{
    const float* hid = (const float*)d_in[0];
    const float* enc = (const float*)d_in[1];
    const float* rc  = (const float*)d_in[2];
    const float* rs  = (const float*)d_in[3];
    const float* Wq  = (const float*)d_in[4];  const float* bq = (const float*)d_in[5];
    const float* Wk  = (const float*)d_in[6];  const float* bk = (const float*)d_in[7];
    const float* Wv  = (const float*)d_in[8];  const float* bv = (const float*)d_in[9];
    const float* Wo  = (const float*)d_in[10]; const float* bo = (const float*)d_in[11];
    const float* lqd = (const float*)d_in[12]; const float* lqu = (const float*)d_in[13];
    const float* lkd = (const float*)d_in[14]; const float* lku = (const float*)d_in[15];
    const float* lvd = (const float*)d_in[16]; const float* lvu = (const float*)d_in[17];
    const float* lpd = (const float*)d_in[18]; const float* lpu = (const float*)d_in[19];
    const float* gq  = (const float*)d_in[20]; const float* btq = (const float*)d_in[21];
    const float* gk  = (const float*)d_in[22]; const float* btk = (const float*)d_in[23];

    static int attr_done = 0;
    if (!attr_done) {
        cudaFuncSetAttribute(attn_hmma, cudaFuncAttributeMaxDynamicSharedMemorySize,
                             ATT_SMEM);
        cudaFuncSetAttribute(gemm_hmma, cudaFuncAttributeMaxDynamicSharedMemorySize,
                             GEMM_SMEM);
        cudaFuncSetAttribute(gemm_qkv, cudaFuncAttributeMaxDynamicSharedMemorySize,
                             GEMM_SMEM);
        attr_done = 1;
    }

    float *pv, *pt;
    __half *pab, *ptb, *pldb, *pwbase;
    cudaGetSymbolAddress((void**)&pv, g_v);
    cudaGetSymbolAddress((void**)&pt, g_t);
    cudaGetSymbolAddress((void**)&pab, g_ab);
    cudaGetSymbolAddress((void**)&ptb, g_tb);
    cudaGetSymbolAddress((void**)&pldb, g_ldb);
    cudaGetSymbolAddress((void**)&pwbase, g_wb);

    const int nHD = S_TOT * DMODEL;
    const int nW  = DMODEL * DMODEL;
    const int nLD = RANK_ * DMODEL;
    const int nLU = DMODEL * RANK_;

    dim3 qkv_grid(72, S_TOT / 128, 1);
    dim3 oproj_grid(DMODEL / 128, S_TOT / 128, 3);   // split-K 3: 17/17/16 chunks
    dim3 lora3_grid(3, S_TOT / 128, 8);
    dim3 lora1_grid(1, S_TOT / 128, 8);
    const int LORA_CH = MAIN_CH / 8;                 // 6

    // ---- A operand + hi-plane weight splits ----
    split_concat_kernel<<<(nHD + 255) / 256, 256>>>(hid, enc);
    splitb3_kernel<<<(3 * nW + 255) / 256, 256>>>(Wq, Wk, Wv, pwbase,
                                                  (size_t)DMODEL * LDB2,
                                                  DMODEL, LDB2, 0, nW);
    splitb3_kernel<<<(3 * nLU + 255) / 256, 256>>>(lqu, lku, lvu, pwbase,
                                                   (size_t)DMODEL * LDB2,
                                                   RANK_, LDB2, DMODEL, nLU);
    splitb3_kernel<<<(3 * nLD + 255) / 256, 256>>>(lqd, lkd, lvd, pldb,
                                                   (size_t)RANK_ * DMODEL,
                                                   DMODEL, DMODEL, 0, nLD);

    // ---- batched lora-down (1-term) ----
    cudaMemsetAsync(pt, 0, S_TOT * 3 * RANK_ * sizeof(float));
    gemm_hmma<<<lora3_grid, 128, GEMM_SMEM>>>(pab, nullptr, 0, pldb, DMODEL,
                                              nullptr, pt, 3 * RANK_,
                                              LORA_CH, MAIN_CH, 0, 1, 0);
    tsplit_kernel<<<(S_TOT * 3 * RANK_ + 255) / 256, 256>>>(3);

    // ---- merged q/k/v GEMM with fused LN+RoPE+plane epilogue ----
    gemm_qkv<<<qkv_grid, 128, GEMM_SMEM>>>(pab, ptb, pwbase, bq, bk, bv,
                                           gq, btq, gk, btk, rc, rs, pv);

    // ---- V transpose plane ----
    vt_split<<<dim3(S_TOT / 64, NHEADS), 256>>>();

    // ---- attention (writes fp16 split of O into g_ab) ----
    attn_hmma<<<dim3(S_TOT / 128, NHEADS), 256, ATT_SMEM>>>();

    // ---- output projection ----
    splitb1_kernel<<<(nW + 255) / 256, 256>>>(Wo, pwbase, DMODEL, LDB2, 0, nW);
    splitb1_kernel<<<(nLU + 255) / 256, 256>>>(lpu, pwbase, RANK_, LDB2, DMODEL, nLU);
    splitb1_kernel<<<(nLD + 255) / 256, 256>>>(lpd, pldb, DMODEL, DMODEL, 0, nLD);
    cudaMemsetAsync(pt, 0, S_TOT * RANK_ * sizeof(float));
    gemm_hmma<<<lora1_grid, 128, GEMM_SMEM>>>(pab, nullptr, 0, pldb, DMODEL,
                                              nullptr, pt, RANK_,
                                              LORA_CH, MAIN_CH, 0, 1, 0);
    tsplit_kernel<<<(S_TOT * RANK_ + 255) / 256, 256>>>(1);
    cudaMemsetAsync(d_out, 0, (size_t)out_size * sizeof(float));
    gemm_hmma<<<oproj_grid, 128, GEMM_SMEM>>>(pab, ptb, 0, pwbase, LDB2,
                                              bo, (float*)d_out, DMODEL,
                                              17, ALL_CH, 1, 1, 1);
}

// round 15
// speedup vs baseline: 1.3846x; 1.0019x over previous
#include <cuda_runtime.h>
#include <cuda_bf16.h>
#include <cuda_fp16.h>
#include <cstdint>

#define S_TOT 2048
#define DMODEL 3072
#define NHEADS 48
#define HDIM 64
#define RANK_ 128
#define TLEN 226
#define VLEN 1822

#define K2 (2 * DMODEL)       // 6144: g_ab row stride ([hi|lo])
#define LDB2 (DMODEL + RANK_) // 3200: weight row stride ([W hi | lu hi])
#define MAIN_CH (DMODEL / 64) // 48
#define ALL_CH (MAIN_CH + 2)  // 50

// ---------------- fp32 scratch ----------------------------------------------
__device__ __align__(256) float g_t[S_TOT * 3 * RANK_];

// ---------------- fp16 operand buffers ---------------------------------------
__device__ __align__(256) __half g_ab[(size_t)S_TOT * K2];
__device__ __align__(256) __half g_tb[(size_t)S_TOT * 768];
__device__ __align__(256) __half g_wb[3][(size_t)DMODEL * LDB2];
__device__ __align__(256) __half g_ldb[(size_t)(3 * RANK_) * DMODEL];

// ---------------- attention fp16 planes (head-major) ------------------------
__device__ __align__(256) __half g_qhi[(size_t)NHEADS * S_TOT * HDIM];
__device__ __align__(256) __half g_qlo[(size_t)NHEADS * S_TOT * HDIM];
__device__ __align__(256) __half g_khi[(size_t)NHEADS * S_TOT * HDIM];
__device__ __align__(256) __half g_vthi[(size_t)NHEADS * HDIM * S_TOT];

// ============================================================================
// helpers
// ============================================================================
__device__ __forceinline__ uint32_t s2u(const void* p) {
    return (uint32_t)__cvta_generic_to_shared(p);
}
__device__ __forceinline__ void cpa16(uint32_t s, const void* g) {
    asm volatile("cp.async.cg.shared.global [%0], [%1], 16;" :: "r"(s), "l"(g));
}
__device__ __forceinline__ void cpa_commit() {
    asm volatile("cp.async.commit_group;" ::: "memory");
}
__device__ __forceinline__ void ldsm4(uint32_t* r, uint32_t a) {
    asm volatile("ldmatrix.sync.aligned.m8n8.x4.shared.b16 {%0,%1,%2,%3}, [%4];"
                 : "=r"(r[0]), "=r"(r[1]), "=r"(r[2]), "=r"(r[3]) : "r"(a));
}
__device__ __forceinline__ void ldsm2(uint32_t* r, uint32_t a) {
    asm volatile("ldmatrix.sync.aligned.m8n8.x2.shared.b16 {%0,%1}, [%2];"
                 : "=r"(r[0]), "=r"(r[1]) : "r"(a));
}
__device__ __forceinline__ void mma_f16(float* c, const uint32_t* a, const uint32_t* b) {
    asm volatile(
        "mma.sync.aligned.m16n8k16.row.col.f32.f16.f16.f32 "
        "{%0,%1,%2,%3}, {%4,%5,%6,%7}, {%8,%9}, {%0,%1,%2,%3};"
        : "+f"(c[0]), "+f"(c[1]), "+f"(c[2]), "+f"(c[3])
        : "r"(a[0]), "r"(a[1]), "r"(a[2]), "r"(a[3]), "r"(b[0]), "r"(b[1]));
}
__device__ __forceinline__ void split2h(float x, float y, uint32_t& hi, uint32_t& lo) {
    __half2 h = __floats2half2_rn(x, y);
    float hx = __half2float(__low2half(h)), hy = __half2float(__high2half(h));
    __half2 l = __floats2half2_rn(x - hx, y - hy);
    hi = *reinterpret_cast<uint32_t*>(&h);
    lo = *reinterpret_cast<uint32_t*>(&l);
}
__device__ __forceinline__ uint32_t pack2h(float x, float y) {
    __half2 h = __floats2half2_rn(x, y);
    return *reinterpret_cast<uint32_t*>(&h);
}

// ============================================================================
// split kernels
// ============================================================================
__global__ void splitb1_kernel(const float* __restrict__ src,
                               __half* __restrict__ dst,
                               int K, int dstStride, int dstOff, int n)
{
    int i = blockIdx.x * 256 + threadIdx.x;
    if (i >= n) return;
    int r = i / K, k = i % K;
    dst[(size_t)r * dstStride + dstOff + k] = __float2half_rn(src[i]);
}

__global__ void splitb3_kernel(const float* __restrict__ s0,
                               const float* __restrict__ s1,
                               const float* __restrict__ s2,
                               __half* __restrict__ dst, size_t dstProjStride,
                               int K, int dstStride, int dstOff, int n)
{
    int i = blockIdx.x * 256 + threadIdx.x;
    if (i >= 3 * n) return;
    int p = i / n, j = i % n;
    const float* src = (p == 0) ? s0 : (p == 1) ? s1 : s2;
    int r = j / K, k = j % K;
    dst[p * dstProjStride + (size_t)r * dstStride + dstOff + k] = __float2half_rn(src[j]);
}

__global__ void split_concat_kernel(const float* __restrict__ hid,
                                    const float* __restrict__ enc)
{
    int i = blockIdx.x * 256 + threadIdx.x;
    if (i >= S_TOT * DMODEL) return;
    int r = i / DMODEL, k = i % DMODEL;
    float x = (r < TLEN) ? enc[i] : hid[i - TLEN * DMODEL];
    __half hi = __float2half_rn(x);
    __half lo = __float2half_rn(x - __half2float(hi));
    __half* d = g_ab + (size_t)r * K2;
    d[k] = hi;
    d[DMODEL + k] = lo;
}

__global__ void tsplit_kernel(int nproj)
{
    int n = S_TOT * nproj * RANK_;
    int i = blockIdx.x * 256 + threadIdx.x;
    if (i >= n) return;
    int kw = nproj * RANK_;
    int r = i / kw, k = i % kw;
    int p = k >> 7, kk = k & 127;
    float x = g_t[(size_t)r * kw + k];
    __half hi = __float2half_rn(x);
    __half lo = __float2half_rn(x - __half2float(hi));
    __half* d = g_tb + (size_t)r * 768 + p * 256;
    d[kk] = hi;
    d[128 + kk] = lo;
}

// ============================================================================
// GEMM core: BK=64 physical, B tile resident, A hi(+lo) passes.
// ============================================================================
#define TILE_B 18432
#define STAGE_B (3 * TILE_B)
#define GEMM_SMEM (2 * STAGE_B)   // 110592

struct GemmCore {
    float acc[4][8][4];
    uint32_t smb;
    int lane, wm0, wn0, lrow, lch;

    __device__ __forceinline__ void init(void* sm) {
        smb = s2u(sm);
        int tid = threadIdx.x;
        lane = tid & 31;
        int wid = tid >> 5;
        wm0 = (wid & 1) * 64; wn0 = (wid >> 1) * 64;
        lrow = tid >> 3; lch = tid & 7;
#pragma unroll
        for (int i = 0; i < 4; i++)
#pragma unroll
            for (int j = 0; j < 8; j++)
#pragma unroll
                for (int e = 0; e < 4; e++) acc[i][j][e] = 0.f;
    }

    __device__ __forceinline__ void load_tile(int buf,
                                              const __half* gaHi, const __half* gaLo,
                                              int alda, const __half* gb, int ldb,
                                              int two) {
        uint32_t base = smb + buf * STAGE_B + lrow * 144 + lch * 16;
#pragma unroll
        for (int i = 0; i < 8; i++) {
            int row = lrow + i * 16;
            cpa16(base + i * (16 * 144), gaHi + (size_t)row * alda);
            cpa16(base + TILE_B * 2 + i * (16 * 144), gb + (size_t)row * ldb);
        }
        if (two) {
#pragma unroll
            for (int i = 0; i < 8; i++) {
                int row = lrow + i * 16;
                cpa16(base + TILE_B + i * (16 * 144), gaLo + (size_t)row * alda);
            }
        }
        cpa_commit();
    }

    __device__ __forceinline__ void compute(int buf, int two) {
        uint32_t sawh = smb + buf * STAGE_B
                        + (uint32_t)((wm0 + (lane & 15)) * 144) + ((lane >> 4) << 4);
        uint32_t sbw = smb + buf * STAGE_B + 2 * TILE_B
                       + (uint32_t)((wn0 + (lane & 7)) * 144) + (((lane >> 3) & 1) << 4);
#pragma unroll
        for (int s = 0; s < 4; s++) {
            uint32_t ah[4][4], al[4][4], bf[8][2];
#pragma unroll
            for (int i = 0; i < 4; i++) ldsm4(ah[i], sawh + i * (16 * 144) + s * 32);
            if (two) {
#pragma unroll
                for (int i = 0; i < 4; i++)
                    ldsm4(al[i], sawh + TILE_B + i * (16 * 144) + s * 32);
            }
#pragma unroll
            for (int j = 0; j < 8; j++) ldsm2(bf[j], sbw + j * (8 * 144) + s * 32);
#pragma unroll
            for (int i = 0; i < 4; i++)
#pragma unroll
                for (int j = 0; j < 8; j++)
                    mma_f16(acc[i][j], ah[i], bf[j]);
            if (two) {
#pragma unroll
                for (int i = 0; i < 4; i++)
#pragma unroll
                    for (int j = 0; j < 8; j++)
                        mma_f16(acc[i][j], al[i], bf[j]);
            }
        }
    }

    __device__ __forceinline__ void store(int r0, int c0, const float* bias,
                                          float* C, int ldc, int use_atomic, int permute) {
#pragma unroll
        for (int i = 0; i < 4; i++) {
#pragma unroll
            for (int j = 0; j < 8; j++) {
                int mm = r0 + wm0 + i * 16 + (lane >> 2);
                int nn = c0 + wn0 + j * 8 + (lane & 3) * 2;
                int row0 = mm, row1 = mm + 8;
                if (permute) {
                    row0 = (row0 < TLEN) ? row0 + VLEN : row0 - TLEN;
                    row1 = (row1 < TLEN) ? row1 + VLEN : row1 - TLEN;
                }
                float* p0 = C + (size_t)row0 * ldc + nn;
                float* p1 = C + (size_t)row1 * ldc + nn;
                float b0v = bias ? bias[nn] : 0.f;
                float b1v = bias ? bias[nn + 1] : 0.f;
                if (use_atomic) {
                    atomicAdd(p0,     acc[i][j][0] + b0v);
                    atomicAdd(p0 + 1, acc[i][j][1] + b1v);
                    atomicAdd(p1,     acc[i][j][2] + b0v);
                    atomicAdd(p1 + 1, acc[i][j][3] + b1v);
                } else {
                    p0[0] = acc[i][j][0] + b0v;
                    p0[1] = acc[i][j][1] + b1v;
                    p1[0] = acc[i][j][2] + b0v;
                    p1[1] = acc[i][j][3] + b1v;
                }
            }
        }
    }
};

// generic GEMM; chunks clamped to total_ch for uneven split-K.
__global__ void __launch_bounds__(128, 2) gemm_hmma(
    const __half* __restrict__ Ah,
    const __half* __restrict__ At, int toff,
    const __half* __restrict__ B, int ldb2,
    const float* __restrict__ bias, float* __restrict__ C, int ldc,
    int chunks, int total_ch, int two_term, int use_atomic, int permute)
{
    extern __shared__ __half sm[];
    GemmCore g;
    g.init(sm);
    const int r0 = blockIdx.y << 7;
    const int c0 = blockIdx.x << 7;
    const int gcb = blockIdx.z * chunks;
    int ch = chunks;
    if (gcb + ch > total_ch) ch = total_ch - gcb;

    auto ldTile = [&](int buf, int gc) {
        const __half *ahi, *alo;
        int alda;
        if (gc < MAIN_CH) {
            ahi = Ah + (size_t)r0 * K2 + gc * 64 + g.lch * 8;
            alo = Ah + (size_t)r0 * K2 + DMODEL + gc * 64 + g.lch * 8;
            alda = K2;
        } else {
            int ct = gc - MAIN_CH;
            ahi = At + (size_t)r0 * 768 + toff + ct * 64 + g.lch * 8;
            alo = At + (size_t)r0 * 768 + toff + 128 + ct * 64 + g.lch * 8;
            alda = 768;
        }
        int bcol = (gc < MAIN_CH) ? gc * 64 : DMODEL + (gc - MAIN_CH) * 64;
        const __half* gb = B + (size_t)c0 * ldb2 + bcol + g.lch * 8;
        g.load_tile(buf, ahi, alo, alda, gb, ldb2, two_term);
    };

    ldTile(0, gcb);
    for (int c = 0; c < ch; c++) {
        if (c + 1 < ch) {
            ldTile((c + 1) & 1, gcb + c + 1);
            asm volatile("cp.async.wait_group 1;" ::: "memory");
        } else {
            asm volatile("cp.async.wait_group 0;" ::: "memory");
        }
        __syncthreads();
        g.compute(c & 1, two_term);
        __syncthreads();
    }
    const float* biasz = (blockIdx.z == 0) ? bias : nullptr;
    g.store(r0, c0, biasz, C, ldc, use_atomic, permute);
}

// ============================================================================
// merged q/k/v projection GEMM with fused epilogues:
// proj 0 -> LN+RoPE -> qhi/qlo (scaled 0.125); proj 1 -> LN+RoPE -> khi;
// proj 2 -> fp16 transpose into g_vthi (via smem staging).
// ============================================================================
__global__ void __launch_bounds__(128, 2) gemm_qkv(
    const __half* __restrict__ Ah, const __half* __restrict__ At,
    const __half* __restrict__ Wbase,
    const float* __restrict__ b0, const float* __restrict__ b1, const float* __restrict__ b2,
    const float* __restrict__ gq, const float* __restrict__ btq,
    const float* __restrict__ gk, const float* __restrict__ btk,
    const float* __restrict__ rc, const float* __restrict__ rs)
{
    extern __shared__ __half sm[];
    GemmCore g;
    g.init(sm);
    const int tid = threadIdx.x;
    const int proj = blockIdx.x / 24;
    const int c0 = (blockIdx.x % 24) << 7;
    const int r0 = blockIdx.y << 7;
    const __half* B = Wbase + (size_t)proj * DMODEL * LDB2;
    const int toff = proj * 256;

    auto ldTile = [&](int buf, int gc) {
        const __half *ahi, *alo;
        int alda;
        if (gc < MAIN_CH) {
            ahi = Ah + (size_t)r0 * K2 + gc * 64 + g.lch * 8;
            alo = Ah + (size_t)r0 * K2 + DMODEL + gc * 64 + g.lch * 8;
            alda = K2;
        } else {
            int ct = gc - MAIN_CH;
            ahi = At + (size_t)r0 * 768 + toff + ct * 64 + g.lch * 8;
            alo = At + (size_t)r0 * 768 + toff + 128 + ct * 64 + g.lch * 8;
            alda = 768;
        }
        int bcol = (gc < MAIN_CH) ? gc * 64 : DMODEL + (gc - MAIN_CH) * 64;
        const __half* gb = B + (size_t)c0 * LDB2 + bcol + g.lch * 8;
        g.load_tile(buf, ahi, alo, alda, gb, LDB2, 1);
    };

    ldTile(0, 0);
    for (int c = 0; c < ALL_CH; c++) {
        if (c + 1 < ALL_CH) {
            ldTile((c + 1) & 1, c + 1);
            asm volatile("cp.async.wait_group 1;" ::: "memory");
        } else {
            asm volatile("cp.async.wait_group 0;" ::: "memory");
        }
        __syncthreads();
        g.compute(c & 1, 1);
        __syncthreads();
    }

    const int lq = g.lane & 3, rq = g.lane >> 2;

    if (proj == 2) {
        // ---- fused V transpose: acc+bias -> smem [dim][pos] fp16 -> g_vthi ----
        __half* st = sm;   // pipeline smem is free now; 128 x 136 halves
#pragma unroll
        for (int i = 0; i < 4; i++) {
#pragma unroll
            for (int j = 0; j < 8; j++) {
                int dl = g.wn0 + j * 8 + lq * 2;
                float bv0 = b2[c0 + dl], bv1 = b2[c0 + dl + 1];
#pragma unroll
                for (int half = 0; half < 2; half++) {
                    int p = g.wm0 + i * 16 + rq + half * 8;
                    st[dl * 136 + p]       = __float2half_rn(g.acc[i][j][2 * half] + bv0);
                    st[(dl + 1) * 136 + p] = __float2half_rn(g.acc[i][j][2 * half + 1] + bv1);
                }
            }
        }
        __syncthreads();
        // coalesced copy-out: 16 threads per dim row, uint4 (8 halves) each
#pragma unroll
        for (int i = 0; i < 16; i++) {
            int d = (tid >> 4) + i * 8;
            int pc = tid & 15;
            uint4 v4 = *reinterpret_cast<uint4*>(st + d * 136 + pc * 8);
            *reinterpret_cast<uint4*>(g_vthi + (size_t)(c0 + d) * S_TOT + r0 + pc * 8) = v4;
        }
        return;
    }

    // ---- fused LN + RoPE + fp16 plane split (one head per warp column) ----
    const float* bias = (proj == 0) ? b0 : b1;
    const float* gamma = (proj == 0) ? gq : gk;
    const float* beta  = (proj == 0) ? btq : btk;
    const float qscale = (proj == 0) ? 0.125f : 1.0f;
    const int head = (c0 + g.wn0) >> 6;

#pragma unroll
    for (int i = 0; i < 4; i++) {
#pragma unroll
        for (int half = 0; half < 2; half++) {
            int pos = r0 + g.wm0 + i * 16 + rq + half * 8;
            float v[16];
            float sum = 0.f, sq = 0.f;
#pragma unroll
            for (int j = 0; j < 8; j++) {
                int d0 = j * 8 + lq * 2;
                float x0 = g.acc[i][j][2 * half]     + bias[c0 + g.wn0 + d0];
                float x1 = g.acc[i][j][2 * half + 1] + bias[c0 + g.wn0 + d0 + 1];
                v[2 * j] = x0; v[2 * j + 1] = x1;
                sum += x0 + x1;
                sq += x0 * x0 + x1 * x1;
            }
            sum += __shfl_xor_sync(0xffffffffu, sum, 1);
            sum += __shfl_xor_sync(0xffffffffu, sum, 2);
            sq  += __shfl_xor_sync(0xffffffffu, sq, 1);
            sq  += __shfl_xor_sync(0xffffffffu, sq, 2);
            float mu = sum * (1.f / 64.f);
            float var = fmaxf(sq * (1.f / 64.f) - mu * mu, 0.f);
            float inv = rsqrtf(var + 1e-5f);

            size_t base = ((size_t)head * S_TOT + pos) * HDIM;
            int rope = (pos >= TLEN);
            int rr = pos - TLEN;
#pragma unroll
            for (int j = 0; j < 8; j++) {
                int d0 = j * 8 + lq * 2;
                float y0 = (v[2 * j]     - mu) * inv * gamma[d0]     + beta[d0];
                float y1 = (v[2 * j + 1] - mu) * inv * gamma[d0 + 1] + beta[d0 + 1];
                if (rope) {
                    float cc0 = rc[rr * HDIM + d0], cc1 = rc[rr * HDIM + d0 + 1];
                    float ss0 = rs[rr * HDIM + d0], ss1 = rs[rr * HDIM + d0 + 1];
                    float t0 = y0 * cc0 - y1 * ss0;
                    float t1 = y1 * cc1 + y0 * ss1;
                    y0 = t0; y1 = t1;
                }
                y0 *= qscale; y1 *= qscale;
                if (proj == 0) {
                    uint32_t hi, lo;
                    split2h(y0, y1, hi, lo);
                    *reinterpret_cast<uint32_t*>(g_qhi + base + d0) = hi;
                    *reinterpret_cast<uint32_t*>(g_qlo + base + d0) = lo;
                } else {
                    *reinterpret_cast<uint32_t*>(g_khi + base + d0) = pack2h(y0, y1);
                }
            }
        }
    }
}

// ============================================================================
// HMMA flash attention: scores fp16 2-term, PV fp16 1-term, KT=64, 2 CTAs/SM.
// ============================================================================
#define ASQH 0
#define ASQL 18432
#define ASK  36864
#define ASV  55296
#define ATT_SMEM 73728
#define N_KCH (S_TOT / 64)

__global__ void __launch_bounds__(256, 2) attn_hmma()
{
    extern __shared__ char smc[];
    const int head = blockIdx.y;
    const int q0 = blockIdx.x * 128;
    const int tid = threadIdx.x;
    const int lane = tid & 31;
    const int wid = tid >> 5;
    const uint32_t smb = s2u(smc);

    {
        const __half* Qh = g_qhi + ((size_t)head * S_TOT + q0) * HDIM;
        const __half* Ql = g_qlo + ((size_t)head * S_TOT + q0) * HDIM;
#pragma unroll
        for (int i = 0; i < 4; i++) {
            int idx = tid + i * 256;
            int row = idx >> 3, ch = idx & 7;
            cpa16(smb + ASQH + row * 144 + ch * 16, Qh + row * HDIM + ch * 8);
            cpa16(smb + ASQL + row * 144 + ch * 16, Ql + row * HDIM + ch * 8);
        }
        cpa_commit();
    }

    auto load_kv = [&](int c) {
        int buf = c & 1;
        const __half* Kh = g_khi + ((size_t)head * S_TOT + c * 64) * HDIM;
        uint32_t kb = smb + ASK + buf * 9216;
#pragma unroll
        for (int i = 0; i < 2; i++) {
            int idx = tid + i * 256;
            int row = idx >> 3, ch = idx & 7;
            cpa16(kb + row * 144 + ch * 16, Kh + row * HDIM + ch * 8);
        }
        const __half* Vh = g_vthi + (size_t)head * HDIM * S_TOT + c * 64;
        uint32_t vb = smb + ASV + buf * 9216;
#pragma unroll
        for (int i = 0; i < 2; i++) {
            int idx = tid + i * 256;
            int d = idx >> 3, ch = idx & 7;
            cpa16(vb + d * 144 + ch * 16, Vh + (size_t)d * S_TOT + ch * 8);
        }
        cpa_commit();
    };

    load_kv(0);

    uint32_t aQh[4][4], aQl[4][4];
    float O[8][4];
#pragma unroll
    for (int j = 0; j < 8; j++)
#pragma unroll
        for (int e = 0; e < 4; e++) O[j][e] = 0.f;
    float m0 = -1e30f, m1 = -1e30f, l0 = 0.f, l1 = 0.f;

    for (int c = 0; c < N_KCH; c++) {
        if (c + 1 < N_KCH) {
            load_kv(c + 1);
            asm volatile("cp.async.wait_group 1;" ::: "memory");
        } else {
            asm volatile("cp.async.wait_group 0;" ::: "memory");
        }
        __syncthreads();

        if (c == 0) {
            uint32_t qa = smb + (uint32_t)((wid * 16 + (lane & 15)) * 144)
                          + ((lane >> 4) << 4);
#pragma unroll
            for (int kc = 0; kc < 4; kc++) {
                ldsm4(aQh[kc], qa + ASQH + kc * 32);
                ldsm4(aQl[kc], qa + ASQL + kc * 32);
            }
        }

        int buf = c & 1;
        float s[8][4];
#pragma unroll
        for (int j = 0; j < 8; j++)
#pragma unroll
            for (int e = 0; e < 4; e++) s[j][e] = 0.f;

        uint32_t kb = smb + ASK + buf * 9216 + (uint32_t)((lane & 7) * 144)
                      + (((lane >> 3) & 1) << 4);
#pragma unroll
        for (int kc = 0; kc < 4; kc++) {
#pragma unroll
            for (int j = 0; j < 8; j++) {
                uint32_t bh[2];
                ldsm2(bh, kb + j * (8 * 144) + kc * 32);
                mma_f16(s[j], aQh[kc], bh);
                mma_f16(s[j], aQl[kc], bh);
            }
        }

        float mx0 = -1e30f, mx1 = -1e30f;
#pragma unroll
        for (int j = 0; j < 8; j++) {
            mx0 = fmaxf(mx0, fmaxf(s[j][0], s[j][1]));
            mx1 = fmaxf(mx1, fmaxf(s[j][2], s[j][3]));
        }
        mx0 = fmaxf(mx0, __shfl_xor_sync(0xffffffffu, mx0, 1));
        mx0 = fmaxf(mx0, __shfl_xor_sync(0xffffffffu, mx0, 2));
        mx1 = fmaxf(mx1, __shfl_xor_sync(0xffffffffu, mx1, 1));
        mx1 = fmaxf(mx1, __shfl_xor_sync(0xffffffffu, mx1, 2));
        float mn0 = fmaxf(m0, mx0), mn1 = fmaxf(m1, mx1);
        float cr0 = __expf(m0 - mn0), cr1 = __expf(m1 - mn1);
        m0 = mn0; m1 = mn1;

        float rs0 = 0.f, rs1 = 0.f;
#pragma unroll
        for (int j = 0; j < 8; j++) {
            s[j][0] = __expf(s[j][0] - mn0);
            s[j][1] = __expf(s[j][1] - mn0);
            s[j][2] = __expf(s[j][2] - mn1);
            s[j][3] = __expf(s[j][3] - mn1);
            rs0 += s[j][0] + s[j][1];
            rs1 += s[j][2] + s[j][3];
        }
        rs0 += __shfl_xor_sync(0xffffffffu, rs0, 1);
        rs0 += __shfl_xor_sync(0xffffffffu, rs0, 2);
        rs1 += __shfl_xor_sync(0xffffffffu, rs1, 1);
        rs1 += __shfl_xor_sync(0xffffffffu, rs1, 2);
        l0 = l0 * cr0 + rs0;
        l1 = l1 * cr1 + rs1;

#pragma unroll
        for (int j = 0; j < 8; j++) {
            O[j][0] *= cr0; O[j][1] *= cr0;
            O[j][2] *= cr1; O[j][3] *= cr1;
        }

        uint32_t vb = smb + ASV + buf * 9216 + (uint32_t)((lane & 7) * 144)
                      + (((lane >> 3) & 1) << 4);
#pragma unroll
        for (int ck = 0; ck < 4; ck++) {
            uint32_t ah[4];
            ah[0] = pack2h(s[2 * ck][0],     s[2 * ck][1]);
            ah[1] = pack2h(s[2 * ck][2],     s[2 * ck][3]);
            ah[2] = pack2h(s[2 * ck + 1][0], s[2 * ck + 1][1]);
            ah[3] = pack2h(s[2 * ck + 1][2], s[2 * ck + 1][3]);
#pragma unroll
            for (int jd = 0; jd < 8; jd++) {
                uint32_t bh[2];
                ldsm2(bh, vb + jd * (8 * 144) + ck * 32);
                mma_f16(O[jd], ah, bh);
            }
        }
        __syncthreads();
    }

    float i0 = 1.f / l0, i1 = 1.f / l1;
    int r = q0 + wid * 16 + (lane >> 2);
    int cb = head * HDIM + (lane & 3) * 2;
    __half* row0 = g_ab + (size_t)r * K2;
    __half* row1 = g_ab + (size_t)(r + 8) * K2;
#pragma unroll
    for (int jd = 0; jd < 8; jd++) {
        int col = cb + jd * 8;
        uint32_t hi, lo;
        split2h(O[jd][0] * i0, O[jd][1] * i0, hi, lo);
        *reinterpret_cast<uint32_t*>(row0 + col) = hi;
        *reinterpret_cast<uint32_t*>(row0 + DMODEL + col) = lo;
        split2h(O[jd][2] * i1, O[jd][3] * i1, hi, lo);
        *reinterpret_cast<uint32_t*>(row1 + col) = hi;
        *reinterpret_cast<uint32_t*>(row1 + DMODEL + col) = lo;
    }
}

// ============================================================================
extern "C" void kernel_launch(void* const* d_in, const int* in_sizes, int n_in,
                              void* d_out, int out_size)
{
    const float* hid = (const float*)d_in[0];
    const float* enc = (const float*)d_in[1];
    const float* rc  = (const float*)d_in[2];
    const float* rs  = (const float*)d_in[3];
    const float* Wq  = (const float*)d_in[4];  const float* bq = (const float*)d_in[5];
    const float* Wk  = (const float*)d_in[6];  const float* bk = (const float*)d_in[7];
    const float* Wv  = (const float*)d_in[8];  const float* bv = (const float*)d_in[9];
    const float* Wo  = (const float*)d_in[10]; const float* bo = (const float*)d_in[11];
    const float* lqd = (const float*)d_in[12]; const float* lqu = (const float*)d_in[13];
    const float* lkd = (const float*)d_in[14]; const float* lku = (const float*)d_in[15];
    const float* lvd = (const float*)d_in[16]; const float* lvu = (const float*)d_in[17];
    const float* lpd = (const float*)d_in[18]; const float* lpu = (const float*)d_in[19];
    const float* gq  = (const float*)d_in[20]; const float* btq = (const float*)d_in[21];
    const float* gk  = (const float*)d_in[22]; const float* btk = (const float*)d_in[23];

    static int attr_done = 0;
    if (!attr_done) {
        cudaFuncSetAttribute(attn_hmma, cudaFuncAttributeMaxDynamicSharedMemorySize,
                             ATT_SMEM);
        cudaFuncSetAttribute(gemm_hmma, cudaFuncAttributeMaxDynamicSharedMemorySize,
                             GEMM_SMEM);
        cudaFuncSetAttribute(gemm_qkv, cudaFuncAttributeMaxDynamicSharedMemorySize,
                             GEMM_SMEM);
        attr_done = 1;
    }

    float* pt;
    __half *pab, *ptb, *pldb, *pwbase;
    cudaGetSymbolAddress((void**)&pt, g_t);
    cudaGetSymbolAddress((void**)&pab, g_ab);
    cudaGetSymbolAddress((void**)&ptb, g_tb);
    cudaGetSymbolAddress((void**)&pldb, g_ldb);
    cudaGetSymbolAddress((void**)&pwbase, g_wb);

    const int nHD = S_TOT * DMODEL;
    const int nW  = DMODEL * DMODEL;
    const int nLD = RANK_ * DMODEL;
    const int nLU = DMODEL * RANK_;

    dim3 qkv_grid(72, S_TOT / 128, 1);
    dim3 oproj_grid(DMODEL / 128, S_TOT / 128, 3);   // split-K 3: 17/17/16
    dim3 lora3_grid(3, S_TOT / 128, 8);
    dim3 lora1_grid(1, S_TOT / 128, 8);
    const int LORA_CH = MAIN_CH / 8;                 // 6

    // ---- A operand + hi-plane weight splits ----
    split_concat_kernel<<<(nHD + 255) / 256, 256>>>(hid, enc);
    splitb3_kernel<<<(3 * nW + 255) / 256, 256>>>(Wq, Wk, Wv, pwbase,
                                                  (size_t)DMODEL * LDB2,
                                                  DMODEL, LDB2, 0, nW);
    splitb3_kernel<<<(3 * nLU + 255) / 256, 256>>>(lqu, lku, lvu, pwbase,
                                                   (size_t)DMODEL * LDB2,
                                                   RANK_, LDB2, DMODEL, nLU);
    splitb3_kernel<<<(3 * nLD + 255) / 256, 256>>>(lqd, lkd, lvd, pldb,
                                                   (size_t)RANK_ * DMODEL,
                                                   DMODEL, DMODEL, 0, nLD);

    // ---- batched lora-down (1-term) ----
    cudaMemsetAsync(pt, 0, S_TOT * 3 * RANK_ * sizeof(float));
    gemm_hmma<<<lora3_grid, 128, GEMM_SMEM>>>(pab, nullptr, 0, pldb, DMODEL,
                                              nullptr, pt, 3 * RANK_,
                                              LORA_CH, MAIN_CH, 0, 1, 0);
    tsplit_kernel<<<(S_TOT * 3 * RANK_ + 255) / 256, 256>>>(3);

    // ---- merged q/k/v GEMM with fused LN+RoPE / V-transpose epilogues ----
    gemm_qkv<<<qkv_grid, 128, GEMM_SMEM>>>(pab, ptb, pwbase, bq, bk, bv,
                                           gq, btq, gk, btk, rc, rs);

    // ---- attention (writes fp16 split of O into g_ab) ----
    attn_hmma<<<dim3(S_TOT / 128, NHEADS), 256, ATT_SMEM>>>();

    // ---- output projection ----
    splitb1_kernel<<<(nW + 255) / 256, 256>>>(Wo, pwbase, DMODEL, LDB2, 0, nW);
    splitb1_kernel<<<(nLU + 255) / 256, 256>>>(lpu, pwbase, RANK_, LDB2, DMODEL, nLU);
    splitb1_kernel<<<(nLD + 255) / 256, 256>>>(lpd, pldb, DMODEL, DMODEL, 0, nLD);
    cudaMemsetAsync(pt, 0, S_TOT * RANK_ * sizeof(float));
    gemm_hmma<<<lora1_grid, 128, GEMM_SMEM>>>(pab, nullptr, 0, pldb, DMODEL,
                                              nullptr, pt, RANK_,
                                              LORA_CH, MAIN_CH, 0, 1, 0);
    tsplit_kernel<<<(S_TOT * RANK_ + 255) / 256, 256>>>(1);
    cudaMemsetAsync(d_out, 0, (size_t)out_size * sizeof(float));
    gemm_hmma<<<oproj_grid, 128, GEMM_SMEM>>>(pab, ptb, 0, pwbase, LDB2,
                                              bo, (float*)d_out, DMODEL,
                                              17, ALL_CH, 1, 1, 1);
}

// round 16
// speedup vs baseline: 1.3949x; 1.0074x over previous
#include <cuda_runtime.h>
#include <cuda_bf16.h>
#include <cuda_fp16.h>
#include <cstdint>

#define S_TOT 2048
#define DMODEL 3072
#define NHEADS 48
#define HDIM 64
#define RANK_ 128
#define TLEN 226
#define VLEN 1822

#define K2 (2 * DMODEL)       // 6144: g_ab row stride ([hi|lo])
#define LDB2 (DMODEL + RANK_) // 3200: weight row stride ([W hi | lu hi])
#define MAIN_CH (DMODEL / 64) // 48
#define ALL_CH (MAIN_CH + 2)  // 50

// ---------------- fp32 scratch ----------------------------------------------
__device__ __align__(256) float g_t[S_TOT * 3 * RANK_];

// ---------------- fp16 operand buffers ---------------------------------------
__device__ __align__(256) __half g_ab[(size_t)S_TOT * K2];
__device__ __align__(256) __half g_tb[(size_t)S_TOT * 768];
__device__ __align__(256) __half g_wb[4][(size_t)DMODEL * LDB2];   // q,k,v,o
__device__ __align__(256) __half g_ldb[(size_t)(4 * RANK_) * DMODEL]; // q,k,v,o lora-down

// ---------------- attention fp16 planes (head-major) ------------------------
__device__ __align__(256) __half g_qhi[(size_t)NHEADS * S_TOT * HDIM];
__device__ __align__(256) __half g_qlo[(size_t)NHEADS * S_TOT * HDIM];
__device__ __align__(256) __half g_khi[(size_t)NHEADS * S_TOT * HDIM];
__device__ __align__(256) __half g_vthi[(size_t)NHEADS * HDIM * S_TOT];

// ============================================================================
// helpers
// ============================================================================
__device__ __forceinline__ uint32_t s2u(const void* p) {
    return (uint32_t)__cvta_generic_to_shared(p);
}
__device__ __forceinline__ void cpa16(uint32_t s, const void* g) {
    asm volatile("cp.async.cg.shared.global [%0], [%1], 16;" :: "r"(s), "l"(g));
}
__device__ __forceinline__ void cpa_commit() {
    asm volatile("cp.async.commit_group;" ::: "memory");
}
__device__ __forceinline__ void ldsm4(uint32_t* r, uint32_t a) {
    asm volatile("ldmatrix.sync.aligned.m8n8.x4.shared.b16 {%0,%1,%2,%3}, [%4];"
                 : "=r"(r[0]), "=r"(r[1]), "=r"(r[2]), "=r"(r[3]) : "r"(a));
}
__device__ __forceinline__ void ldsm2(uint32_t* r, uint32_t a) {
    asm volatile("ldmatrix.sync.aligned.m8n8.x2.shared.b16 {%0,%1}, [%2];"
                 : "=r"(r[0]), "=r"(r[1]) : "r"(a));
}
__device__ __forceinline__ void mma_f16(float* c, const uint32_t* a, const uint32_t* b) {
    asm volatile(
        "mma.sync.aligned.m16n8k16.row.col.f32.f16.f16.f32 "
        "{%0,%1,%2,%3}, {%4,%5,%6,%7}, {%8,%9}, {%0,%1,%2,%3};"
        : "+f"(c[0]), "+f"(c[1]), "+f"(c[2]), "+f"(c[3])
        : "r"(a[0]), "r"(a[1]), "r"(a[2]), "r"(a[3]), "r"(b[0]), "r"(b[1]));
}
__device__ __forceinline__ void split2h(float x, float y, uint32_t& hi, uint32_t& lo) {
    __half2 h = __floats2half2_rn(x, y);
    float hx = __half2float(__low2half(h)), hy = __half2float(__high2half(h));
    __half2 l = __floats2half2_rn(x - hx, y - hy);
    hi = *reinterpret_cast<uint32_t*>(&h);
    lo = *reinterpret_cast<uint32_t*>(&l);
}
__device__ __forceinline__ uint32_t pack2h(float x, float y) {
    __half2 h = __floats2half2_rn(x, y);
    return *reinterpret_cast<uint32_t*>(&h);
}

// ============================================================================
// split kernels
// ============================================================================
__global__ void splitb1_kernel(const float* __restrict__ src,
                               __half* __restrict__ dst,
                               int K, int dstStride, int dstOff, int n)
{
    int i = blockIdx.x * 256 + threadIdx.x;
    if (i >= n) return;
    int r = i / K, k = i % K;
    dst[(size_t)r * dstStride + dstOff + k] = __float2half_rn(src[i]);
}

__global__ void splitb3_kernel(const float* __restrict__ s0,
                               const float* __restrict__ s1,
                               const float* __restrict__ s2,
                               __half* __restrict__ dst, size_t dstProjStride,
                               int K, int dstStride, int dstOff, int n)
{
    int i = blockIdx.x * 256 + threadIdx.x;
    if (i >= 3 * n) return;
    int p = i / n, j = i % n;
    const float* src = (p == 0) ? s0 : (p == 1) ? s1 : s2;
    int r = j / K, k = j % K;
    dst[p * dstProjStride + (size_t)r * dstStride + dstOff + k] = __float2half_rn(src[j]);
}

__global__ void split_concat_kernel(const float* __restrict__ hid,
                                    const float* __restrict__ enc)
{
    int i = blockIdx.x * 256 + threadIdx.x;
    if (i >= S_TOT * DMODEL) return;
    int r = i / DMODEL, k = i % DMODEL;
    float x = (r < TLEN) ? enc[i] : hid[i - TLEN * DMODEL];
    __half hi = __float2half_rn(x);
    __half lo = __float2half_rn(x - __half2float(hi));
    __half* d = g_ab + (size_t)r * K2;
    d[k] = hi;
    d[DMODEL + k] = lo;
}

__global__ void tsplit_kernel(int nproj)
{
    int n = S_TOT * nproj * RANK_;
    int i = blockIdx.x * 256 + threadIdx.x;
    if (i >= n) return;
    int kw = nproj * RANK_;
    int r = i / kw, k = i % kw;
    int p = k >> 7, kk = k & 127;
    float x = g_t[(size_t)r * kw + k];
    __half hi = __float2half_rn(x);
    __half lo = __float2half_rn(x - __half2float(hi));
    __half* d = g_tb + (size_t)r * 768 + p * 256;
    d[kk] = hi;
    d[128 + kk] = lo;
}

// ============================================================================
// GEMM core: BK=64 physical, B tile resident, A hi(+lo) passes.
// ============================================================================
#define TILE_B 18432
#define STAGE_B (3 * TILE_B)
#define GEMM_SMEM (2 * STAGE_B)   // 110592

struct GemmCore {
    float acc[4][8][4];
    uint32_t smb;
    int lane, wm0, wn0, lrow, lch;

    __device__ __forceinline__ void init(void* sm) {
        smb = s2u(sm);
        int tid = threadIdx.x;
        lane = tid & 31;
        int wid = tid >> 5;
        wm0 = (wid & 1) * 64; wn0 = (wid >> 1) * 64;
        lrow = tid >> 3; lch = tid & 7;
#pragma unroll
        for (int i = 0; i < 4; i++)
#pragma unroll
            for (int j = 0; j < 8; j++)
#pragma unroll
                for (int e = 0; e < 4; e++) acc[i][j][e] = 0.f;
    }

    __device__ __forceinline__ void load_tile(int buf,
                                              const __half* gaHi, const __half* gaLo,
                                              int alda, const __half* gb, int ldb,
                                              int two) {
        uint32_t base = smb + buf * STAGE_B + lrow * 144 + lch * 16;
#pragma unroll
        for (int i = 0; i < 8; i++) {
            int row = lrow + i * 16;
            cpa16(base + i * (16 * 144), gaHi + (size_t)row * alda);
            cpa16(base + TILE_B * 2 + i * (16 * 144), gb + (size_t)row * ldb);
        }
        if (two) {
#pragma unroll
            for (int i = 0; i < 8; i++) {
                int row = lrow + i * 16;
                cpa16(base + TILE_B + i * (16 * 144), gaLo + (size_t)row * alda);
            }
        }
        cpa_commit();
    }

    __device__ __forceinline__ void compute(int buf, int two) {
        uint32_t sawh = smb + buf * STAGE_B
                        + (uint32_t)((wm0 + (lane & 15)) * 144) + ((lane >> 4) << 4);
        uint32_t sbw = smb + buf * STAGE_B + 2 * TILE_B
                       + (uint32_t)((wn0 + (lane & 7)) * 144) + (((lane >> 3) & 1) << 4);
#pragma unroll
        for (int s = 0; s < 4; s++) {
            uint32_t ah[4][4], al[4][4], bf[8][2];
#pragma unroll
            for (int i = 0; i < 4; i++) ldsm4(ah[i], sawh + i * (16 * 144) + s * 32);
            if (two) {
#pragma unroll
                for (int i = 0; i < 4; i++)
                    ldsm4(al[i], sawh + TILE_B + i * (16 * 144) + s * 32);
            }
#pragma unroll
            for (int j = 0; j < 8; j++) ldsm2(bf[j], sbw + j * (8 * 144) + s * 32);
#pragma unroll
            for (int i = 0; i < 4; i++)
#pragma unroll
                for (int j = 0; j < 8; j++)
                    mma_f16(acc[i][j], ah[i], bf[j]);
            if (two) {
#pragma unroll
                for (int i = 0; i < 4; i++)
#pragma unroll
                    for (int j = 0; j < 8; j++)
                        mma_f16(acc[i][j], al[i], bf[j]);
            }
        }
    }

    __device__ __forceinline__ void store(int r0, int c0, const float* bias,
                                          float* C, int ldc, int use_atomic, int permute) {
#pragma unroll
        for (int i = 0; i < 4; i++) {
#pragma unroll
            for (int j = 0; j < 8; j++) {
                int mm = r0 + wm0 + i * 16 + (lane >> 2);
                int nn = c0 + wn0 + j * 8 + (lane & 3) * 2;
                int row0 = mm, row1 = mm + 8;
                if (permute) {
                    row0 = (row0 < TLEN) ? row0 + VLEN : row0 - TLEN;
                    row1 = (row1 < TLEN) ? row1 + VLEN : row1 - TLEN;
                }
                float* p0 = C + (size_t)row0 * ldc + nn;
                float* p1 = C + (size_t)row1 * ldc + nn;
                float b0v = bias ? bias[nn] : 0.f;
                float b1v = bias ? bias[nn + 1] : 0.f;
                if (use_atomic) {
                    atomicAdd(p0,     acc[i][j][0] + b0v);
                    atomicAdd(p0 + 1, acc[i][j][1] + b1v);
                    atomicAdd(p1,     acc[i][j][2] + b0v);
                    atomicAdd(p1 + 1, acc[i][j][3] + b1v);
                } else {
                    p0[0] = acc[i][j][0] + b0v;
                    p0[1] = acc[i][j][1] + b1v;
                    p1[0] = acc[i][j][2] + b0v;
                    p1[1] = acc[i][j][3] + b1v;
                }
            }
        }
    }
};

// generic GEMM; chunks clamped to total_ch for uneven split-K.
__global__ void __launch_bounds__(128, 2) gemm_hmma(
    const __half* __restrict__ Ah,
    const __half* __restrict__ At, int toff,
    const __half* __restrict__ B, int ldb2,
    const float* __restrict__ bias, float* __restrict__ C, int ldc,
    int chunks, int total_ch, int two_term, int use_atomic, int permute)
{
    extern __shared__ __half sm[];
    GemmCore g;
    g.init(sm);
    const int r0 = blockIdx.y << 7;
    const int c0 = blockIdx.x << 7;
    const int gcb = blockIdx.z * chunks;
    int ch = chunks;
    if (gcb + ch > total_ch) ch = total_ch - gcb;

    auto ldTile = [&](int buf, int gc) {
        const __half *ahi, *alo;
        int alda;
        if (gc < MAIN_CH) {
            ahi = Ah + (size_t)r0 * K2 + gc * 64 + g.lch * 8;
            alo = Ah + (size_t)r0 * K2 + DMODEL + gc * 64 + g.lch * 8;
            alda = K2;
        } else {
            int ct = gc - MAIN_CH;
            ahi = At + (size_t)r0 * 768 + toff + ct * 64 + g.lch * 8;
            alo = At + (size_t)r0 * 768 + toff + 128 + ct * 64 + g.lch * 8;
            alda = 768;
        }
        int bcol = (gc < MAIN_CH) ? gc * 64 : DMODEL + (gc - MAIN_CH) * 64;
        const __half* gb = B + (size_t)c0 * ldb2 + bcol + g.lch * 8;
        g.load_tile(buf, ahi, alo, alda, gb, ldb2, two_term);
    };

    ldTile(0, gcb);
    for (int c = 0; c < ch; c++) {
        if (c + 1 < ch) {
            ldTile((c + 1) & 1, gcb + c + 1);
            asm volatile("cp.async.wait_group 1;" ::: "memory");
        } else {
            asm volatile("cp.async.wait_group 0;" ::: "memory");
        }
        __syncthreads();
        g.compute(c & 1, two_term);
        __syncthreads();
    }
    const float* biasz = (blockIdx.z == 0) ? bias : nullptr;
    g.store(r0, c0, biasz, C, ldc, use_atomic, permute);
}

// ============================================================================
// merged q/k/v projection GEMM with fused epilogues (unchanged from R15)
// ============================================================================
__global__ void __launch_bounds__(128, 2) gemm_qkv(
    const __half* __restrict__ Ah, const __half* __restrict__ At,
    const __half* __restrict__ Wbase,
    const float* __restrict__ b0, const float* __restrict__ b1, const float* __restrict__ b2,
    const float* __restrict__ gq, const float* __restrict__ btq,
    const float* __restrict__ gk, const float* __restrict__ btk,
    const float* __restrict__ rc, const float* __restrict__ rs)
{
    extern __shared__ __half sm[];
    GemmCore g;
    g.init(sm);
    const int tid = threadIdx.x;
    const int proj = blockIdx.x / 24;
    const int c0 = (blockIdx.x % 24) << 7;
    const int r0 = blockIdx.y << 7;
    const __half* B = Wbase + (size_t)proj * DMODEL * LDB2;
    const int toff = proj * 256;

    auto ldTile = [&](int buf, int gc) {
        const __half *ahi, *alo;
        int alda;
        if (gc < MAIN_CH) {
            ahi = Ah + (size_t)r0 * K2 + gc * 64 + g.lch * 8;
            alo = Ah + (size_t)r0 * K2 + DMODEL + gc * 64 + g.lch * 8;
            alda = K2;
        } else {
            int ct = gc - MAIN_CH;
            ahi = At + (size_t)r0 * 768 + toff + ct * 64 + g.lch * 8;
            alo = At + (size_t)r0 * 768 + toff + 128 + ct * 64 + g.lch * 8;
            alda = 768;
        }
        int bcol = (gc < MAIN_CH) ? gc * 64 : DMODEL + (gc - MAIN_CH) * 64;
        const __half* gb = B + (size_t)c0 * LDB2 + bcol + g.lch * 8;
        g.load_tile(buf, ahi, alo, alda, gb, LDB2, 1);
    };

    ldTile(0, 0);
    for (int c = 0; c < ALL_CH; c++) {
        if (c + 1 < ALL_CH) {
            ldTile((c + 1) & 1, c + 1);
            asm volatile("cp.async.wait_group 1;" ::: "memory");
        } else {
            asm volatile("cp.async.wait_group 0;" ::: "memory");
        }
        __syncthreads();
        g.compute(c & 1, 1);
        __syncthreads();
    }

    const int lq = g.lane & 3, rq = g.lane >> 2;

    if (proj == 2) {
        __half* st = sm;
#pragma unroll
        for (int i = 0; i < 4; i++) {
#pragma unroll
            for (int j = 0; j < 8; j++) {
                int dl = g.wn0 + j * 8 + lq * 2;
                float bv0 = b2[c0 + dl], bv1 = b2[c0 + dl + 1];
#pragma unroll
                for (int half = 0; half < 2; half++) {
                    int p = g.wm0 + i * 16 + rq + half * 8;
                    st[dl * 136 + p]       = __float2half_rn(g.acc[i][j][2 * half] + bv0);
                    st[(dl + 1) * 136 + p] = __float2half_rn(g.acc[i][j][2 * half + 1] + bv1);
                }
            }
        }
        __syncthreads();
#pragma unroll
        for (int i = 0; i < 16; i++) {
            int d = (tid >> 4) + i * 8;
            int pc = tid & 15;
            uint4 v4 = *reinterpret_cast<uint4*>(st + d * 136 + pc * 8);
            *reinterpret_cast<uint4*>(g_vthi + (size_t)(c0 + d) * S_TOT + r0 + pc * 8) = v4;
        }
        return;
    }

    const float* bias = (proj == 0) ? b0 : b1;
    const float* gamma = (proj == 0) ? gq : gk;
    const float* beta  = (proj == 0) ? btq : btk;
    const float qscale = (proj == 0) ? 0.125f : 1.0f;
    const int head = (c0 + g.wn0) >> 6;

#pragma unroll
    for (int i = 0; i < 4; i++) {
#pragma unroll
        for (int half = 0; half < 2; half++) {
            int pos = r0 + g.wm0 + i * 16 + rq + half * 8;
            float v[16];
            float sum = 0.f, sq = 0.f;
#pragma unroll
            for (int j = 0; j < 8; j++) {
                int d0 = j * 8 + lq * 2;
                float x0 = g.acc[i][j][2 * half]     + bias[c0 + g.wn0 + d0];
                float x1 = g.acc[i][j][2 * half + 1] + bias[c0 + g.wn0 + d0 + 1];
                v[2 * j] = x0; v[2 * j + 1] = x1;
                sum += x0 + x1;
                sq += x0 * x0 + x1 * x1;
            }
            sum += __shfl_xor_sync(0xffffffffu, sum, 1);
            sum += __shfl_xor_sync(0xffffffffu, sum, 2);
            sq  += __shfl_xor_sync(0xffffffffu, sq, 1);
            sq  += __shfl_xor_sync(0xffffffffu, sq, 2);
            float mu = sum * (1.f / 64.f);
            float var = fmaxf(sq * (1.f / 64.f) - mu * mu, 0.f);
            float inv = rsqrtf(var + 1e-5f);

            size_t base = ((size_t)head * S_TOT + pos) * HDIM;
            int rope = (pos >= TLEN);
            int rr = pos - TLEN;
#pragma unroll
            for (int j = 0; j < 8; j++) {
                int d0 = j * 8 + lq * 2;
                float y0 = (v[2 * j]     - mu) * inv * gamma[d0]     + beta[d0];
                float y1 = (v[2 * j + 1] - mu) * inv * gamma[d0 + 1] + beta[d0 + 1];
                if (rope) {
                    float cc0 = rc[rr * HDIM + d0], cc1 = rc[rr * HDIM + d0 + 1];
                    float ss0 = rs[rr * HDIM + d0], ss1 = rs[rr * HDIM + d0 + 1];
                    float t0 = y0 * cc0 - y1 * ss0;
                    float t1 = y1 * cc1 + y0 * ss1;
                    y0 = t0; y1 = t1;
                }
                y0 *= qscale; y1 *= qscale;
                if (proj == 0) {
                    uint32_t hi, lo;
                    split2h(y0, y1, hi, lo);
                    *reinterpret_cast<uint32_t*>(g_qhi + base + d0) = hi;
                    *reinterpret_cast<uint32_t*>(g_qlo + base + d0) = lo;
                } else {
                    *reinterpret_cast<uint32_t*>(g_khi + base + d0) = pack2h(y0, y1);
                }
            }
        }
    }
}

// ============================================================================
// HMMA flash attention (unchanged from R15)
// ============================================================================
#define ASQH 0
#define ASQL 18432
#define ASK  36864
#define ASV  55296
#define ATT_SMEM 73728
#define N_KCH (S_TOT / 64)

__global__ void __launch_bounds__(256, 2) attn_hmma()
{
    extern __shared__ char smc[];
    const int head = blockIdx.y;
    const int q0 = blockIdx.x * 128;
    const int tid = threadIdx.x;
    const int lane = tid & 31;
    const int wid = tid >> 5;
    const uint32_t smb = s2u(smc);

    {
        const __half* Qh = g_qhi + ((size_t)head * S_TOT + q0) * HDIM;
        const __half* Ql = g_qlo + ((size_t)head * S_TOT + q0) * HDIM;
#pragma unroll
        for (int i = 0; i < 4; i++) {
            int idx = tid + i * 256;
            int row = idx >> 3, ch = idx & 7;
            cpa16(smb + ASQH + row * 144 + ch * 16, Qh + row * HDIM + ch * 8);
            cpa16(smb + ASQL + row * 144 + ch * 16, Ql + row * HDIM + ch * 8);
        }
        cpa_commit();
    }

    auto load_kv = [&](int c) {
        int buf = c & 1;
        const __half* Kh = g_khi + ((size_t)head * S_TOT + c * 64) * HDIM;
        uint32_t kb = smb + ASK + buf * 9216;
#pragma unroll
        for (int i = 0; i < 2; i++) {
            int idx = tid + i * 256;
            int row = idx >> 3, ch = idx & 7;
            cpa16(kb + row * 144 + ch * 16, Kh + row * HDIM + ch * 8);
        }
        const __half* Vh = g_vthi + (size_t)head * HDIM * S_TOT + c * 64;
        uint32_t vb = smb + ASV + buf * 9216;
#pragma unroll
        for (int i = 0; i < 2; i++) {
            int idx = tid + i * 256;
            int d = idx >> 3, ch = idx & 7;
            cpa16(vb + d * 144 + ch * 16, Vh + (size_t)d * S_TOT + ch * 8);
        }
        cpa_commit();
    };

    load_kv(0);

    uint32_t aQh[4][4], aQl[4][4];
    float O[8][4];
#pragma unroll
    for (int j = 0; j < 8; j++)
#pragma unroll
        for (int e = 0; e < 4; e++) O[j][e] = 0.f;
    float m0 = -1e30f, m1 = -1e30f, l0 = 0.f, l1 = 0.f;

    for (int c = 0; c < N_KCH; c++) {
        if (c + 1 < N_KCH) {
            load_kv(c + 1);
            asm volatile("cp.async.wait_group 1;" ::: "memory");
        } else {
            asm volatile("cp.async.wait_group 0;" ::: "memory");
        }
        __syncthreads();

        if (c == 0) {
            uint32_t qa = smb + (uint32_t)((wid * 16 + (lane & 15)) * 144)
                          + ((lane >> 4) << 4);
#pragma unroll
            for (int kc = 0; kc < 4; kc++) {
                ldsm4(aQh[kc], qa + ASQH + kc * 32);
                ldsm4(aQl[kc], qa + ASQL + kc * 32);
            }
        }

        int buf = c & 1;
        float s[8][4];
#pragma unroll
        for (int j = 0; j < 8; j++)
#pragma unroll
            for (int e = 0; e < 4; e++) s[j][e] = 0.f;

        uint32_t kb = smb + ASK + buf * 9216 + (uint32_t)((lane & 7) * 144)
                      + (((lane >> 3) & 1) << 4);
#pragma unroll
        for (int kc = 0; kc < 4; kc++) {
#pragma unroll
            for (int j = 0; j < 8; j++) {
                uint32_t bh[2];
                ldsm2(bh, kb + j * (8 * 144) + kc * 32);
                mma_f16(s[j], aQh[kc], bh);
                mma_f16(s[j], aQl[kc], bh);
            }
        }

        float mx0 = -1e30f, mx1 = -1e30f;
#pragma unroll
        for (int j = 0; j < 8; j++) {
            mx0 = fmaxf(mx0, fmaxf(s[j][0], s[j][1]));
            mx1 = fmaxf(mx1, fmaxf(s[j][2], s[j][3]));
        }
        mx0 = fmaxf(mx0, __shfl_xor_sync(0xffffffffu, mx0, 1));
        mx0 = fmaxf(mx0, __shfl_xor_sync(0xffffffffu, mx0, 2));
        mx1 = fmaxf(mx1, __shfl_xor_sync(0xffffffffu, mx1, 1));
        mx1 = fmaxf(mx1, __shfl_xor_sync(0xffffffffu, mx1, 2));
        float mn0 = fmaxf(m0, mx0), mn1 = fmaxf(m1, mx1);
        float cr0 = __expf(m0 - mn0), cr1 = __expf(m1 - mn1);
        m0 = mn0; m1 = mn1;

        float rs0 = 0.f, rs1 = 0.f;
#pragma unroll
        for (int j = 0; j < 8; j++) {
            s[j][0] = __expf(s[j][0] - mn0);
            s[j][1] = __expf(s[j][1] - mn0);
            s[j][2] = __expf(s[j][2] - mn1);
            s[j][3] = __expf(s[j][3] - mn1);
            rs0 += s[j][0] + s[j][1];
            rs1 += s[j][2] + s[j][3];
        }
        rs0 += __shfl_xor_sync(0xffffffffu, rs0, 1);
        rs0 += __shfl_xor_sync(0xffffffffu, rs0, 2);
        rs1 += __shfl_xor_sync(0xffffffffu, rs1, 1);
        rs1 += __shfl_xor_sync(0xffffffffu, rs1, 2);
        l0 = l0 * cr0 + rs0;
        l1 = l1 * cr1 + rs1;

#pragma unroll
        for (int j = 0; j < 8; j++) {
            O[j][0] *= cr0; O[j][1] *= cr0;
            O[j][2] *= cr1; O[j][3] *= cr1;
        }

        uint32_t vb = smb + ASV + buf * 9216 + (uint32_t)((lane & 7) * 144)
                      + (((lane >> 3) & 1) << 4);
#pragma unroll
        for (int ck = 0; ck < 4; ck++) {
            uint32_t ah[4];
            ah[0] = pack2h(s[2 * ck][0],     s[2 * ck][1]);
            ah[1] = pack2h(s[2 * ck][2],     s[2 * ck][3]);
            ah[2] = pack2h(s[2 * ck + 1][0], s[2 * ck + 1][1]);
            ah[3] = pack2h(s[2 * ck + 1][2], s[2 * ck + 1][3]);
#pragma unroll
            for (int jd = 0; jd < 8; jd++) {
                uint32_t bh[2];
                ldsm2(bh, vb + jd * (8 * 144) + ck * 32);
                mma_f16(O[jd], ah, bh);
            }
        }
        __syncthreads();
    }

    float i0 = 1.f / l0, i1 = 1.f / l1;
    int r = q0 + wid * 16 + (lane >> 2);
    int cb = head * HDIM + (lane & 3) * 2;
    __half* row0 = g_ab + (size_t)r * K2;
    __half* row1 = g_ab + (size_t)(r + 8) * K2;
#pragma unroll
    for (int jd = 0; jd < 8; jd++) {
        int col = cb + jd * 8;
        uint32_t hi, lo;
        split2h(O[jd][0] * i0, O[jd][1] * i0, hi, lo);
        *reinterpret_cast<uint32_t*>(row0 + col) = hi;
        *reinterpret_cast<uint32_t*>(row0 + DMODEL + col) = lo;
        split2h(O[jd][2] * i1, O[jd][3] * i1, hi, lo);
        *reinterpret_cast<uint32_t*>(row1 + col) = hi;
        *reinterpret_cast<uint32_t*>(row1 + DMODEL + col) = lo;
    }
}

// ============================================================================
extern "C" void kernel_launch(void* const* d_in, const int* in_sizes, int n_in,
                              void* d_out, int out_size)
{
    const float* hid = (const float*)d_in[0];
    const float* enc = (const float*)d_in[1];
    const float* rc  = (const float*)d_in[2];
    const float* rs  = (const float*)d_in[3];
    const float* Wq  = (const float*)d_in[4];  const float* bq = (const float*)d_in[5];
    const float* Wk  = (const float*)d_in[6];  const float* bk = (const float*)d_in[7];
    const float* Wv  = (const float*)d_in[8];  const float* bv = (const float*)d_in[9];
    const float* Wo  = (const float*)d_in[10]; const float* bo = (const float*)d_in[11];
    const float* lqd = (const float*)d_in[12]; const float* lqu = (const float*)d_in[13];
    const float* lkd = (const float*)d_in[14]; const float* lku = (const float*)d_in[15];
    const float* lvd = (const float*)d_in[16]; const float* lvu = (const float*)d_in[17];
    const float* lpd = (const float*)d_in[18]; const float* lpu = (const float*)d_in[19];
    const float* gq  = (const float*)d_in[20]; const float* btq = (const float*)d_in[21];
    const float* gk  = (const float*)d_in[22]; const float* btk = (const float*)d_in[23];

    static cudaStream_t s2 = nullptr;
    static cudaEvent_t evFork = nullptr, evSplits = nullptr, evS2done = nullptr;
    static int attr_done = 0;
    if (!attr_done) {
        cudaFuncSetAttribute(attn_hmma, cudaFuncAttributeMaxDynamicSharedMemorySize,
                             ATT_SMEM);
        cudaFuncSetAttribute(gemm_hmma, cudaFuncAttributeMaxDynamicSharedMemorySize,
                             GEMM_SMEM);
        cudaFuncSetAttribute(gemm_qkv, cudaFuncAttributeMaxDynamicSharedMemorySize,
                             GEMM_SMEM);
        cudaStreamCreateWithFlags(&s2, cudaStreamNonBlocking);
        cudaEventCreateWithFlags(&evFork, cudaEventDisableTiming);
        cudaEventCreateWithFlags(&evSplits, cudaEventDisableTiming);
        cudaEventCreateWithFlags(&evS2done, cudaEventDisableTiming);
        attr_done = 1;
    }

    float* pt;
    __half *pab, *ptb, *pldb, *pwbase;
    cudaGetSymbolAddress((void**)&pt, g_t);
    cudaGetSymbolAddress((void**)&pab, g_ab);
    cudaGetSymbolAddress((void**)&ptb, g_tb);
    cudaGetSymbolAddress((void**)&pldb, g_ldb);
    cudaGetSymbolAddress((void**)&pwbase, g_wb);
    __half* pwo  = pwbase + (size_t)3 * DMODEL * LDB2;    // 4th weight slot (o-proj)
    __half* plpd = pldb + (size_t)(3 * RANK_) * DMODEL;   // 4th lora-down block

    const int nHD = S_TOT * DMODEL;
    const int nW  = DMODEL * DMODEL;
    const int nLD = RANK_ * DMODEL;
    const int nLU = DMODEL * RANK_;

    dim3 qkv_grid(72, S_TOT / 128, 1);
    dim3 oproj_grid(DMODEL / 128, S_TOT / 128, 3);   // split-K 3: 17/17/16
    dim3 lora3_grid(3, S_TOT / 128, 8);
    dim3 lora1_grid(1, S_TOT / 128, 8);
    const int LORA_CH = MAIN_CH / 8;                 // 6

    // ================= fork: all weight splits on s2 =================
    cudaEventRecord(evFork, 0);
    cudaStreamWaitEvent(s2, evFork, 0);
    splitb3_kernel<<<(3 * nW + 255) / 256, 256, 0, s2>>>(Wq, Wk, Wv, pwbase,
                                                         (size_t)DMODEL * LDB2,
                                                         DMODEL, LDB2, 0, nW);
    splitb3_kernel<<<(3 * nLU + 255) / 256, 256, 0, s2>>>(lqu, lku, lvu, pwbase,
                                                          (size_t)DMODEL * LDB2,
                                                          RANK_, LDB2, DMODEL, nLU);
    splitb3_kernel<<<(3 * nLD + 255) / 256, 256, 0, s2>>>(lqd, lkd, lvd, pldb,
                                                          (size_t)RANK_ * DMODEL,
                                                          DMODEL, DMODEL, 0, nLD);
    cudaEventRecord(evSplits, s2);
    // o-proj weight prep (independent of main chain until the o-proj GEMM)
    splitb1_kernel<<<(nW + 255) / 256, 256, 0, s2>>>(Wo, pwo, DMODEL, LDB2, 0, nW);
    splitb1_kernel<<<(nLU + 255) / 256, 256, 0, s2>>>(lpu, pwo, RANK_, LDB2, DMODEL, nLU);
    splitb1_kernel<<<(nLD + 255) / 256, 256, 0, s2>>>(lpd, plpd, DMODEL, DMODEL, 0, nLD);
    cudaMemsetAsync(d_out, 0, (size_t)out_size * sizeof(float), s2);
    cudaEventRecord(evS2done, s2);

    // ================= main chain (stream 0) =================
    split_concat_kernel<<<(nHD + 255) / 256, 256>>>(hid, enc);
    cudaMemsetAsync(pt, 0, S_TOT * 3 * RANK_ * sizeof(float));
    cudaStreamWaitEvent(0, evSplits, 0);
    gemm_hmma<<<lora3_grid, 128, GEMM_SMEM>>>(pab, nullptr, 0, pldb, DMODEL,
                                              nullptr, pt, 3 * RANK_,
                                              LORA_CH, MAIN_CH, 0, 1, 0);
    tsplit_kernel<<<(S_TOT * 3 * RANK_ + 255) / 256, 256>>>(3);
    // pt free again: zero it for the o-proj lora while qkv runs after it
    gemm_qkv<<<qkv_grid, 128, GEMM_SMEM>>>(pab, ptb, pwbase, bq, bk, bv,
                                           gq, btq, gk, btk, rc, rs);
    cudaMemsetAsync(pt, 0, S_TOT * RANK_ * sizeof(float));

    attn_hmma<<<dim3(S_TOT / 128, NHEADS), 256, ATT_SMEM>>>();

    // join s2 (o-proj weights + d_out zero) before the o-proj chain
    cudaStreamWaitEvent(0, evS2done, 0);
    gemm_hmma<<<lora1_grid, 128, GEMM_SMEM>>>(pab, nullptr, 0, plpd, DMODEL,
                                              nullptr, pt, RANK_,
                                              LORA_CH, MAIN_CH, 0, 1, 0);
    tsplit_kernel<<<(S_TOT * RANK_ + 255) / 256, 256>>>(1);
    gemm_hmma<<<oproj_grid, 128, GEMM_SMEM>>>(pab, ptb, 0, pwo, LDB2,
                                              bo, (float*)d_out, DMODEL,
                                              17, ALL_CH, 1, 1, 1);
}